// round 7
// baseline (speedup 1.0000x reference)
#include <cuda_runtime.h>
#include <cuda_bf16.h>
#include <math.h>
#include <stdint.h>

typedef __nv_bfloat16 bf16;

#define BB 1024
#define DD 128
#define WW 512
#define TT 8
#define NELEM (BB*DD)
#define HELEM (BB*WW)
#define MAX_STEPS 48
#define NBLK 128
#define NTHR 512
#define NGRP 16            // CTAs per dependency group
#define RTOLc 1e-3f
#define ATOLc 1e-6f

#define SROW 144           // smem row stride bytes (72 bf16)
#define ABY (128*SROW)     // A array bytes per chunk (128 rows)
#define BBY (32*SROW)      // B array bytes per chunk (32 rows)
#define STGB (2*ABY + 2*BBY)   // 46080 per pipeline stage
#define NSTG 3

#define A21f 0.161f
#define A31f (-0.008480655492356989f)
#define A32f 0.335480655492357f
#define A41f 2.8971530571054935f
#define A42f (-6.359448489975075f)
#define A43f 4.3622954328695815f
#define A51f 5.325864828439257f
#define A52f (-11.748883564062828f)
#define A53f 7.4955393428898365f
#define A54f (-0.09249506636175525f)
#define A61f 5.86145544294642f
#define A62f (-12.92096931784711f)
#define A63f 8.159367898576159f
#define A64f (-0.071584973281401f)
#define A65f (-0.028269050394068383f)
#define Bc1 0.09646076681806523f
#define Bc2 0.01f
#define Bc3 0.4798896504144996f
#define Bc4 1.379008574103742f
#define Bc5 (-3.290069515436081f)
#define Bc6 2.324710524099774f
#define Ec1 (-0.00178001105222577714f)
#define Ec2 (-0.0008164344596567469f)
#define Ec3 0.007880878010261995f
#define Ec4 (-0.1447110071732629f)
#define Ec5 0.5823571654525552f
#define Ec6 (-0.45808210592918697f)
#define Ec7 0.015151515151515152f

// ---------------- device state ----------------
__device__ __align__(16) float g_y[NELEM], g_ynew[NELEM], g_k[7][NELEM];
__device__ __align__(16) bf16 g_Xhi[NELEM], g_Xlo[NELEM];
__device__ __align__(16) bf16 g_H1hi[HELEM], g_H1lo[HELEM];
__device__ __align__(16) bf16 g_H2hi[HELEM], g_H2lo[HELEM];
__device__ __align__(16) bf16 g_W0hi[WW*DD], g_W0lo[WW*DD];
__device__ __align__(16) bf16 g_W1hi[WW*WW], g_W1lo[WW*WW];
__device__ __align__(16) bf16 g_W2hi[DD*WW], g_W2lo[DD*WW];
__device__ double g_errpart[NBLK];
__device__ volatile float g_t, g_dt, g_h, g_tns;
__device__ volatile int g_si, g_sic, g_done, g_accept, g_hit, g_wrow;
__device__ unsigned g_arrive;
__device__ unsigned g_garr[8 * 32];   // 8 groups, 128B apart

__constant__ float c_coef[6][6] = {
  {A21f,0,0,0,0,0},
  {A31f,A32f,0,0,0,0},
  {A41f,A42f,A43f,0,0,0},
  {A51f,A52f,A53f,A54f,0,0},
  {A61f,A62f,A63f,A64f,A65f,0},
  {Bc1,Bc2,Bc3,Bc4,Bc5,Bc6},
};

// ---------------- helpers ----------------
__device__ __forceinline__ uint32_t smem_u32(const void* p) {
  uint32_t a;
  asm("{ .reg .u64 t; cvta.to.shared.u64 t, %1; cvt.u32.u64 %0, t; }" : "=r"(a) : "l"(p));
  return a;
}
__device__ __forceinline__ void cp16(uint32_t dst, const void* src) {
  asm volatile("cp.async.cg.shared.global [%0], [%1], 16;" :: "r"(dst), "l"(src) : "memory");
}
__device__ __forceinline__ void cp_commit() { asm volatile("cp.async.commit_group;" ::: "memory"); }
__device__ __forceinline__ void cp_wait1() { asm volatile("cp.async.wait_group 1;" ::: "memory"); }

__device__ __forceinline__ void mma16816(float* c, const uint32_t* a, const uint32_t* b) {
  asm volatile(
    "mma.sync.aligned.m16n8k16.row.col.f32.bf16.bf16.f32 "
    "{%0,%1,%2,%3}, {%4,%5,%6,%7}, {%8,%9}, {%0,%1,%2,%3};"
    : "+f"(c[0]), "+f"(c[1]), "+f"(c[2]), "+f"(c[3])
    : "r"(a[0]), "r"(a[1]), "r"(a[2]), "r"(a[3]), "r"(b[0]), "r"(b[1]));
}
__device__ __forceinline__ uint32_t lds32(const char* base, int row, int colbf) {
  return *(const uint32_t*)(base + row * SROW + colbf * 2);
}

// -------- barriers --------
__device__ __forceinline__ void gsync() {
  __syncthreads();
  if (threadIdx.x == 0) {
    __threadfence();
    unsigned t = atomicAdd(&g_arrive, 1u) + 1u;
    unsigned target = ((t + NBLK - 1u) / NBLK) * NBLK;
    while (*(volatile unsigned*)&g_arrive < target) {}
    __threadfence();
  }
  __syncthreads();
}
__device__ __forceinline__ void ggsync(int grp) {
  __syncthreads();
  if (threadIdx.x == 0) {
    __threadfence();
    unsigned* ctr = &g_garr[grp * 32];
    unsigned t = atomicAdd(ctr, 1u) + 1u;
    unsigned target = ((t + NGRP - 1u) / NGRP) * NGRP;
    while (*(volatile unsigned*)ctr < target) {}
    __threadfence();
  }
  __syncthreads();
}

// -------- MUFU-free softplus (abs err ~2e-6) --------
__device__ __forceinline__ float softplus_f(float x) {
  float t = fabsf(x);
  float s = fminf(t * 1.4426950408889634f, 100.f);
  float n = floorf(s);
  float r = n - s;
  float p = 1.3215487e-6f;
  p = fmaf(p, r, 1.5252734e-5f);
  p = fmaf(p, r, 1.5403530e-4f);
  p = fmaf(p, r, 1.3333558e-3f);
  p = fmaf(p, r, 9.6181291e-3f);
  p = fmaf(p, r, 5.5504109e-2f);
  p = fmaf(p, r, 2.4022651e-1f);
  p = fmaf(p, r, 6.9314718e-1f);
  p = fmaf(p, r, 1.0f);
  float u = p * __uint_as_float((uint32_t)(127 - (int)n) << 23);
  float d = 2.f + u;
  float w = fmaf(-0.1635f, u, 0.4915f);
  w = w * fmaf(-d, w, 2.f);
  w = w * fmaf(-d, w, 2.f);
  float v = u * w;
  float v2 = v * v;
  float g = 0.09090909f;
  g = fmaf(g, v2, 0.11111111f);
  g = fmaf(g, v2, 0.14285714f);
  g = fmaf(g, v2, 0.2f);
  g = fmaf(g, v2, 0.33333333f);
  g = fmaf(g, v2, 1.0f);
  return fmaxf(x, 0.f) + 2.f * v * g;
}

__device__ __forceinline__ void split_pack(float x0, float x1, uint32_t& hv, uint32_t& lv) {
  bf16 h0 = __float2bfloat16(x0), h1 = __float2bfloat16(x1);
  bf16 l0 = __float2bfloat16(x0 - __bfloat162float(h0));
  bf16 l1 = __float2bfloat16(x1 - __bfloat162float(h1));
  hv = (uint32_t)__bfloat16_as_ushort(h0) | ((uint32_t)__bfloat16_as_ushort(h1) << 16);
  lv = (uint32_t)__bfloat16_as_ushort(l0) | ((uint32_t)__bfloat16_as_ushort(l1) << 16);
}

// -------- chunk fill via cp.async: Ahi/Alo (arows x 64) + Bhi/Blo (brows x 64) --------
__device__ __forceinline__ void fill_chunk(char* dst,
    const bf16* __restrict__ Ahi, const bf16* __restrict__ Alo,
    const bf16* __restrict__ Bhi, const bf16* __restrict__ Blo,
    int ldk, int arow0, int arows, int brow0, int brows, int koff)
{
  const int tid = threadIdx.x;
  const int t = tid & 127;
  const int part = tid >> 7;
  const bf16* src;
  char* d;
  bool on;
  if (part == 0)      { src = Ahi + (arow0 + t) * ldk + koff; d = dst;           on = t < arows; }
  else if (part == 1) { src = Alo + (arow0 + t) * ldk + koff; d = dst + ABY;     on = t < arows; }
  else if (part == 2) { src = Bhi + (brow0 + t) * ldk + koff; d = dst + 2*ABY;   on = t < brows; }
  else                { src = Blo + (brow0 + t) * ldk + koff; d = dst + 2*ABY + BBY; on = t < brows; }
  if (on) {
    uint32_t da = smem_u32(d + t * SROW);
    #pragma unroll
    for (int j = 0; j < 8; ++j) cp16(da + j * 16, src + j * 8);
  }
}

// ---------------- GEMM1/2: C[128,32] = act(A @ B^T + bias) -> bf16 hi/lo ----------------
template<int NCHUNK, bool SP>
__device__ __forceinline__ void gemm_fwd(char* sm,
    const bf16* __restrict__ Ahi, const bf16* __restrict__ Alo,
    const bf16* __restrict__ Bhi, const bf16* __restrict__ Blo,
    int ldk, int bm, int bn, const float* __restrict__ bias,
    bf16* __restrict__ Chi, bf16* __restrict__ Clo, int ldc)
{
  const int tid = threadIdx.x;
  const int wid = tid >> 5, lane = tid & 31;
  const int wm = wid >> 1, wn = wid & 1;   // 8 x 2 warp grid over 128x32
  const int grp = lane >> 2, tig = lane & 3;

  float acc[2][4] = {};

  fill_chunk(sm, Ahi, Alo, Bhi, Blo, ldk, bm, 128, bn, 32, 0);
  cp_commit();
  if (NCHUNK > 1) fill_chunk(sm + STGB, Ahi, Alo, Bhi, Blo, ldk, bm, 128, bn, 32, 64);
  cp_commit();

  const int r0 = wm * 16 + grp;
  const int nr0 = wn * 16 + grp;
  const int cw = tig * 2;

  for (int c = 0; c < NCHUNK; ++c) {
    cp_wait1();
    __syncthreads();
    if (c + 2 < NCHUNK)
      fill_chunk(sm + ((c + 2) % NSTG) * STGB, Ahi, Alo, Bhi, Blo, ldk, bm, 128, bn, 32, (c + 2) * 64);
    cp_commit();
    char* st = sm + (c % NSTG) * STGB;
    char* sAh = st;
    char* sAl = st + ABY;
    char* sBh = st + 2 * ABY;
    char* sBl = st + 2 * ABY + BBY;
    #pragma unroll
    for (int ks = 0; ks < 4; ++ks) {
      const int kc = ks * 16;
      uint32_t ah[4], al[4];
      ah[0] = lds32(sAh, r0,     kc + cw);
      ah[1] = lds32(sAh, r0 + 8, kc + cw);
      ah[2] = lds32(sAh, r0,     kc + cw + 8);
      ah[3] = lds32(sAh, r0 + 8, kc + cw + 8);
      al[0] = lds32(sAl, r0,     kc + cw);
      al[1] = lds32(sAl, r0 + 8, kc + cw);
      al[2] = lds32(sAl, r0,     kc + cw + 8);
      al[3] = lds32(sAl, r0 + 8, kc + cw + 8);
      #pragma unroll
      for (int ni = 0; ni < 2; ++ni) {
        uint32_t bh[2], bl[2];
        int nr = nr0 + ni * 8;
        bh[0] = lds32(sBh, nr, kc + cw);
        bh[1] = lds32(sBh, nr, kc + cw + 8);
        bl[0] = lds32(sBl, nr, kc + cw);
        bl[1] = lds32(sBl, nr, kc + cw + 8);
        mma16816(acc[ni], ah, bh);
        mma16816(acc[ni], ah, bl);
        mma16816(acc[ni], al, bh);
      }
    }
  }

  #pragma unroll
  for (int ni = 0; ni < 2; ++ni) {
    int n = bn + wn * 16 + ni * 8 + tig * 2;
    int m0 = bm + wm * 16 + grp;
    float bv0 = __ldg(bias + n), bv1 = __ldg(bias + n + 1);
    float x0 = acc[ni][0] + bv0, x1 = acc[ni][1] + bv1;
    float x2 = acc[ni][2] + bv0, x3 = acc[ni][3] + bv1;
    if (SP) { x0 = softplus_f(x0); x1 = softplus_f(x1); x2 = softplus_f(x2); x3 = softplus_f(x3); }
    uint32_t hv, lv;
    split_pack(x0, x1, hv, lv);
    __stcg((uint32_t*)(Chi + m0 * ldc + n), hv);
    __stcg((uint32_t*)(Clo + m0 * ldc + n), lv);
    split_pack(x2, x3, hv, lv);
    __stcg((uint32_t*)(Chi + (m0 + 8) * ldc + n), hv);
    __stcg((uint32_t*)(Clo + (m0 + 8) * ldc + n), lv);
  }
}

// ---------------- GEMM3 (stage S): k_S[64,16] tile, K=512, fused RK epilogue ----------------
template<int S>
__device__ __forceinline__ void gemm3_stage(char* sm, float* sred, int bm, int bn,
                                            const float* __restrict__ b2, double* sd)
{
  const int tid = threadIdx.x;
  const int wid = tid >> 5, lane = tid & 31;
  const int wm = wid & 3, wn = (wid >> 2) & 1, wk = wid >> 3;  // 4 x 2 x 2
  const int grp = lane >> 2, tig = lane & 3;

  float acc[4] = {};

  fill_chunk(sm, g_H2hi, g_H2lo, g_W2hi, g_W2lo, WW, bm, 64, bn, 16, 0);
  cp_commit();
  fill_chunk(sm + STGB, g_H2hi, g_H2lo, g_W2hi, g_W2lo, WW, bm, 64, bn, 16, 64);
  cp_commit();

  const int r0 = wm * 16 + grp;
  const int nr = wn * 8 + grp;
  const int cw = tig * 2;

  for (int c = 0; c < 8; ++c) {
    cp_wait1();
    __syncthreads();
    if (c + 2 < 8)
      fill_chunk(sm + ((c + 2) % NSTG) * STGB, g_H2hi, g_H2lo, g_W2hi, g_W2lo, WW, bm, 64, bn, 16, (c + 2) * 64);
    cp_commit();
    if ((c & 1) == wk) {
      char* st = sm + (c % NSTG) * STGB;
      char* sAh = st;
      char* sAl = st + ABY;
      char* sBh = st + 2 * ABY;
      char* sBl = st + 2 * ABY + BBY;
      #pragma unroll
      for (int ks = 0; ks < 4; ++ks) {
        const int kc = ks * 16;
        uint32_t ah[4], al[4], bh[2], bl[2];
        ah[0] = lds32(sAh, r0,     kc + cw);
        ah[1] = lds32(sAh, r0 + 8, kc + cw);
        ah[2] = lds32(sAh, r0,     kc + cw + 8);
        ah[3] = lds32(sAh, r0 + 8, kc + cw + 8);
        al[0] = lds32(sAl, r0,     kc + cw);
        al[1] = lds32(sAl, r0 + 8, kc + cw);
        al[2] = lds32(sAl, r0,     kc + cw + 8);
        al[3] = lds32(sAl, r0 + 8, kc + cw + 8);
        bh[0] = lds32(sBh, nr, kc + cw);
        bh[1] = lds32(sBh, nr, kc + cw + 8);
        bl[0] = lds32(sBl, nr, kc + cw);
        bl[1] = lds32(sBl, nr, kc + cw + 8);
        mma16816(acc, ah, bh);
        mma16816(acc, ah, bl);
        mma16816(acc, al, bh);
      }
    }
  }

  // cross-wk reduce via smem
  const int ml = wm * 16 + grp;
  const int nl = wn * 8 + tig * 2;
  if (wk == 1) {
    sred[ml * 16 + nl]           = acc[0];
    sred[ml * 16 + nl + 1]       = acc[1];
    sred[(ml + 8) * 16 + nl]     = acc[2];
    sred[(ml + 8) * 16 + nl + 1] = acc[3];
  }
  __syncthreads();
  double ss = 0.0;
  if (wk == 0) {
    acc[0] += sred[ml * 16 + nl];
    acc[1] += sred[ml * 16 + nl + 1];
    acc[2] += sred[(ml + 8) * 16 + nl];
    acc[3] += sred[(ml + 8) * 16 + nl + 1];

    const int n0 = bn + nl;
    const int m0 = bm + ml;
    const float h = g_h;
    const int i0 = m0 * DD + n0;
    const int i1 = (m0 + 8) * DD + n0;
    float bv0 = __ldg(b2 + n0), bv1 = __ldg(b2 + n0 + 1);
    float2 v0 = {acc[0] + bv0, acc[1] + bv1};
    float2 v1 = {acc[2] + bv0, acc[3] + bv1};
    __stcg((float2*)(g_k[S] + i0), v0);
    __stcg((float2*)(g_k[S] + i1), v1);

    const int idxs[2] = {i0, i1};
    const float2 vs[2] = {v0, v1};
    if constexpr (S <= 5) {
      #pragma unroll
      for (int r = 0; r < 2; ++r) {
        int ix = idxs[r];
        float2 y2 = __ldcg((const float2*)(g_y + ix));
        float cS = c_coef[S][S];
        float ax = cS * vs[r].x, ay = cS * vs[r].y;
        #pragma unroll
        for (int j = 0; j < S; ++j) {
          float cj = c_coef[S][j];
          float2 kj = __ldcg((const float2*)(g_k[j] + ix));
          ax = fmaf(cj, kj.x, ax);
          ay = fmaf(cj, kj.y, ay);
        }
        float Xx = fmaf(h, ax, y2.x);
        float Xy = fmaf(h, ay, y2.y);
        if constexpr (S == 5) {
          float2 yn = {Xx, Xy};
          __stcg((float2*)(g_ynew + ix), yn);
        }
        uint32_t hv, lv;
        split_pack(Xx, Xy, hv, lv);
        __stcg((uint32_t*)(g_Xhi + ix), hv);
        __stcg((uint32_t*)(g_Xlo + ix), lv);
      }
    } else {
      #pragma unroll
      for (int r = 0; r < 2; ++r) {
        int ix = idxs[r];
        float2 k0 = __ldcg((const float2*)(g_k[0] + ix));
        float2 k1 = __ldcg((const float2*)(g_k[1] + ix));
        float2 k2 = __ldcg((const float2*)(g_k[2] + ix));
        float2 k3 = __ldcg((const float2*)(g_k[3] + ix));
        float2 k4 = __ldcg((const float2*)(g_k[4] + ix));
        float2 k5 = __ldcg((const float2*)(g_k[5] + ix));
        float2 y2 = __ldcg((const float2*)(g_y + ix));
        float2 yn = __ldcg((const float2*)(g_ynew + ix));
        #pragma unroll
        for (int cc = 0; cc < 2; ++cc) {
          float e = Ec1 * (cc ? k0.y : k0.x);
          e = fmaf(Ec2, cc ? k1.y : k1.x, e);
          e = fmaf(Ec3, cc ? k2.y : k2.x, e);
          e = fmaf(Ec4, cc ? k3.y : k3.x, e);
          e = fmaf(Ec5, cc ? k4.y : k4.x, e);
          e = fmaf(Ec6, cc ? k5.y : k5.x, e);
          e = fmaf(Ec7, cc ? vs[r].y : vs[r].x, e);
          float err = h * e;
          float yv = cc ? y2.y : y2.x, ynv = cc ? yn.y : yn.x;
          float scale = ATOLc + RTOLc * fmaxf(fabsf(yv), fabsf(ynv));
          float rr = err / scale;
          ss += (double)rr * (double)rr;
        }
      }
    }
  }
  if constexpr (S == 6) {
    sd[tid] = ss;
    __syncthreads();
    #pragma unroll
    for (int s2 = 256; s2 > 0; s2 >>= 1) {
      if (tid < s2) sd[tid] += sd[tid + s2];
      __syncthreads();
    }
    if (tid == 0) ((volatile double*)g_errpart)[blockIdx.x] = sd[0];
  }
}

// ---------------- one RK stage (group-local syncs) ----------------
template<int S>
__device__ __forceinline__ void do_stage(char* sm, float* sred, int bid, int grp_id,
    const float* b0, const float* b1, const float* b2, double* sd)
{
  const int bm = (bid >> 4) << 7;      // 8 m-tiles of 128
  const int bn = (bid & 15) << 5;      // 16 n-tiles of 32
  gemm_fwd<2, true>(sm, g_Xhi, g_Xlo, g_W0hi, g_W0lo, DD, bm, bn, b0, g_H1hi, g_H1lo, WW);
  ggsync(grp_id);
  gemm_fwd<8, true>(sm, g_H1hi, g_H1lo, g_W1hi, g_W1lo, WW, bm, bn, b1, g_H2hi, g_H2lo, WW);
  ggsync(grp_id);
  gemm3_stage<S>(sm, sred, (bid >> 3) << 6, (bid & 7) << 4, b2, sd);
  if (S < 6) ggsync(grp_id);   // stage 6 followed by global gsync instead
}

__device__ __forceinline__ void update_phase(int gid2, float* __restrict__ out) {
  float2 v;
  if (g_accept) {
    v = __ldcg((const float2*)(g_ynew + gid2));
    __stcg((float2*)(g_y + gid2), v);
    if (g_hit) *(float2*)(out + g_wrow * NELEM + gid2) = v;
  } else {
    v = __ldcg((const float2*)(g_y + gid2));
  }
  uint32_t hv, lv;
  split_pack(v.x, v.y, hv, lv);
  __stcg((uint32_t*)(g_Xhi + gid2), hv);
  __stcg((uint32_t*)(g_Xlo + gid2), lv);
}

// ---------------- persistent solver ----------------
__global__ void __launch_bounds__(NTHR, 1) solve_kernel(
    const float* __restrict__ ts,
    const float* __restrict__ b0, const float* __restrict__ b1,
    const float* __restrict__ b2, float* __restrict__ out)
{
  extern __shared__ __align__(16) char sm[];
  __shared__ double sd[NTHR];
  __shared__ float sred[64 * 16];

  const int bid = blockIdx.x;
  const int tid = threadIdx.x;
  const int grp_id = bid >> 4;
  const int gid2 = (bid * NTHR + tid) * 2;

  for (int step = 0; step < MAX_STEPS; ++step) {
    update_phase(gid2, out);
    ggsync(grp_id);

    do_stage<0>(sm, sred, bid, grp_id, b0, b1, b2, sd);
    do_stage<1>(sm, sred, bid, grp_id, b0, b1, b2, sd);
    do_stage<2>(sm, sred, bid, grp_id, b0, b1, b2, sd);
    do_stage<3>(sm, sred, bid, grp_id, b0, b1, b2, sd);
    do_stage<4>(sm, sred, bid, grp_id, b0, b1, b2, sd);
    do_stage<5>(sm, sred, bid, grp_id, b0, b1, b2, sd);
    do_stage<6>(sm, sred, bid, grp_id, b0, b1, b2, sd);

    gsync();   // all err partials visible

    if (bid == 0) {
      double v = (tid < NBLK) ? ((volatile double*)g_errpart)[tid] : 0.0;
      sd[tid] = v;
      __syncthreads();
      #pragma unroll
      for (int s2 = 256; s2 > 0; s2 >>= 1) {
        if (tid < s2) sd[tid] += sd[tid + s2];
        __syncthreads();
      }
      if (tid == 0) {
        float enorm = sqrtf((float)(sd[0] / (double)NELEM));
        int done = g_done;
        float h = g_h;
        int accept = (enorm <= 1.0f) && !done;
        float t_new = g_t + h;
        int hit = accept && (t_new >= g_tns - 1e-6f);
        if (accept) g_t = t_new;
        g_accept = accept;
        g_hit = hit;
        g_wrow = g_sic;
        int si = g_si + hit;
        g_si = si;
        float factor;
        if (enorm > 0.f) {
          factor = 0.9f * powf(enorm, -0.2f);
          factor = fminf(fmaxf(factor, 0.2f), 10.f);
        } else factor = 10.f;
        if (!done) g_dt = g_dt * factor;
        // fold in next step's "pre" phase
        int done2 = (si >= TT) ? 1 : 0;
        int sic2 = si < (TT - 1) ? si : (TT - 1);
        float tns2 = __ldg(ts + sic2);
        float h2 = done2 ? 0.f : fmaxf(fminf(g_dt, tns2 - g_t), 0.f);
        g_done = done2; g_sic = sic2; g_tns = tns2; g_h = h2;
      }
    }
    gsync();   // controller state visible to all
  }
  update_phase(gid2, out);
}

// ---------------- init ----------------
__global__ void init_kernel(const float* __restrict__ ts, const float* __restrict__ y0,
                            const float* __restrict__ W0, const float* __restrict__ W1,
                            const float* __restrict__ W2, float* __restrict__ out)
{
  int idx = blockIdx.x * NTHR + threadIdx.x;
  if (idx < TT * NELEM) out[idx] = (idx < NELEM) ? y0[idx] : 0.f;
  if (idx < NELEM) {
    float v = y0[idx];
    g_y[idx] = v;
    bf16 h = __float2bfloat16(v);
    g_Xhi[idx] = h;
    g_Xlo[idx] = __float2bfloat16(v - __bfloat162float(h));
  }
  if (idx < WW * DD) {
    float w = W0[idx];
    bf16 h = __float2bfloat16(w);
    g_W0hi[idx] = h; g_W0lo[idx] = __float2bfloat16(w - __bfloat162float(h));
    float w2 = W2[idx];
    bf16 h2 = __float2bfloat16(w2);
    g_W2hi[idx] = h2; g_W2lo[idx] = __float2bfloat16(w2 - __bfloat162float(h2));
  }
  if (idx < WW * WW) {
    float w = W1[idx];
    bf16 h = __float2bfloat16(w);
    g_W1hi[idx] = h; g_W1lo[idx] = __float2bfloat16(w - __bfloat162float(h));
  }
  if (idx < 8 * 32) g_garr[idx] = 0u;
  if (idx == 0) {
    float t0 = ts[0];
    float dt0 = ts[1] - ts[0];
    g_t = t0;
    g_dt = dt0;
    g_si = 1;
    g_accept = 0;
    g_hit = 0;
    g_wrow = 0;
    g_arrive = 0u;
    // step-0 "pre" controller state
    g_done = 0;
    g_sic = 1;
    float tns = ts[1];
    g_tns = tns;
    g_h = fmaxf(fminf(dt0, tns - t0), 0.f);
  }
}

extern "C" void kernel_launch(void* const* d_in, const int* in_sizes, int n_in,
                              void* d_out, int out_size) {
  const float* ts = (const float*)d_in[0];
  const float* y0 = (const float*)d_in[1];
  const float* W0 = (const float*)d_in[2];
  const float* b0 = (const float*)d_in[3];
  const float* W1 = (const float*)d_in[4];
  const float* b1 = (const float*)d_in[5];
  const float* W2 = (const float*)d_in[6];
  const float* b2 = (const float*)d_in[7];
  float* out = (float*)d_out;

  cudaFuncSetAttribute(solve_kernel, cudaFuncAttributeMaxDynamicSharedMemorySize, NSTG * STGB);

  init_kernel<<<(TT * NELEM) / NTHR, NTHR>>>(ts, y0, W0, W1, W2, out);
  solve_kernel<<<NBLK, NTHR, NSTG * STGB>>>(ts, b0, b1, b2, out);
}

// round 8
// speedup vs baseline: 1.4227x; 1.4227x over previous
#include <cuda_runtime.h>
#include <cuda_bf16.h>
#include <math.h>
#include <stdint.h>

typedef __nv_bfloat16 bf16;

#define BB 1024
#define DD 128
#define WW 512
#define TT 8
#define NELEM (BB*DD)
#define HELEM (BB*WW)
#define MAX_STEPS 48
#define NBLK 128
#define NTHR 256
#define NGRP 16
#define RTOLc 1e-3f
#define ATOLc 1e-6f
#define SAS 72   // smem row stride in bf16 (144B)

#define A21f 0.161f
#define A31f (-0.008480655492356989f)
#define A32f 0.335480655492357f
#define A41f 2.8971530571054935f
#define A42f (-6.359448489975075f)
#define A43f 4.3622954328695815f
#define A51f 5.325864828439257f
#define A52f (-11.748883564062828f)
#define A53f 7.4955393428898365f
#define A54f (-0.09249506636175525f)
#define A61f 5.86145544294642f
#define A62f (-12.92096931784711f)
#define A63f 8.159367898576159f
#define A64f (-0.071584973281401f)
#define A65f (-0.028269050394068383f)
#define Bc1 0.09646076681806523f
#define Bc2 0.01f
#define Bc3 0.4798896504144996f
#define Bc4 1.379008574103742f
#define Bc5 (-3.290069515436081f)
#define Bc6 2.324710524099774f
#define Ec1 (-0.00178001105222577714f)
#define Ec2 (-0.0008164344596567469f)
#define Ec3 0.007880878010261995f
#define Ec4 (-0.1447110071732629f)
#define Ec5 0.5823571654525552f
#define Ec6 (-0.45808210592918697f)
#define Ec7 0.015151515151515152f

// ---------------- device state ----------------
__device__ __align__(16) float g_y[NELEM], g_ynew[NELEM], g_k[7][NELEM];
__device__ __align__(16) bf16 g_Xhi[NELEM], g_Xlo[NELEM];
__device__ __align__(16) bf16 g_H1hi[HELEM], g_H1lo[HELEM];
__device__ __align__(16) bf16 g_H2hi[HELEM], g_H2lo[HELEM];
__device__ __align__(16) bf16 g_W0hi[WW*DD], g_W0lo[WW*DD];
__device__ __align__(16) bf16 g_W1hi[WW*WW], g_W1lo[WW*WW];
__device__ __align__(16) bf16 g_W2hi[DD*WW], g_W2lo[DD*WW];
__device__ double g_errpart[NBLK];
__device__ volatile float g_t, g_dt, g_h, g_tns;
__device__ volatile int g_si, g_sic, g_done, g_accept, g_hit, g_wrow;
__device__ unsigned g_arrive;
__device__ volatile unsigned gg_flag[NBLK * 32];   // one padded word per CTA

__constant__ float c_coef[6][6] = {
  {A21f,0,0,0,0,0},
  {A31f,A32f,0,0,0,0},
  {A41f,A42f,A43f,0,0,0},
  {A51f,A52f,A53f,A54f,0,0},
  {A61f,A62f,A63f,A64f,A65f,0},
  {Bc1,Bc2,Bc3,Bc4,Bc5,Bc6},
};

// ---------------- barriers ----------------
// global: atomic ticket (2 uses per step only)
__device__ __forceinline__ void gsync() {
  __syncthreads();
  if (threadIdx.x == 0) {
    __threadfence();
    unsigned t = atomicAdd(&g_arrive, 1u) + 1u;
    unsigned target = ((t + NBLK - 1u) / NBLK) * NBLK;
    while (*(volatile unsigned*)&g_arrive < target) {}
    __threadfence();
  }
  __syncthreads();
}
// group: contention-free flag barrier over 16 CTAs
__device__ __forceinline__ void ggsync(int grp, unsigned ep) {
  __syncthreads();
  if (threadIdx.x == 0) {
    __threadfence();
    gg_flag[blockIdx.x * 32] = ep;
  }
  if (threadIdx.x < NGRP) {
    const volatile unsigned* f = &gg_flag[(grp * NGRP + threadIdx.x) * 32];
    while (*f < ep) {}
  }
  __syncthreads();
}

// ---------------- math helpers ----------------
__device__ __forceinline__ void mma16816(float* c, const uint32_t* a, const uint32_t* b) {
  asm volatile(
    "mma.sync.aligned.m16n8k16.row.col.f32.bf16.bf16.f32 "
    "{%0,%1,%2,%3}, {%4,%5,%6,%7}, {%8,%9}, {%0,%1,%2,%3};"
    : "+f"(c[0]), "+f"(c[1]), "+f"(c[2]), "+f"(c[3])
    : "r"(a[0]), "r"(a[1]), "r"(a[2]), "r"(a[3]), "r"(b[0]), "r"(b[1]));
}

// MUFU-free softplus (abs err ~2e-6)
__device__ __forceinline__ float softplus_f(float x) {
  float t = fabsf(x);
  float s = fminf(t * 1.4426950408889634f, 100.f);
  float n = floorf(s);
  float r = n - s;
  float p = 1.3215487e-6f;
  p = fmaf(p, r, 1.5252734e-5f);
  p = fmaf(p, r, 1.5403530e-4f);
  p = fmaf(p, r, 1.3333558e-3f);
  p = fmaf(p, r, 9.6181291e-3f);
  p = fmaf(p, r, 5.5504109e-2f);
  p = fmaf(p, r, 2.4022651e-1f);
  p = fmaf(p, r, 6.9314718e-1f);
  p = fmaf(p, r, 1.0f);
  float u = p * __uint_as_float((uint32_t)(127 - (int)n) << 23);
  float d = 2.f + u;
  float w = fmaf(-0.1635f, u, 0.4915f);
  w = w * fmaf(-d, w, 2.f);
  w = w * fmaf(-d, w, 2.f);
  float v = u * w;
  float v2 = v * v;
  float g = 0.09090909f;
  g = fmaf(g, v2, 0.11111111f);
  g = fmaf(g, v2, 0.14285714f);
  g = fmaf(g, v2, 0.2f);
  g = fmaf(g, v2, 0.33333333f);
  g = fmaf(g, v2, 1.0f);
  return fmaxf(x, 0.f) + 2.f * v * g;
}

__device__ __forceinline__ void split_pack(float x0, float x1, uint32_t& hv, uint32_t& lv) {
  bf16 h0 = __float2bfloat16(x0), h1 = __float2bfloat16(x1);
  bf16 l0 = __float2bfloat16(x0 - __bfloat162float(h0));
  bf16 l1 = __float2bfloat16(x1 - __bfloat162float(h1));
  hv = (uint32_t)__bfloat16_as_ushort(h0) | ((uint32_t)__bfloat16_as_ushort(h1) << 16);
  lv = (uint32_t)__bfloat16_as_ushort(l0) | ((uint32_t)__bfloat16_as_ushort(l1) << 16);
}

// ---------------- GEMM1/2: C[128,32] = act(A[M,K] @ B[N,K]^T + bias) -> bf16 hi/lo ----------------
// identical structure to the R5 kernel (best so far)
template<bool SP>
__device__ __forceinline__ void mma_gemm(
    const bf16* __restrict__ Ahi, const bf16* __restrict__ Alo,
    const bf16* __restrict__ Bhi, const bf16* __restrict__ Blo,
    int ldk, int bm, int bn, int nchunk,
    const float* __restrict__ bias,
    bf16* __restrict__ Chi, bf16* __restrict__ Clo, int ldc,
    bf16* sAhi, bf16* sAlo, bf16* sBhi, bf16* sBlo)
{
  const int tid = threadIdx.x;
  const int wid = tid >> 5;
  const int lane = tid & 31;
  const int grp = lane >> 2, tig = lane & 3;
  const int wm = wid >> 1, wn = wid & 1;

  float acc[2][2][4] = {};

  int ar[4], as[4];
  #pragma unroll
  for (int i = 0; i < 4; ++i) {
    int lin = tid + i * 256;
    ar[i] = lin >> 3;
    as[i] = (lin & 7) << 3;
  }
  const int br = tid >> 3;
  const int bs = (tid & 7) << 3;

  uint4 pah[4], pal[4], pbh, pbl;
  #pragma unroll
  for (int i = 0; i < 4; ++i) {
    pah[i] = __ldcg((const uint4*)(Ahi + (bm + ar[i]) * ldk + as[i]));
    pal[i] = __ldcg((const uint4*)(Alo + (bm + ar[i]) * ldk + as[i]));
  }
  pbh = __ldg((const uint4*)(Bhi + (bn + br) * ldk + bs));
  pbl = __ldg((const uint4*)(Blo + (bn + br) * ldk + bs));

  for (int c = 0; c < nchunk; ++c) {
    #pragma unroll
    for (int i = 0; i < 4; ++i) {
      *(uint4*)(sAhi + ar[i] * SAS + as[i]) = pah[i];
      *(uint4*)(sAlo + ar[i] * SAS + as[i]) = pal[i];
    }
    *(uint4*)(sBhi + br * SAS + bs) = pbh;
    *(uint4*)(sBlo + br * SAS + bs) = pbl;
    if (c + 1 < nchunk) {
      int k0 = (c + 1) * 64;
      #pragma unroll
      for (int i = 0; i < 4; ++i) {
        pah[i] = __ldcg((const uint4*)(Ahi + (bm + ar[i]) * ldk + k0 + as[i]));
        pal[i] = __ldcg((const uint4*)(Alo + (bm + ar[i]) * ldk + k0 + as[i]));
      }
      pbh = __ldg((const uint4*)(Bhi + (bn + br) * ldk + k0 + bs));
      pbl = __ldg((const uint4*)(Blo + (bn + br) * ldk + k0 + bs));
    }
    __syncthreads();
    #pragma unroll
    for (int ks = 0; ks < 4; ++ks) {
      const int kc = ks * 16;
      uint32_t ah[2][4], al[2][4], bh[2][2], bl[2][2];
      #pragma unroll
      for (int mi = 0; mi < 2; ++mi) {
        int r0 = wm * 32 + mi * 16 + grp;
        int c0 = kc + tig * 2;
        ah[mi][0] = *(const uint32_t*)(sAhi + r0 * SAS + c0);
        ah[mi][1] = *(const uint32_t*)(sAhi + (r0 + 8) * SAS + c0);
        ah[mi][2] = *(const uint32_t*)(sAhi + r0 * SAS + c0 + 8);
        ah[mi][3] = *(const uint32_t*)(sAhi + (r0 + 8) * SAS + c0 + 8);
        al[mi][0] = *(const uint32_t*)(sAlo + r0 * SAS + c0);
        al[mi][1] = *(const uint32_t*)(sAlo + (r0 + 8) * SAS + c0);
        al[mi][2] = *(const uint32_t*)(sAlo + r0 * SAS + c0 + 8);
        al[mi][3] = *(const uint32_t*)(sAlo + (r0 + 8) * SAS + c0 + 8);
      }
      #pragma unroll
      for (int ni = 0; ni < 2; ++ni) {
        int nr = wn * 16 + ni * 8 + grp;
        int c0 = kc + tig * 2;
        bh[ni][0] = *(const uint32_t*)(sBhi + nr * SAS + c0);
        bh[ni][1] = *(const uint32_t*)(sBhi + nr * SAS + c0 + 8);
        bl[ni][0] = *(const uint32_t*)(sBlo + nr * SAS + c0);
        bl[ni][1] = *(const uint32_t*)(sBlo + nr * SAS + c0 + 8);
      }
      #pragma unroll
      for (int mi = 0; mi < 2; ++mi)
        #pragma unroll
        for (int ni = 0; ni < 2; ++ni) {
          mma16816(acc[mi][ni], ah[mi], bh[ni]);
          mma16816(acc[mi][ni], ah[mi], bl[ni]);
          mma16816(acc[mi][ni], al[mi], bh[ni]);
        }
    }
    __syncthreads();
  }

  #pragma unroll
  for (int mi = 0; mi < 2; ++mi) {
    #pragma unroll
    for (int ni = 0; ni < 2; ++ni) {
      int m0 = bm + wm * 32 + mi * 16 + grp;
      int n  = bn + wn * 16 + ni * 8 + tig * 2;
      float bv0 = __ldg(bias + n), bv1 = __ldg(bias + n + 1);
      float x0 = acc[mi][ni][0] + bv0, x1 = acc[mi][ni][1] + bv1;
      float x2 = acc[mi][ni][2] + bv0, x3 = acc[mi][ni][3] + bv1;
      if (SP) { x0 = softplus_f(x0); x1 = softplus_f(x1); x2 = softplus_f(x2); x3 = softplus_f(x3); }
      uint32_t hv, lv;
      split_pack(x0, x1, hv, lv);
      __stcg((uint32_t*)(Chi + m0 * ldc + n), hv);
      __stcg((uint32_t*)(Clo + m0 * ldc + n), lv);
      split_pack(x2, x3, hv, lv);
      __stcg((uint32_t*)(Chi + (m0 + 8) * ldc + n), hv);
      __stcg((uint32_t*)(Clo + (m0 + 8) * ldc + n), lv);
    }
  }
}

// ---------------- GEMM3 (stage S): k_S[64,16] tile, full K=512, fused RK epilogue ----------------
template<int S>
__device__ __forceinline__ void gemm3_stage(
    bf16* sAh, bf16* sAl, bf16* sBh, bf16* sBl,
    int bm, int bn, const float* __restrict__ b2, double* sd)
{
  const int tid = threadIdx.x;
  const int wid = tid >> 5, lane = tid & 31;
  const int wm = wid & 3, wn = wid >> 2;
  const int grp = lane >> 2, tig = lane & 3;

  float acc[4] = {};

  // fill indexing: A 64 rows x 64 cols (hi+lo, 2 uint4/thread each), B 16 rows (1 uint4, hi or lo)
  const int arow = tid >> 2;
  const int acol = (tid & 3) * 16;
  const int brow = (tid & 127) >> 3;
  const int bcol = (tid & 7) * 8;
  const bool bsel = tid >= 128;
  const bf16* Ah = g_H2hi + (bm + arow) * WW;
  const bf16* Al = g_H2lo + (bm + arow) * WW;
  const bf16* Bs = (bsel ? g_W2lo : g_W2hi) + (bn + brow) * WW;
  bf16* sBd = bsel ? sBl : sBh;

  uint4 pah[2], pal[2], pb;
  pah[0] = __ldcg((const uint4*)(Ah + acol));
  pah[1] = __ldcg((const uint4*)(Ah + acol + 8));
  pal[0] = __ldcg((const uint4*)(Al + acol));
  pal[1] = __ldcg((const uint4*)(Al + acol + 8));
  pb = __ldg((const uint4*)(Bs + bcol));

  for (int c = 0; c < 8; ++c) {
    *(uint4*)(sAh + arow * SAS + acol) = pah[0];
    *(uint4*)(sAh + arow * SAS + acol + 8) = pah[1];
    *(uint4*)(sAl + arow * SAS + acol) = pal[0];
    *(uint4*)(sAl + arow * SAS + acol + 8) = pal[1];
    *(uint4*)(sBd + brow * SAS + bcol) = pb;
    if (c + 1 < 8) {
      int k0 = (c + 1) * 64;
      pah[0] = __ldcg((const uint4*)(Ah + k0 + acol));
      pah[1] = __ldcg((const uint4*)(Ah + k0 + acol + 8));
      pal[0] = __ldcg((const uint4*)(Al + k0 + acol));
      pal[1] = __ldcg((const uint4*)(Al + k0 + acol + 8));
      pb = __ldg((const uint4*)(Bs + k0 + bcol));
    }
    __syncthreads();
    const int r0 = wm * 16 + grp;
    const int nr = wn * 8 + grp;
    #pragma unroll
    for (int ks = 0; ks < 4; ++ks) {
      const int c0 = ks * 16 + tig * 2;
      uint32_t ah[4], al[4], bh[2], bl[2];
      ah[0] = *(const uint32_t*)(sAh + r0 * SAS + c0);
      ah[1] = *(const uint32_t*)(sAh + (r0 + 8) * SAS + c0);
      ah[2] = *(const uint32_t*)(sAh + r0 * SAS + c0 + 8);
      ah[3] = *(const uint32_t*)(sAh + (r0 + 8) * SAS + c0 + 8);
      al[0] = *(const uint32_t*)(sAl + r0 * SAS + c0);
      al[1] = *(const uint32_t*)(sAl + (r0 + 8) * SAS + c0);
      al[2] = *(const uint32_t*)(sAl + r0 * SAS + c0 + 8);
      al[3] = *(const uint32_t*)(sAl + (r0 + 8) * SAS + c0 + 8);
      bh[0] = *(const uint32_t*)(sBh + nr * SAS + c0);
      bh[1] = *(const uint32_t*)(sBh + nr * SAS + c0 + 8);
      bl[0] = *(const uint32_t*)(sBl + nr * SAS + c0);
      bl[1] = *(const uint32_t*)(sBl + nr * SAS + c0 + 8);
      mma16816(acc, ah, bh);
      mma16816(acc, ah, bl);
      mma16816(acc, al, bh);
    }
    __syncthreads();
  }

  // fused epilogue
  const int ml = wm * 16 + grp;
  const int nl = wn * 8 + tig * 2;
  const int n0 = bn + nl;
  const int m0 = bm + ml;
  const float h = g_h;
  const int i0 = m0 * DD + n0;
  const int i1 = (m0 + 8) * DD + n0;
  float bv0 = __ldg(b2 + n0), bv1 = __ldg(b2 + n0 + 1);
  float2 v0 = {acc[0] + bv0, acc[1] + bv1};
  float2 v1 = {acc[2] + bv0, acc[3] + bv1};
  __stcg((float2*)(g_k[S] + i0), v0);
  __stcg((float2*)(g_k[S] + i1), v1);

  const int idxs[2] = {i0, i1};
  const float2 vs[2] = {v0, v1};
  if constexpr (S <= 5) {
    #pragma unroll
    for (int r = 0; r < 2; ++r) {
      int ix = idxs[r];
      float2 y2 = __ldcg((const float2*)(g_y + ix));
      float cS = c_coef[S][S];
      float ax = cS * vs[r].x, ay = cS * vs[r].y;
      #pragma unroll
      for (int j = 0; j < S; ++j) {
        float cj = c_coef[S][j];
        float2 kj = __ldcg((const float2*)(g_k[j] + ix));
        ax = fmaf(cj, kj.x, ax);
        ay = fmaf(cj, kj.y, ay);
      }
      float Xx = fmaf(h, ax, y2.x);
      float Xy = fmaf(h, ay, y2.y);
      if constexpr (S == 5) {
        float2 yn = {Xx, Xy};
        __stcg((float2*)(g_ynew + ix), yn);
      }
      uint32_t hv, lv;
      split_pack(Xx, Xy, hv, lv);
      __stcg((uint32_t*)(g_Xhi + ix), hv);
      __stcg((uint32_t*)(g_Xlo + ix), lv);
    }
  } else {
    double ss = 0.0;
    #pragma unroll
    for (int r = 0; r < 2; ++r) {
      int ix = idxs[r];
      float2 k0 = __ldcg((const float2*)(g_k[0] + ix));
      float2 k1 = __ldcg((const float2*)(g_k[1] + ix));
      float2 k2 = __ldcg((const float2*)(g_k[2] + ix));
      float2 k3 = __ldcg((const float2*)(g_k[3] + ix));
      float2 k4 = __ldcg((const float2*)(g_k[4] + ix));
      float2 k5 = __ldcg((const float2*)(g_k[5] + ix));
      float2 y2 = __ldcg((const float2*)(g_y + ix));
      float2 yn = __ldcg((const float2*)(g_ynew + ix));
      #pragma unroll
      for (int cc = 0; cc < 2; ++cc) {
        float e = Ec1 * (cc ? k0.y : k0.x);
        e = fmaf(Ec2, cc ? k1.y : k1.x, e);
        e = fmaf(Ec3, cc ? k2.y : k2.x, e);
        e = fmaf(Ec4, cc ? k3.y : k3.x, e);
        e = fmaf(Ec5, cc ? k4.y : k4.x, e);
        e = fmaf(Ec6, cc ? k5.y : k5.x, e);
        e = fmaf(Ec7, cc ? vs[r].y : vs[r].x, e);
        float err = h * e;
        float yv = cc ? y2.y : y2.x, ynv = cc ? yn.y : yn.x;
        float scale = ATOLc + RTOLc * fmaxf(fabsf(yv), fabsf(ynv));
        float rr = err / scale;
        ss += (double)rr * (double)rr;
      }
    }
    sd[tid] = ss;
    __syncthreads();
    #pragma unroll
    for (int s2 = 128; s2 > 0; s2 >>= 1) {
      if (tid < s2) sd[tid] += sd[tid + s2];
      __syncthreads();
    }
    if (tid == 0) ((volatile double*)g_errpart)[blockIdx.x] = sd[0];
  }
}

// ---------------- one RK stage (group-local syncs) ----------------
template<int S>
__device__ __forceinline__ void do_stage(int bid, int grp_id, unsigned& ep,
    const float* b0, const float* b1, const float* b2,
    bf16* sAhi, bf16* sAlo, bf16* sBhi, bf16* sBlo, double* sd)
{
  const int bm = (bid >> 4) << 7;
  const int bn = (bid & 15) << 5;
  mma_gemm<true>(g_Xhi, g_Xlo, g_W0hi, g_W0lo, DD, bm, bn, 2, b0, g_H1hi, g_H1lo, WW,
                 sAhi, sAlo, sBhi, sBlo);
  ggsync(grp_id, ep++);
  mma_gemm<true>(g_H1hi, g_H1lo, g_W1hi, g_W1lo, WW, bm, bn, 8, b1, g_H2hi, g_H2lo, WW,
                 sAhi, sAlo, sBhi, sBlo);
  ggsync(grp_id, ep++);
  gemm3_stage<S>(sAhi, sAlo, sBhi, sBlo, (bid >> 3) << 6, (bid & 7) << 4, b2, sd);
  if (S < 6) ggsync(grp_id, ep++);
}

__device__ __forceinline__ void update_phase(int gid4, float* __restrict__ out) {
  float4 v;
  if (g_accept) {
    v = __ldcg((const float4*)(g_ynew + gid4));
    __stcg((float4*)(g_y + gid4), v);
    if (g_hit) *(float4*)(out + g_wrow * NELEM + gid4) = v;
  } else {
    v = __ldcg((const float4*)(g_y + gid4));
  }
  uint2 hv, lv;
  split_pack(v.x, v.y, hv.x, lv.x);
  split_pack(v.z, v.w, hv.y, lv.y);
  __stcg((uint2*)(g_Xhi + gid4), hv);
  __stcg((uint2*)(g_Xlo + gid4), lv);
}

// ---------------- persistent solver ----------------
__global__ void __launch_bounds__(NTHR, 1) solve_kernel(
    const float* __restrict__ ts,
    const float* __restrict__ b0, const float* __restrict__ b1,
    const float* __restrict__ b2, float* __restrict__ out)
{
  __shared__ __align__(16) bf16 sAhi[128 * SAS];
  __shared__ __align__(16) bf16 sAlo[128 * SAS];
  __shared__ __align__(16) bf16 sBhi[32 * SAS];
  __shared__ __align__(16) bf16 sBlo[32 * SAS];
  __shared__ double sd[NTHR];

  const int bid = blockIdx.x;
  const int tid = threadIdx.x;
  const int grp_id = bid >> 4;
  const int gid4 = (bid * NTHR + tid) * 4;
  unsigned ep = 1;

  for (int step = 0; step < MAX_STEPS; ++step) {
    update_phase(gid4, out);
    ggsync(grp_id, ep++);

    do_stage<0>(bid, grp_id, ep, b0, b1, b2, sAhi, sAlo, sBhi, sBlo, sd);
    do_stage<1>(bid, grp_id, ep, b0, b1, b2, sAhi, sAlo, sBhi, sBlo, sd);
    do_stage<2>(bid, grp_id, ep, b0, b1, b2, sAhi, sAlo, sBhi, sBlo, sd);
    do_stage<3>(bid, grp_id, ep, b0, b1, b2, sAhi, sAlo, sBhi, sBlo, sd);
    do_stage<4>(bid, grp_id, ep, b0, b1, b2, sAhi, sAlo, sBhi, sBlo, sd);
    do_stage<5>(bid, grp_id, ep, b0, b1, b2, sAhi, sAlo, sBhi, sBlo, sd);
    do_stage<6>(bid, grp_id, ep, b0, b1, b2, sAhi, sAlo, sBhi, sBlo, sd);

    gsync();   // err partials visible everywhere

    if (bid == 0) {
      double v = (tid < NBLK) ? ((volatile double*)g_errpart)[tid] : 0.0;
      sd[tid] = v;
      __syncthreads();
      #pragma unroll
      for (int s2 = 128; s2 > 0; s2 >>= 1) {
        if (tid < s2) sd[tid] += sd[tid + s2];
        __syncthreads();
      }
      if (tid == 0) {
        float enorm = sqrtf((float)(sd[0] / (double)NELEM));
        int done = g_done;
        float h = g_h;
        int accept = (enorm <= 1.0f) && !done;
        float t_new = g_t + h;
        int hit = accept && (t_new >= g_tns - 1e-6f);
        if (accept) g_t = t_new;
        g_accept = accept;
        g_hit = hit;
        g_wrow = g_sic;
        int si = g_si + hit;
        g_si = si;
        float factor;
        if (enorm > 0.f) {
          factor = 0.9f * powf(enorm, -0.2f);
          factor = fminf(fmaxf(factor, 0.2f), 10.f);
        } else factor = 10.f;
        if (!done) g_dt = g_dt * factor;
        // fold next step's "pre" phase
        int done2 = (si >= TT) ? 1 : 0;
        int sic2 = si < (TT - 1) ? si : (TT - 1);
        float tns2 = __ldg(ts + sic2);
        float h2 = done2 ? 0.f : fmaxf(fminf(g_dt, tns2 - g_t), 0.f);
        g_done = done2; g_sic = sic2; g_tns = tns2; g_h = h2;
      }
    }
    gsync();   // controller state visible
  }
  update_phase(gid4, out);
}

// ---------------- init ----------------
__global__ void init_kernel(const float* __restrict__ ts, const float* __restrict__ y0,
                            const float* __restrict__ W0, const float* __restrict__ W1,
                            const float* __restrict__ W2, float* __restrict__ out)
{
  int idx = blockIdx.x * NTHR + threadIdx.x;
  if (idx < TT * NELEM) out[idx] = (idx < NELEM) ? y0[idx] : 0.f;
  if (idx < NELEM) {
    float v = y0[idx];
    g_y[idx] = v;
    bf16 h = __float2bfloat16(v);
    g_Xhi[idx] = h;
    g_Xlo[idx] = __float2bfloat16(v - __bfloat162float(h));
  }
  if (idx < WW * DD) {
    float w = W0[idx];
    bf16 h = __float2bfloat16(w);
    g_W0hi[idx] = h; g_W0lo[idx] = __float2bfloat16(w - __bfloat162float(h));
    float w2 = W2[idx];
    bf16 h2 = __float2bfloat16(w2);
    g_W2hi[idx] = h2; g_W2lo[idx] = __float2bfloat16(w2 - __bfloat162float(h2));
  }
  if (idx < WW * WW) {
    float w = W1[idx];
    bf16 h = __float2bfloat16(w);
    g_W1hi[idx] = h; g_W1lo[idx] = __float2bfloat16(w - __bfloat162float(h));
  }
  if (idx < NBLK * 32) gg_flag[idx] = 0u;
  if (idx == 0) {
    float t0 = ts[0];
    float dt0 = ts[1] - ts[0];
    g_t = t0;
    g_dt = dt0;
    g_si = 1;
    g_accept = 0;
    g_hit = 0;
    g_wrow = 0;
    g_arrive = 0u;
    g_done = 0;
    g_sic = 1;
    float tns = ts[1];
    g_tns = tns;
    g_h = fmaxf(fminf(dt0, tns - t0), 0.f);
  }
}

extern "C" void kernel_launch(void* const* d_in, const int* in_sizes, int n_in,
                              void* d_out, int out_size) {
  const float* ts = (const float*)d_in[0];
  const float* y0 = (const float*)d_in[1];
  const float* W0 = (const float*)d_in[2];
  const float* b0 = (const float*)d_in[3];
  const float* W1 = (const float*)d_in[4];
  const float* b1 = (const float*)d_in[5];
  const float* W2 = (const float*)d_in[6];
  const float* b2 = (const float*)d_in[7];
  float* out = (float*)d_out;

  init_kernel<<<(TT * NELEM) / NTHR, NTHR>>>(ts, y0, W0, W1, W2, out);
  solve_kernel<<<NBLK, NTHR>>>(ts, b0, b1, b2, out);
}

// round 9
// speedup vs baseline: 1.5011x; 1.0551x over previous
#include <cuda_runtime.h>
#include <cuda_bf16.h>
#include <math.h>
#include <stdint.h>

typedef __nv_bfloat16 bf16;

#define BB 1024
#define DD 128
#define WW 512
#define TT 8
#define NELEM (BB*DD)
#define HELEM (BB*WW)
#define MAX_STEPS 48
#define NBLK 256
#define NTHR 256
#define GCTA 16            // CTAs per group
#define RTOLc 1e-3f
#define ATOLc 1e-6f
#define SAS 72             // smem row stride in bf16 (144B)

#define A21f 0.161f
#define A31f (-0.008480655492356989f)
#define A32f 0.335480655492357f
#define A41f 2.8971530571054935f
#define A42f (-6.359448489975075f)
#define A43f 4.3622954328695815f
#define A51f 5.325864828439257f
#define A52f (-11.748883564062828f)
#define A53f 7.4955393428898365f
#define A54f (-0.09249506636175525f)
#define A61f 5.86145544294642f
#define A62f (-12.92096931784711f)
#define A63f 8.159367898576159f
#define A64f (-0.071584973281401f)
#define A65f (-0.028269050394068383f)
#define Bc1 0.09646076681806523f
#define Bc2 0.01f
#define Bc3 0.4798896504144996f
#define Bc4 1.379008574103742f
#define Bc5 (-3.290069515436081f)
#define Bc6 2.324710524099774f
#define Ec1 (-0.00178001105222577714f)
#define Ec2 (-0.0008164344596567469f)
#define Ec3 0.007880878010261995f
#define Ec4 (-0.1447110071732629f)
#define Ec5 0.5823571654525552f
#define Ec6 (-0.45808210592918697f)
#define Ec7 0.015151515151515152f

// ---------------- device state ----------------
__device__ __align__(16) float g_y[NELEM], g_ynew[NELEM], g_k[7][NELEM];
__device__ __align__(16) bf16 g_Xhi[NELEM], g_Xlo[NELEM];
__device__ __align__(16) bf16 g_H1hi[HELEM], g_H1lo[HELEM];
__device__ __align__(16) bf16 g_H2hi[HELEM], g_H2lo[HELEM];
__device__ __align__(16) bf16 g_W0hi[WW*DD], g_W0lo[WW*DD];
__device__ __align__(16) bf16 g_W1hi[WW*WW], g_W1lo[WW*WW];
__device__ __align__(16) bf16 g_W2hi[DD*WW], g_W2lo[DD*WW];
__device__ double g_errpart[NBLK];
__device__ volatile float g_t, g_dt, g_h, g_tns;
__device__ volatile int g_si, g_sic, g_done, g_accept, g_hit, g_wrow;
__device__ unsigned g_arrive;
__device__ volatile unsigned gg_flag[NBLK * 32];

__constant__ float c_coef[6][6] = {
  {A21f,0,0,0,0,0},
  {A31f,A32f,0,0,0,0},
  {A41f,A42f,A43f,0,0,0},
  {A51f,A52f,A53f,A54f,0,0},
  {A61f,A62f,A63f,A64f,A65f,0},
  {Bc1,Bc2,Bc3,Bc4,Bc5,Bc6},
};

// ---------------- barriers ----------------
__device__ __forceinline__ void gsync() {
  __syncthreads();
  if (threadIdx.x == 0) {
    __threadfence();
    unsigned t = atomicAdd(&g_arrive, 1u) + 1u;
    unsigned target = ((t + NBLK - 1u) / NBLK) * NBLK;
    while (*(volatile unsigned*)&g_arrive < target) {}
    __threadfence();
  }
  __syncthreads();
}
__device__ __forceinline__ void ggsync(int grp, unsigned ep) {
  __syncthreads();
  if (threadIdx.x == 0) {
    __threadfence();
    gg_flag[blockIdx.x * 32] = ep;
  }
  if (threadIdx.x < GCTA) {
    const volatile unsigned* f = &gg_flag[(grp * GCTA + threadIdx.x) * 32];
    while (*f < ep) {}
  }
  __syncthreads();
}

// ---------------- math helpers ----------------
__device__ __forceinline__ void mma16816(float* c, const uint32_t* a, const uint32_t* b) {
  asm volatile(
    "mma.sync.aligned.m16n8k16.row.col.f32.bf16.bf16.f32 "
    "{%0,%1,%2,%3}, {%4,%5,%6,%7}, {%8,%9}, {%0,%1,%2,%3};"
    : "+f"(c[0]), "+f"(c[1]), "+f"(c[2]), "+f"(c[3])
    : "r"(a[0]), "r"(a[1]), "r"(a[2]), "r"(a[3]), "r"(b[0]), "r"(b[1]));
}

// MUFU-free softplus (abs err ~2e-6)
__device__ __forceinline__ float softplus_f(float x) {
  float t = fabsf(x);
  float s = fminf(t * 1.4426950408889634f, 100.f);
  float n = floorf(s);
  float r = n - s;
  float p = 1.3215487e-6f;
  p = fmaf(p, r, 1.5252734e-5f);
  p = fmaf(p, r, 1.5403530e-4f);
  p = fmaf(p, r, 1.3333558e-3f);
  p = fmaf(p, r, 9.6181291e-3f);
  p = fmaf(p, r, 5.5504109e-2f);
  p = fmaf(p, r, 2.4022651e-1f);
  p = fmaf(p, r, 6.9314718e-1f);
  p = fmaf(p, r, 1.0f);
  float u = p * __uint_as_float((uint32_t)(127 - (int)n) << 23);
  float d = 2.f + u;
  float w = fmaf(-0.1635f, u, 0.4915f);
  w = w * fmaf(-d, w, 2.f);
  w = w * fmaf(-d, w, 2.f);
  float v = u * w;
  float v2 = v * v;
  float g = 0.09090909f;
  g = fmaf(g, v2, 0.11111111f);
  g = fmaf(g, v2, 0.14285714f);
  g = fmaf(g, v2, 0.2f);
  g = fmaf(g, v2, 0.33333333f);
  g = fmaf(g, v2, 1.0f);
  return fmaxf(x, 0.f) + 2.f * v * g;
}

__device__ __forceinline__ void split_pack(float x0, float x1, uint32_t& hv, uint32_t& lv) {
  bf16 h0 = __float2bfloat16(x0), h1 = __float2bfloat16(x1);
  bf16 l0 = __float2bfloat16(x0 - __bfloat162float(h0));
  bf16 l1 = __float2bfloat16(x1 - __bfloat162float(h1));
  hv = (uint32_t)__bfloat16_as_ushort(h0) | ((uint32_t)__bfloat16_as_ushort(h1) << 16);
  lv = (uint32_t)__bfloat16_as_ushort(l0) | ((uint32_t)__bfloat16_as_ushort(l1) << 16);
}

// ---------------- GEMM1/2: C[64,32] = act(A[64,K] @ B[32,K]^T + bias) -> bf16 hi/lo ----------------
template<bool SP>
__device__ __forceinline__ void mma_gemm(
    const bf16* __restrict__ Ahi, const bf16* __restrict__ Alo,
    const bf16* __restrict__ Bhi, const bf16* __restrict__ Blo,
    int ldk, int bm, int bn, int nchunk,
    const float* __restrict__ bias,
    bf16* __restrict__ Chi, bf16* __restrict__ Clo, int ldc,
    bf16* sAhi, bf16* sAlo, bf16* sBhi, bf16* sBlo)
{
  const int tid = threadIdx.x;
  const int wid = tid >> 5;
  const int lane = tid & 31;
  const int grp = lane >> 2, tig = lane & 3;
  const int wm = wid >> 1, wn = wid & 1;   // 4 x 2 warps over 64x32

  float acc[2][4] = {};

  // A fill: 1024 uint4 over {hi,lo} x 64 rows x 8 segs -> 4/thread
  int ar[4], as[4]; bool asel[4];
  #pragma unroll
  for (int i = 0; i < 4; ++i) {
    int lin = i * 256 + tid;
    asel[i] = lin >= 512;
    ar[i] = (lin >> 3) & 63;
    as[i] = (lin & 7) << 3;
  }
  // B fill: 512 uint4 over {hi,lo} x 32 rows x 8 segs -> 2/thread
  int br[2], bs[2]; bool bsel[2];
  #pragma unroll
  for (int i = 0; i < 2; ++i) {
    int lin = i * 256 + tid;
    bsel[i] = lin >= 256;
    br[i] = (lin >> 3) & 31;
    bs[i] = (lin & 7) << 3;
  }

  uint4 pa[4], pb[2];
  #pragma unroll
  for (int i = 0; i < 4; ++i) {
    const bf16* A = asel[i] ? Alo : Ahi;
    pa[i] = __ldcg((const uint4*)(A + (bm + ar[i]) * ldk + as[i]));
  }
  #pragma unroll
  for (int i = 0; i < 2; ++i) {
    const bf16* B = bsel[i] ? Blo : Bhi;
    pb[i] = __ldg((const uint4*)(B + (bn + br[i]) * ldk + bs[i]));
  }

  for (int c = 0; c < nchunk; ++c) {
    #pragma unroll
    for (int i = 0; i < 4; ++i) {
      bf16* sA = asel[i] ? sAlo : sAhi;
      *(uint4*)(sA + ar[i] * SAS + as[i]) = pa[i];
    }
    #pragma unroll
    for (int i = 0; i < 2; ++i) {
      bf16* sB = bsel[i] ? sBlo : sBhi;
      *(uint4*)(sB + br[i] * SAS + bs[i]) = pb[i];
    }
    if (c + 1 < nchunk) {
      int k0 = (c + 1) * 64;
      #pragma unroll
      for (int i = 0; i < 4; ++i) {
        const bf16* A = asel[i] ? Alo : Ahi;
        pa[i] = __ldcg((const uint4*)(A + (bm + ar[i]) * ldk + k0 + as[i]));
      }
      #pragma unroll
      for (int i = 0; i < 2; ++i) {
        const bf16* B = bsel[i] ? Blo : Bhi;
        pb[i] = __ldg((const uint4*)(B + (bn + br[i]) * ldk + k0 + bs[i]));
      }
    }
    __syncthreads();
    #pragma unroll
    for (int ks = 0; ks < 4; ++ks) {
      const int c0 = ks * 16 + tig * 2;
      const int r0 = wm * 16 + grp;
      uint32_t ah[4], al[4];
      ah[0] = *(const uint32_t*)(sAhi + r0 * SAS + c0);
      ah[1] = *(const uint32_t*)(sAhi + (r0 + 8) * SAS + c0);
      ah[2] = *(const uint32_t*)(sAhi + r0 * SAS + c0 + 8);
      ah[3] = *(const uint32_t*)(sAhi + (r0 + 8) * SAS + c0 + 8);
      al[0] = *(const uint32_t*)(sAlo + r0 * SAS + c0);
      al[1] = *(const uint32_t*)(sAlo + (r0 + 8) * SAS + c0);
      al[2] = *(const uint32_t*)(sAlo + r0 * SAS + c0 + 8);
      al[3] = *(const uint32_t*)(sAlo + (r0 + 8) * SAS + c0 + 8);
      #pragma unroll
      for (int ni = 0; ni < 2; ++ni) {
        int nr = wn * 16 + ni * 8 + grp;
        uint32_t bh[2], bl[2];
        bh[0] = *(const uint32_t*)(sBhi + nr * SAS + c0);
        bh[1] = *(const uint32_t*)(sBhi + nr * SAS + c0 + 8);
        bl[0] = *(const uint32_t*)(sBlo + nr * SAS + c0);
        bl[1] = *(const uint32_t*)(sBlo + nr * SAS + c0 + 8);
        mma16816(acc[ni], ah, bh);
        mma16816(acc[ni], ah, bl);
        mma16816(acc[ni], al, bh);
      }
    }
    __syncthreads();
  }

  #pragma unroll
  for (int ni = 0; ni < 2; ++ni) {
    int m0 = bm + wm * 16 + grp;
    int n  = bn + wn * 16 + ni * 8 + tig * 2;
    float bv0 = __ldg(bias + n), bv1 = __ldg(bias + n + 1);
    float x0 = acc[ni][0] + bv0, x1 = acc[ni][1] + bv1;
    float x2 = acc[ni][2] + bv0, x3 = acc[ni][3] + bv1;
    if (SP) { x0 = softplus_f(x0); x1 = softplus_f(x1); x2 = softplus_f(x2); x3 = softplus_f(x3); }
    uint32_t hv, lv;
    split_pack(x0, x1, hv, lv);
    __stcg((uint32_t*)(Chi + m0 * ldc + n), hv);
    __stcg((uint32_t*)(Clo + m0 * ldc + n), lv);
    split_pack(x2, x3, hv, lv);
    __stcg((uint32_t*)(Chi + (m0 + 8) * ldc + n), hv);
    __stcg((uint32_t*)(Clo + (m0 + 8) * ldc + n), lv);
  }
}

// ---------------- GEMM3 (stage S): k_S[64,8] tile, K=512, fused RK epilogue ----------------
template<int S>
__device__ __forceinline__ void gemm3_stage(
    bf16* sAh, bf16* sAl, bf16* sBh, bf16* sBl, float* sred,
    int bm, int bn, const float* __restrict__ b2, double* sd)
{
  const int tid = threadIdx.x;
  const int wid = tid >> 5, lane = tid & 31;
  const int wm = wid & 3, wk = wid >> 2;       // 4 m-warps x 2 k-halves
  const int grp = lane >> 2, tig = lane & 3;

  float acc[4] = {};

  // A fill: identical layout to mma_gemm (64 rows)
  int ar[4], as[4]; bool asel[4];
  #pragma unroll
  for (int i = 0; i < 4; ++i) {
    int lin = i * 256 + tid;
    asel[i] = lin >= 512;
    ar[i] = (lin >> 3) & 63;
    as[i] = (lin & 7) << 3;
  }
  // B fill: 8 rows x 8 segs x {hi,lo} = 128 uint4 -> threads 0..127
  const bool bon = tid < 128;
  const bool bsel = tid >= 64;
  const int brow = (tid >> 3) & 7;
  const int bseg = (tid & 7) << 3;

  uint4 pa[4], pb;
  #pragma unroll
  for (int i = 0; i < 4; ++i) {
    const bf16* A = asel[i] ? g_H2lo : g_H2hi;
    pa[i] = __ldcg((const uint4*)(A + (bm + ar[i]) * WW + as[i]));
  }
  if (bon) {
    const bf16* B = bsel ? g_W2lo : g_W2hi;
    pb = __ldg((const uint4*)(B + (bn + brow) * WW + bseg));
  }

  for (int c = 0; c < 8; ++c) {
    #pragma unroll
    for (int i = 0; i < 4; ++i) {
      bf16* sA = asel[i] ? sAl : sAh;
      *(uint4*)(sA + ar[i] * SAS + as[i]) = pa[i];
    }
    if (bon) {
      bf16* sB = bsel ? sBl : sBh;
      *(uint4*)(sB + brow * SAS + bseg) = pb;
    }
    if (c + 1 < 8) {
      int k0 = (c + 1) * 64;
      #pragma unroll
      for (int i = 0; i < 4; ++i) {
        const bf16* A = asel[i] ? g_H2lo : g_H2hi;
        pa[i] = __ldcg((const uint4*)(A + (bm + ar[i]) * WW + k0 + as[i]));
      }
      if (bon) {
        const bf16* B = bsel ? g_W2lo : g_W2hi;
        pb = __ldg((const uint4*)(B + (bn + brow) * WW + k0 + bseg));
      }
    }
    __syncthreads();
    #pragma unroll
    for (int ks2 = 0; ks2 < 2; ++ks2) {
      const int ks = wk * 2 + ks2;
      const int c0 = ks * 16 + tig * 2;
      const int r0 = wm * 16 + grp;
      uint32_t ah[4], al[4], bh[2], bl[2];
      ah[0] = *(const uint32_t*)(sAh + r0 * SAS + c0);
      ah[1] = *(const uint32_t*)(sAh + (r0 + 8) * SAS + c0);
      ah[2] = *(const uint32_t*)(sAh + r0 * SAS + c0 + 8);
      ah[3] = *(const uint32_t*)(sAh + (r0 + 8) * SAS + c0 + 8);
      al[0] = *(const uint32_t*)(sAl + r0 * SAS + c0);
      al[1] = *(const uint32_t*)(sAl + (r0 + 8) * SAS + c0);
      al[2] = *(const uint32_t*)(sAl + r0 * SAS + c0 + 8);
      al[3] = *(const uint32_t*)(sAl + (r0 + 8) * SAS + c0 + 8);
      bh[0] = *(const uint32_t*)(sBh + grp * SAS + c0);
      bh[1] = *(const uint32_t*)(sBh + grp * SAS + c0 + 8);
      bl[0] = *(const uint32_t*)(sBl + grp * SAS + c0);
      bl[1] = *(const uint32_t*)(sBl + grp * SAS + c0 + 8);
      mma16816(acc, ah, bh);
      mma16816(acc, ah, bl);
      mma16816(acc, al, bh);
    }
    __syncthreads();
  }

  // reduce across the two k-half warp sets
  const int ml = wm * 16 + grp;
  const int nl = tig * 2;
  if (wk == 1) {
    sred[ml * 8 + nl]           = acc[0];
    sred[ml * 8 + nl + 1]       = acc[1];
    sred[(ml + 8) * 8 + nl]     = acc[2];
    sred[(ml + 8) * 8 + nl + 1] = acc[3];
  }
  __syncthreads();
  double ss = 0.0;
  if (wk == 0) {
    acc[0] += sred[ml * 8 + nl];
    acc[1] += sred[ml * 8 + nl + 1];
    acc[2] += sred[(ml + 8) * 8 + nl];
    acc[3] += sred[(ml + 8) * 8 + nl + 1];

    const int n0 = bn + nl;
    const int m0 = bm + ml;
    const float h = g_h;
    const int i0 = m0 * DD + n0;
    const int i1 = (m0 + 8) * DD + n0;
    float bv0 = __ldg(b2 + n0), bv1 = __ldg(b2 + n0 + 1);
    float2 v0 = {acc[0] + bv0, acc[1] + bv1};
    float2 v1 = {acc[2] + bv0, acc[3] + bv1};
    __stcg((float2*)(g_k[S] + i0), v0);
    __stcg((float2*)(g_k[S] + i1), v1);

    const int idxs[2] = {i0, i1};
    const float2 vs[2] = {v0, v1};
    if constexpr (S <= 5) {
      #pragma unroll
      for (int r = 0; r < 2; ++r) {
        int ix = idxs[r];
        float2 y2 = __ldcg((const float2*)(g_y + ix));
        float cS = c_coef[S][S];
        float ax = cS * vs[r].x, ay = cS * vs[r].y;
        #pragma unroll
        for (int j = 0; j < S; ++j) {
          float cj = c_coef[S][j];
          float2 kj = __ldcg((const float2*)(g_k[j] + ix));
          ax = fmaf(cj, kj.x, ax);
          ay = fmaf(cj, kj.y, ay);
        }
        float Xx = fmaf(h, ax, y2.x);
        float Xy = fmaf(h, ay, y2.y);
        if constexpr (S == 5) {
          float2 yn = {Xx, Xy};
          __stcg((float2*)(g_ynew + ix), yn);
        }
        uint32_t hv, lv;
        split_pack(Xx, Xy, hv, lv);
        __stcg((uint32_t*)(g_Xhi + ix), hv);
        __stcg((uint32_t*)(g_Xlo + ix), lv);
      }
    } else {
      #pragma unroll
      for (int r = 0; r < 2; ++r) {
        int ix = idxs[r];
        float2 k0 = __ldcg((const float2*)(g_k[0] + ix));
        float2 k1 = __ldcg((const float2*)(g_k[1] + ix));
        float2 k2 = __ldcg((const float2*)(g_k[2] + ix));
        float2 k3 = __ldcg((const float2*)(g_k[3] + ix));
        float2 k4 = __ldcg((const float2*)(g_k[4] + ix));
        float2 k5 = __ldcg((const float2*)(g_k[5] + ix));
        float2 y2 = __ldcg((const float2*)(g_y + ix));
        float2 yn = __ldcg((const float2*)(g_ynew + ix));
        #pragma unroll
        for (int cc = 0; cc < 2; ++cc) {
          float e = Ec1 * (cc ? k0.y : k0.x);
          e = fmaf(Ec2, cc ? k1.y : k1.x, e);
          e = fmaf(Ec3, cc ? k2.y : k2.x, e);
          e = fmaf(Ec4, cc ? k3.y : k3.x, e);
          e = fmaf(Ec5, cc ? k4.y : k4.x, e);
          e = fmaf(Ec6, cc ? k5.y : k5.x, e);
          e = fmaf(Ec7, cc ? vs[r].y : vs[r].x, e);
          float err = h * e;
          float yv = cc ? y2.y : y2.x, ynv = cc ? yn.y : yn.x;
          float scale = ATOLc + RTOLc * fmaxf(fabsf(yv), fabsf(ynv));
          float rr = err / scale;
          ss += (double)rr * (double)rr;
        }
      }
    }
  }
  if constexpr (S == 6) {
    sd[tid] = ss;
    __syncthreads();
    #pragma unroll
    for (int s2 = 128; s2 > 0; s2 >>= 1) {
      if (tid < s2) sd[tid] += sd[tid + s2];
      __syncthreads();
    }
    if (tid == 0) ((volatile double*)g_errpart)[blockIdx.x] = sd[0];
  }
}

// ---------------- one RK stage (group-local syncs) ----------------
template<int S>
__device__ __forceinline__ void do_stage(int grp_id, int lbid, unsigned& ep,
    const float* b0, const float* b1, const float* b2,
    bf16* sAhi, bf16* sAlo, bf16* sBhi, bf16* sBlo, float* sred, double* sd)
{
  const int bm = grp_id << 6;     // group owns 64 batch rows
  const int bn = lbid << 5;       // N=32 per CTA for GEMM1/2
  mma_gemm<true>(g_Xhi, g_Xlo, g_W0hi, g_W0lo, DD, bm, bn, 2, b0, g_H1hi, g_H1lo, WW,
                 sAhi, sAlo, sBhi, sBlo);
  ggsync(grp_id, ep++);
  mma_gemm<true>(g_H1hi, g_H1lo, g_W1hi, g_W1lo, WW, bm, bn, 8, b1, g_H2hi, g_H2lo, WW,
                 sAhi, sAlo, sBhi, sBlo);
  ggsync(grp_id, ep++);
  gemm3_stage<S>(sAhi, sAlo, sBhi, sBlo, sred, bm, lbid << 3, b2, sd);
  if (S < 6) ggsync(grp_id, ep++);
}

__device__ __forceinline__ void update_phase(int gid2, float* __restrict__ out) {
  float2 v;
  if (g_accept) {
    v = __ldcg((const float2*)(g_ynew + gid2));
    __stcg((float2*)(g_y + gid2), v);
    if (g_hit) *(float2*)(out + g_wrow * NELEM + gid2) = v;
  } else {
    v = __ldcg((const float2*)(g_y + gid2));
  }
  uint32_t hv, lv;
  split_pack(v.x, v.y, hv, lv);
  __stcg((uint32_t*)(g_Xhi + gid2), hv);
  __stcg((uint32_t*)(g_Xlo + gid2), lv);
}

// ---------------- persistent solver ----------------
__global__ void __launch_bounds__(NTHR, 2) solve_kernel(
    const float* __restrict__ ts,
    const float* __restrict__ b0, const float* __restrict__ b1,
    const float* __restrict__ b2, float* __restrict__ out)
{
  __shared__ __align__(16) bf16 sAhi[64 * SAS];
  __shared__ __align__(16) bf16 sAlo[64 * SAS];
  __shared__ __align__(16) bf16 sBhi[32 * SAS];
  __shared__ __align__(16) bf16 sBlo[32 * SAS];
  __shared__ float sred[64 * 8];
  __shared__ double sd[NTHR];

  const int bid = blockIdx.x;
  const int tid = threadIdx.x;
  const int grp_id = bid >> 4;
  const int lbid = bid & 15;
  const int gid2 = (bid * NTHR + tid) * 2;
  unsigned ep = 1;

  for (int step = 0; step < MAX_STEPS; ++step) {
    update_phase(gid2, out);
    ggsync(grp_id, ep++);

    do_stage<0>(grp_id, lbid, ep, b0, b1, b2, sAhi, sAlo, sBhi, sBlo, sred, sd);
    do_stage<1>(grp_id, lbid, ep, b0, b1, b2, sAhi, sAlo, sBhi, sBlo, sred, sd);
    do_stage<2>(grp_id, lbid, ep, b0, b1, b2, sAhi, sAlo, sBhi, sBlo, sred, sd);
    do_stage<3>(grp_id, lbid, ep, b0, b1, b2, sAhi, sAlo, sBhi, sBlo, sred, sd);
    do_stage<4>(grp_id, lbid, ep, b0, b1, b2, sAhi, sAlo, sBhi, sBlo, sred, sd);
    do_stage<5>(grp_id, lbid, ep, b0, b1, b2, sAhi, sAlo, sBhi, sBlo, sred, sd);
    do_stage<6>(grp_id, lbid, ep, b0, b1, b2, sAhi, sAlo, sBhi, sBlo, sred, sd);

    gsync();   // all err partials visible

    if (bid == 0) {
      double v = ((volatile double*)g_errpart)[tid];
      sd[tid] = v;
      __syncthreads();
      #pragma unroll
      for (int s2 = 128; s2 > 0; s2 >>= 1) {
        if (tid < s2) sd[tid] += sd[tid + s2];
        __syncthreads();
      }
      if (tid == 0) {
        float enorm = sqrtf((float)(sd[0] / (double)NELEM));
        int done = g_done;
        float h = g_h;
        int accept = (enorm <= 1.0f) && !done;
        float t_new = g_t + h;
        int hit = accept && (t_new >= g_tns - 1e-6f);
        if (accept) g_t = t_new;
        g_accept = accept;
        g_hit = hit;
        g_wrow = g_sic;
        int si = g_si + hit;
        g_si = si;
        float factor;
        if (enorm > 0.f) {
          factor = 0.9f * powf(enorm, -0.2f);
          factor = fminf(fmaxf(factor, 0.2f), 10.f);
        } else factor = 10.f;
        if (!done) g_dt = g_dt * factor;
        int done2 = (si >= TT) ? 1 : 0;
        int sic2 = si < (TT - 1) ? si : (TT - 1);
        float tns2 = __ldg(ts + sic2);
        float h2 = done2 ? 0.f : fmaxf(fminf(g_dt, tns2 - g_t), 0.f);
        g_done = done2; g_sic = sic2; g_tns = tns2; g_h = h2;
      }
    }
    gsync();   // controller state visible
  }
  update_phase(gid2, out);
}

// ---------------- init ----------------
__global__ void init_kernel(const float* __restrict__ ts, const float* __restrict__ y0,
                            const float* __restrict__ W0, const float* __restrict__ W1,
                            const float* __restrict__ W2, float* __restrict__ out)
{
  int idx = blockIdx.x * NTHR + threadIdx.x;
  if (idx < TT * NELEM) out[idx] = (idx < NELEM) ? y0[idx] : 0.f;
  if (idx < NELEM) {
    float v = y0[idx];
    g_y[idx] = v;
    bf16 h = __float2bfloat16(v);
    g_Xhi[idx] = h;
    g_Xlo[idx] = __float2bfloat16(v - __bfloat162float(h));
  }
  if (idx < WW * DD) {
    float w = W0[idx];
    bf16 h = __float2bfloat16(w);
    g_W0hi[idx] = h; g_W0lo[idx] = __float2bfloat16(w - __bfloat162float(h));
    float w2 = W2[idx];
    bf16 h2 = __float2bfloat16(w2);
    g_W2hi[idx] = h2; g_W2lo[idx] = __float2bfloat16(w2 - __bfloat162float(h2));
  }
  if (idx < WW * WW) {
    float w = W1[idx];
    bf16 h = __float2bfloat16(w);
    g_W1hi[idx] = h; g_W1lo[idx] = __float2bfloat16(w - __bfloat162float(h));
  }
  if (idx < NBLK * 32) gg_flag[idx] = 0u;
  if (idx < NBLK) g_errpart[idx] = 0.0;
  if (idx == 0) {
    float t0 = ts[0];
    float dt0 = ts[1] - ts[0];
    g_t = t0;
    g_dt = dt0;
    g_si = 1;
    g_accept = 0;
    g_hit = 0;
    g_wrow = 0;
    g_arrive = 0u;
    g_done = 0;
    g_sic = 1;
    float tns = ts[1];
    g_tns = tns;
    g_h = fmaxf(fminf(dt0, tns - t0), 0.f);
  }
}

extern "C" void kernel_launch(void* const* d_in, const int* in_sizes, int n_in,
                              void* d_out, int out_size) {
  const float* ts = (const float*)d_in[0];
  const float* y0 = (const float*)d_in[1];
  const float* W0 = (const float*)d_in[2];
  const float* b0 = (const float*)d_in[3];
  const float* W1 = (const float*)d_in[4];
  const float* b1 = (const float*)d_in[5];
  const float* W2 = (const float*)d_in[6];
  const float* b2 = (const float*)d_in[7];
  float* out = (float*)d_out;

  init_kernel<<<(TT * NELEM) / NTHR, NTHR>>>(ts, y0, W0, W1, W2, out);
  solve_kernel<<<NBLK, NTHR>>>(ts, b0, b1, b2, out);
}

// round 11
// speedup vs baseline: 1.6106x; 1.0730x over previous
#include <cuda_runtime.h>
#include <cuda_bf16.h>
#include <math.h>
#include <stdint.h>

typedef __nv_bfloat16 bf16;

#define BB 1024
#define DD 128
#define WW 512
#define TT 8
#define NELEM (BB*DD)
#define HELEM (BB*WW)
#define MAX_STEPS 48
#define NBLK 256
#define NTHR 256
#define GCTA 16
#define RTOLc 1e-3f
#define ATOLc 1e-6f

#define SROWB 144            // smem row stride bytes
#define OA_LO  9216          // 64*144
#define OB_HI 18432
#define OB_LO 23040          // +32*144
#define BUFS  27648          // bytes per buffer set
#define SMEM_DYN (2*BUFS)    // 55296

#define A21f 0.161f
#define A31f (-0.008480655492356989f)
#define A32f 0.335480655492357f
#define A41f 2.8971530571054935f
#define A42f (-6.359448489975075f)
#define A43f 4.3622954328695815f
#define A51f 5.325864828439257f
#define A52f (-11.748883564062828f)
#define A53f 7.4955393428898365f
#define A54f (-0.09249506636175525f)
#define A61f 5.86145544294642f
#define A62f (-12.92096931784711f)
#define A63f 8.159367898576159f
#define A64f (-0.071584973281401f)
#define A65f (-0.028269050394068383f)
#define Bc1 0.09646076681806523f
#define Bc2 0.01f
#define Bc3 0.4798896504144996f
#define Bc4 1.379008574103742f
#define Bc5 (-3.290069515436081f)
#define Bc6 2.324710524099774f
#define Ec1 (-0.00178001105222577714f)
#define Ec2 (-0.0008164344596567469f)
#define Ec3 0.007880878010261995f
#define Ec4 (-0.1447110071732629f)
#define Ec5 0.5823571654525552f
#define Ec6 (-0.45808210592918697f)
#define Ec7 0.015151515151515152f

// ---------------- device state ----------------
__device__ __align__(16) float g_y[NELEM], g_ynew[NELEM], g_k[7][NELEM];
__device__ __align__(16) bf16 g_Xhi[NELEM], g_Xlo[NELEM];
__device__ __align__(16) bf16 g_H1hi[HELEM], g_H1lo[HELEM];
__device__ __align__(16) bf16 g_H2hi[HELEM], g_H2lo[HELEM];
__device__ __align__(16) bf16 g_W0hi[WW*DD], g_W0lo[WW*DD];
__device__ __align__(16) bf16 g_W1hi[WW*WW], g_W1lo[WW*WW];
__device__ __align__(16) bf16 g_W2hi[DD*WW], g_W2lo[DD*WW];
__device__ double g_errpart[NBLK];
__device__ volatile float g_t, g_dt, g_h, g_tns;
__device__ volatile int g_si, g_sic, g_done, g_accept, g_hit, g_wrow;
__device__ unsigned g_arrive;
__device__ volatile unsigned gg_flag[NBLK * 32];

__constant__ float c_coef[6][6] = {
  {A21f,0,0,0,0,0},
  {A31f,A32f,0,0,0,0},
  {A41f,A42f,A43f,0,0,0},
  {A51f,A52f,A53f,A54f,0,0},
  {A61f,A62f,A63f,A64f,A65f,0},
  {Bc1,Bc2,Bc3,Bc4,Bc5,Bc6},
};

// ---------------- helpers ----------------
__device__ __forceinline__ uint32_t smem_u32(const void* p) {
  uint32_t a;
  asm("{ .reg .u64 t; cvta.to.shared.u64 t, %1; cvt.u32.u64 %0, t; }" : "=r"(a) : "l"(p));
  return a;
}
#define LDMX4(r, addr) \
  asm volatile("ldmatrix.sync.aligned.m8n8.x4.shared.b16 {%0,%1,%2,%3}, [%4];" \
    : "=r"((r)[0]), "=r"((r)[1]), "=r"((r)[2]), "=r"((r)[3]) : "r"(addr))
#define LDMX2(r, addr) \
  asm volatile("ldmatrix.sync.aligned.m8n8.x2.shared.b16 {%0,%1}, [%2];" \
    : "=r"((r)[0]), "=r"((r)[1]) : "r"(addr))

__device__ __forceinline__ void mma16816(float* c, const uint32_t* a, const uint32_t* b) {
  asm volatile(
    "mma.sync.aligned.m16n8k16.row.col.f32.bf16.bf16.f32 "
    "{%0,%1,%2,%3}, {%4,%5,%6,%7}, {%8,%9}, {%0,%1,%2,%3};"
    : "+f"(c[0]), "+f"(c[1]), "+f"(c[2]), "+f"(c[3])
    : "r"(a[0]), "r"(a[1]), "r"(a[2]), "r"(a[3]), "r"(b[0]), "r"(b[1]));
}

// ---------------- barriers ----------------
__device__ __forceinline__ void gsync() {
  __syncthreads();
  if (threadIdx.x == 0) {
    __threadfence();
    unsigned t = atomicAdd(&g_arrive, 1u) + 1u;
    unsigned target = ((t + NBLK - 1u) / NBLK) * NBLK;
    while (*(volatile unsigned*)&g_arrive < target) {}
    __threadfence();
  }
  __syncthreads();
}
__device__ __forceinline__ void ggsync(int grp, unsigned ep) {
  __syncthreads();
  if (threadIdx.x == 0) {
    __threadfence();
    gg_flag[blockIdx.x * 32] = ep;
  }
  if (threadIdx.x < GCTA) {
    const volatile unsigned* f = &gg_flag[(grp * GCTA + threadIdx.x) * 32];
    while (*f < ep) {}
  }
  __syncthreads();
}

// -------- MUFU-free softplus (abs err ~2e-6) --------
__device__ __forceinline__ float softplus_f(float x) {
  float t = fabsf(x);
  float s = fminf(t * 1.4426950408889634f, 100.f);
  float n = floorf(s);
  float r = n - s;
  float p = 1.3215487e-6f;
  p = fmaf(p, r, 1.5252734e-5f);
  p = fmaf(p, r, 1.5403530e-4f);
  p = fmaf(p, r, 1.3333558e-3f);
  p = fmaf(p, r, 9.6181291e-3f);
  p = fmaf(p, r, 5.5504109e-2f);
  p = fmaf(p, r, 2.4022651e-1f);
  p = fmaf(p, r, 6.9314718e-1f);
  p = fmaf(p, r, 1.0f);
  float u = p * __uint_as_float((uint32_t)(127 - (int)n) << 23);
  float d = 2.f + u;
  float w = fmaf(-0.1635f, u, 0.4915f);
  w = w * fmaf(-d, w, 2.f);
  w = w * fmaf(-d, w, 2.f);
  float v = u * w;
  float v2 = v * v;
  float g = 0.09090909f;
  g = fmaf(g, v2, 0.11111111f);
  g = fmaf(g, v2, 0.14285714f);
  g = fmaf(g, v2, 0.2f);
  g = fmaf(g, v2, 0.33333333f);
  g = fmaf(g, v2, 1.0f);
  return fmaxf(x, 0.f) + 2.f * v * g;
}

__device__ __forceinline__ void split_pack(float x0, float x1, uint32_t& hv, uint32_t& lv) {
  bf16 h0 = __float2bfloat16(x0), h1 = __float2bfloat16(x1);
  bf16 l0 = __float2bfloat16(x0 - __bfloat162float(h0));
  bf16 l1 = __float2bfloat16(x1 - __bfloat162float(h1));
  hv = (uint32_t)__bfloat16_as_ushort(h0) | ((uint32_t)__bfloat16_as_ushort(h1) << 16);
  lv = (uint32_t)__bfloat16_as_ushort(l0) | ((uint32_t)__bfloat16_as_ushort(l1) << 16);
}

// ---------------- GEMM1/2: C[64,32] = act(A[64,K] @ B[32,K]^T + bias) -> bf16 hi/lo ----------------
template<bool SP>
__device__ __forceinline__ void mma_gemm(
    const bf16* __restrict__ Ahi, const bf16* __restrict__ Alo,
    const bf16* __restrict__ Bhi, const bf16* __restrict__ Blo,
    int ldk, int bm, int bn, int nchunk,
    const float* __restrict__ bias,
    bf16* __restrict__ Chi, bf16* __restrict__ Clo, int ldc,
    char* sm)
{
  const int tid = threadIdx.x;
  const int wid = tid >> 5;
  const int lane = tid & 31;
  const int grp = lane >> 2, tig = lane & 3;
  const int wm = wid >> 1, wn = wid & 1;   // 4 x 2 warps over 64x32

  float acc[2][4] = {};

  // fill index precompute
  int ar[4], as[4]; bool asel[4];
  #pragma unroll
  for (int i = 0; i < 4; ++i) {
    int lin = i * 256 + tid;
    asel[i] = lin >= 512;
    ar[i] = (lin >> 3) & 63;
    as[i] = (lin & 7) << 3;
  }
  int br[2], bs[2]; bool bsel[2];
  #pragma unroll
  for (int i = 0; i < 2; ++i) {
    int lin = i * 256 + tid;
    bsel[i] = lin >= 256;
    br[i] = (lin >> 3) & 31;
    bs[i] = (lin & 7) << 3;
  }
  // STS target pointers (generic space! offsets within buffer set)
  char* pA[4]; char* pB[2];
  #pragma unroll
  for (int i = 0; i < 4; ++i) pA[i] = sm + (asel[i] ? OA_LO : 0) + ar[i] * SROWB + as[i] * 2;
  #pragma unroll
  for (int i = 0; i < 2; ++i) pB[i] = sm + (bsel[i] ? OB_LO : OB_HI) + br[i] * SROWB + bs[i] * 2;
  // ldmatrix base addresses (shared space u32; add BUFS for buffer 1)
  const uint32_t smb = smem_u32(sm);
  const uint32_t laA_hi = smb + (wm * 16 + (lane & 15)) * SROWB + ((lane >> 4) << 4);
  const uint32_t laA_lo = laA_hi + OA_LO;
  const uint32_t laB_hi = smb + OB_HI + (wn * 16 + (lane & 7)) * SROWB + (((lane >> 3) & 1) << 4);
  const uint32_t laB_lo = laB_hi + (OB_LO - OB_HI);

  uint4 pa[4], pb[2];
  // prologue: chunk 0 -> regs -> buf0; chunk 1 -> regs
  #pragma unroll
  for (int i = 0; i < 4; ++i) {
    const bf16* A = asel[i] ? Alo : Ahi;
    pa[i] = __ldcg((const uint4*)(A + (bm + ar[i]) * ldk + as[i]));
  }
  #pragma unroll
  for (int i = 0; i < 2; ++i) {
    const bf16* B = bsel[i] ? Blo : Bhi;
    pb[i] = __ldg((const uint4*)(B + (bn + br[i]) * ldk + bs[i]));
  }
  #pragma unroll
  for (int i = 0; i < 4; ++i) *(uint4*)(pA[i]) = pa[i];
  #pragma unroll
  for (int i = 0; i < 2; ++i) *(uint4*)(pB[i]) = pb[i];
  if (nchunk > 1) {
    #pragma unroll
    for (int i = 0; i < 4; ++i) {
      const bf16* A = asel[i] ? Alo : Ahi;
      pa[i] = __ldcg((const uint4*)(A + (bm + ar[i]) * ldk + 64 + as[i]));
    }
    #pragma unroll
    for (int i = 0; i < 2; ++i) {
      const bf16* B = bsel[i] ? Blo : Bhi;
      pb[i] = __ldg((const uint4*)(B + (bn + br[i]) * ldk + 64 + bs[i]));
    }
  }
  __syncthreads();

  for (int c = 0; c < nchunk; ++c) {
    const uint32_t bo = (c & 1) ? BUFS : 0;
    // MMA from buf[c&1]
    #pragma unroll
    for (int ks = 0; ks < 4; ++ks) {
      uint32_t ah[4], al[4];
      LDMX4(ah, laA_hi + bo + ks * 32);
      LDMX4(al, laA_lo + bo + ks * 32);
      #pragma unroll
      for (int ni = 0; ni < 2; ++ni) {
        uint32_t bh[2], bl[2];
        LDMX2(bh, laB_hi + bo + ni * (8 * SROWB) + ks * 32);
        LDMX2(bl, laB_lo + bo + ni * (8 * SROWB) + ks * 32);
        mma16816(acc[ni], ah, bh);
        mma16816(acc[ni], ah, bl);
        mma16816(acc[ni], al, bh);
      }
    }
    // STS chunk c+1 into other buffer, then prefetch chunk c+2
    if (c + 1 < nchunk) {
      const uint32_t bo2 = ((c + 1) & 1) ? BUFS : 0;
      #pragma unroll
      for (int i = 0; i < 4; ++i) *(uint4*)(pA[i] + bo2) = pa[i];
      #pragma unroll
      for (int i = 0; i < 2; ++i) *(uint4*)(pB[i] + bo2) = pb[i];
      if (c + 2 < nchunk) {
        int k0 = (c + 2) * 64;
        #pragma unroll
        for (int i = 0; i < 4; ++i) {
          const bf16* A = asel[i] ? Alo : Ahi;
          pa[i] = __ldcg((const uint4*)(A + (bm + ar[i]) * ldk + k0 + as[i]));
        }
        #pragma unroll
        for (int i = 0; i < 2; ++i) {
          const bf16* B = bsel[i] ? Blo : Bhi;
          pb[i] = __ldg((const uint4*)(B + (bn + br[i]) * ldk + k0 + bs[i]));
        }
      }
    }
    __syncthreads();
  }

  #pragma unroll
  for (int ni = 0; ni < 2; ++ni) {
    int m0 = bm + wm * 16 + grp;
    int n  = bn + wn * 16 + ni * 8 + tig * 2;
    float bv0 = __ldg(bias + n), bv1 = __ldg(bias + n + 1);
    float x0 = acc[ni][0] + bv0, x1 = acc[ni][1] + bv1;
    float x2 = acc[ni][2] + bv0, x3 = acc[ni][3] + bv1;
    if (SP) { x0 = softplus_f(x0); x1 = softplus_f(x1); x2 = softplus_f(x2); x3 = softplus_f(x3); }
    uint32_t hv, lv;
    split_pack(x0, x1, hv, lv);
    __stcg((uint32_t*)(Chi + m0 * ldc + n), hv);
    __stcg((uint32_t*)(Clo + m0 * ldc + n), lv);
    split_pack(x2, x3, hv, lv);
    __stcg((uint32_t*)(Chi + (m0 + 8) * ldc + n), hv);
    __stcg((uint32_t*)(Clo + (m0 + 8) * ldc + n), lv);
  }
}

// ---------------- GEMM3 (stage S): k_S[64,8] tile, K=512, fused RK epilogue ----------------
template<int S>
__device__ __forceinline__ void gemm3_stage(
    char* sm, float* sred,
    int bm, int bn, const float* __restrict__ b2, double* sd)
{
  const int tid = threadIdx.x;
  const int wid = tid >> 5, lane = tid & 31;
  const int wm = wid & 3, wk = wid >> 2;       // 4 m-warps x 2 k-halves
  const int grp = lane >> 2, tig = lane & 3;

  float acc[4] = {};

  int ar[4], as[4]; bool asel[4];
  #pragma unroll
  for (int i = 0; i < 4; ++i) {
    int lin = i * 256 + tid;
    asel[i] = lin >= 512;
    ar[i] = (lin >> 3) & 63;
    as[i] = (lin & 7) << 3;
  }
  const bool bon = tid < 128;
  const bool bsel = tid >= 64;
  const int brow = (tid >> 3) & 7;
  const int bseg = (tid & 7) << 3;

  char* pA[4];
  #pragma unroll
  for (int i = 0; i < 4; ++i) pA[i] = sm + (asel[i] ? OA_LO : 0) + ar[i] * SROWB + as[i] * 2;
  char* pB = sm + (bsel ? OB_LO : OB_HI) + brow * SROWB + bseg * 2;

  const uint32_t smb = smem_u32(sm);
  const uint32_t laA_hi = smb + (wm * 16 + (lane & 15)) * SROWB + ((lane >> 4) << 4);
  const uint32_t laA_lo = laA_hi + OA_LO;
  const uint32_t laB_hi = smb + OB_HI + (lane & 7) * SROWB + (((lane >> 3) & 1) << 4);
  const uint32_t laB_lo = laB_hi + (OB_LO - OB_HI);

  uint4 pa[4], pb;
  #pragma unroll
  for (int i = 0; i < 4; ++i) {
    const bf16* A = asel[i] ? g_H2lo : g_H2hi;
    pa[i] = __ldcg((const uint4*)(A + (bm + ar[i]) * WW + as[i]));
  }
  if (bon) {
    const bf16* B = bsel ? g_W2lo : g_W2hi;
    pb = __ldg((const uint4*)(B + (bn + brow) * WW + bseg));
  }
  #pragma unroll
  for (int i = 0; i < 4; ++i) *(uint4*)(pA[i]) = pa[i];
  if (bon) *(uint4*)(pB) = pb;
  {
    #pragma unroll
    for (int i = 0; i < 4; ++i) {
      const bf16* A = asel[i] ? g_H2lo : g_H2hi;
      pa[i] = __ldcg((const uint4*)(A + (bm + ar[i]) * WW + 64 + as[i]));
    }
    if (bon) {
      const bf16* B = bsel ? g_W2lo : g_W2hi;
      pb = __ldg((const uint4*)(B + (bn + brow) * WW + 64 + bseg));
    }
  }
  __syncthreads();

  for (int c = 0; c < 8; ++c) {
    const uint32_t bo = (c & 1) ? BUFS : 0;
    #pragma unroll
    for (int ks2 = 0; ks2 < 2; ++ks2) {
      const int ks = wk * 2 + ks2;
      uint32_t ah[4], al[4], bh[2], bl[2];
      LDMX4(ah, laA_hi + bo + ks * 32);
      LDMX4(al, laA_lo + bo + ks * 32);
      LDMX2(bh, laB_hi + bo + ks * 32);
      LDMX2(bl, laB_lo + bo + ks * 32);
      mma16816(acc, ah, bh);
      mma16816(acc, ah, bl);
      mma16816(acc, al, bh);
    }
    if (c + 1 < 8) {
      const uint32_t bo2 = ((c + 1) & 1) ? BUFS : 0;
      #pragma unroll
      for (int i = 0; i < 4; ++i) *(uint4*)(pA[i] + bo2) = pa[i];
      if (bon) *(uint4*)(pB + bo2) = pb;
      if (c + 2 < 8) {
        int k0 = (c + 2) * 64;
        #pragma unroll
        for (int i = 0; i < 4; ++i) {
          const bf16* A = asel[i] ? g_H2lo : g_H2hi;
          pa[i] = __ldcg((const uint4*)(A + (bm + ar[i]) * WW + k0 + as[i]));
        }
        if (bon) {
          const bf16* B = bsel ? g_W2lo : g_W2hi;
          pb = __ldg((const uint4*)(B + (bn + brow) * WW + k0 + bseg));
        }
      }
    }
    __syncthreads();
  }

  // reduce across the two k-half warp sets
  const int ml = wm * 16 + grp;
  const int nl = tig * 2;
  if (wk == 1) {
    sred[ml * 8 + nl]           = acc[0];
    sred[ml * 8 + nl + 1]       = acc[1];
    sred[(ml + 8) * 8 + nl]     = acc[2];
    sred[(ml + 8) * 8 + nl + 1] = acc[3];
  }
  __syncthreads();
  double ss = 0.0;
  if (wk == 0) {
    acc[0] += sred[ml * 8 + nl];
    acc[1] += sred[ml * 8 + nl + 1];
    acc[2] += sred[(ml + 8) * 8 + nl];
    acc[3] += sred[(ml + 8) * 8 + nl + 1];

    const int n0 = bn + nl;
    const int m0 = bm + ml;
    const float h = g_h;
    const int i0 = m0 * DD + n0;
    const int i1 = (m0 + 8) * DD + n0;
    float bv0 = __ldg(b2 + n0), bv1 = __ldg(b2 + n0 + 1);
    float2 v0 = {acc[0] + bv0, acc[1] + bv1};
    float2 v1 = {acc[2] + bv0, acc[3] + bv1};
    __stcg((float2*)(g_k[S] + i0), v0);
    __stcg((float2*)(g_k[S] + i1), v1);

    const int idxs[2] = {i0, i1};
    const float2 vs[2] = {v0, v1};
    if constexpr (S <= 5) {
      #pragma unroll
      for (int r = 0; r < 2; ++r) {
        int ix = idxs[r];
        float2 y2 = __ldcg((const float2*)(g_y + ix));
        float cS = c_coef[S][S];
        float ax = cS * vs[r].x, ay = cS * vs[r].y;
        #pragma unroll
        for (int j = 0; j < S; ++j) {
          float cj = c_coef[S][j];
          float2 kj = __ldcg((const float2*)(g_k[j] + ix));
          ax = fmaf(cj, kj.x, ax);
          ay = fmaf(cj, kj.y, ay);
        }
        float Xx = fmaf(h, ax, y2.x);
        float Xy = fmaf(h, ay, y2.y);
        if constexpr (S == 5) {
          float2 yn = {Xx, Xy};
          __stcg((float2*)(g_ynew + ix), yn);
        }
        uint32_t hv, lv;
        split_pack(Xx, Xy, hv, lv);
        __stcg((uint32_t*)(g_Xhi + ix), hv);
        __stcg((uint32_t*)(g_Xlo + ix), lv);
      }
    } else {
      #pragma unroll
      for (int r = 0; r < 2; ++r) {
        int ix = idxs[r];
        float2 k0 = __ldcg((const float2*)(g_k[0] + ix));
        float2 k1 = __ldcg((const float2*)(g_k[1] + ix));
        float2 k2 = __ldcg((const float2*)(g_k[2] + ix));
        float2 k3 = __ldcg((const float2*)(g_k[3] + ix));
        float2 k4 = __ldcg((const float2*)(g_k[4] + ix));
        float2 k5 = __ldcg((const float2*)(g_k[5] + ix));
        float2 y2 = __ldcg((const float2*)(g_y + ix));
        float2 yn = __ldcg((const float2*)(g_ynew + ix));
        #pragma unroll
        for (int cc = 0; cc < 2; ++cc) {
          float e = Ec1 * (cc ? k0.y : k0.x);
          e = fmaf(Ec2, cc ? k1.y : k1.x, e);
          e = fmaf(Ec3, cc ? k2.y : k2.x, e);
          e = fmaf(Ec4, cc ? k3.y : k3.x, e);
          e = fmaf(Ec5, cc ? k4.y : k4.x, e);
          e = fmaf(Ec6, cc ? k5.y : k5.x, e);
          e = fmaf(Ec7, cc ? vs[r].y : vs[r].x, e);
          float err = h * e;
          float yv = cc ? y2.y : y2.x, ynv = cc ? yn.y : yn.x;
          float scale = ATOLc + RTOLc * fmaxf(fabsf(yv), fabsf(ynv));
          float rr = err / scale;
          ss += (double)rr * (double)rr;
        }
      }
    }
  }
  if constexpr (S == 6) {
    sd[tid] = ss;
    __syncthreads();
    #pragma unroll
    for (int s2 = 128; s2 > 0; s2 >>= 1) {
      if (tid < s2) sd[tid] += sd[tid + s2];
      __syncthreads();
    }
    if (tid == 0) ((volatile double*)g_errpart)[blockIdx.x] = sd[0];
  }
}

// ---------------- one RK stage (group-local syncs) ----------------
template<int S>
__device__ __forceinline__ void do_stage(int grp_id, int lbid, unsigned& ep,
    const float* b0, const float* b1, const float* b2,
    char* sm, float* sred, double* sd)
{
  const int bm = grp_id << 6;
  const int bn = lbid << 5;
  mma_gemm<true>(g_Xhi, g_Xlo, g_W0hi, g_W0lo, DD, bm, bn, 2, b0, g_H1hi, g_H1lo, WW, sm);
  ggsync(grp_id, ep++);
  mma_gemm<true>(g_H1hi, g_H1lo, g_W1hi, g_W1lo, WW, bm, bn, 8, b1, g_H2hi, g_H2lo, WW, sm);
  ggsync(grp_id, ep++);
  gemm3_stage<S>(sm, sred, bm, lbid << 3, b2, sd);
  if (S < 6) ggsync(grp_id, ep++);
}

__device__ __forceinline__ void update_phase(int gid2, float* __restrict__ out) {
  float2 v;
  if (g_accept) {
    v = __ldcg((const float2*)(g_ynew + gid2));
    __stcg((float2*)(g_y + gid2), v);
    if (g_hit) *(float2*)(out + g_wrow * NELEM + gid2) = v;
  } else {
    v = __ldcg((const float2*)(g_y + gid2));
  }
  uint32_t hv, lv;
  split_pack(v.x, v.y, hv, lv);
  __stcg((uint32_t*)(g_Xhi + gid2), hv);
  __stcg((uint32_t*)(g_Xlo + gid2), lv);
}

// ---------------- persistent solver ----------------
__global__ void __launch_bounds__(NTHR, 2) solve_kernel(
    const float* __restrict__ ts,
    const float* __restrict__ b0, const float* __restrict__ b1,
    const float* __restrict__ b2, float* __restrict__ out)
{
  extern __shared__ __align__(16) char sm[];
  __shared__ float sred[64 * 8];
  __shared__ double sd[NTHR];

  const int bid = blockIdx.x;
  const int tid = threadIdx.x;
  const int grp_id = bid >> 4;
  const int lbid = bid & 15;
  const int gid2 = (bid * NTHR + tid) * 2;
  unsigned ep = 1;

  for (int step = 0; step < MAX_STEPS; ++step) {
    update_phase(gid2, out);
    ggsync(grp_id, ep++);

    do_stage<0>(grp_id, lbid, ep, b0, b1, b2, sm, sred, sd);
    do_stage<1>(grp_id, lbid, ep, b0, b1, b2, sm, sred, sd);
    do_stage<2>(grp_id, lbid, ep, b0, b1, b2, sm, sred, sd);
    do_stage<3>(grp_id, lbid, ep, b0, b1, b2, sm, sred, sd);
    do_stage<4>(grp_id, lbid, ep, b0, b1, b2, sm, sred, sd);
    do_stage<5>(grp_id, lbid, ep, b0, b1, b2, sm, sred, sd);
    do_stage<6>(grp_id, lbid, ep, b0, b1, b2, sm, sred, sd);

    gsync();

    if (bid == 0) {
      double v = ((volatile double*)g_errpart)[tid];
      sd[tid] = v;
      __syncthreads();
      #pragma unroll
      for (int s2 = 128; s2 > 0; s2 >>= 1) {
        if (tid < s2) sd[tid] += sd[tid + s2];
        __syncthreads();
      }
      if (tid == 0) {
        float enorm = sqrtf((float)(sd[0] / (double)NELEM));
        int done = g_done;
        float h = g_h;
        int accept = (enorm <= 1.0f) && !done;
        float t_new = g_t + h;
        int hit = accept && (t_new >= g_tns - 1e-6f);
        if (accept) g_t = t_new;
        g_accept = accept;
        g_hit = hit;
        g_wrow = g_sic;
        int si = g_si + hit;
        g_si = si;
        float factor;
        if (enorm > 0.f) {
          factor = 0.9f * powf(enorm, -0.2f);
          factor = fminf(fmaxf(factor, 0.2f), 10.f);
        } else factor = 10.f;
        if (!done) g_dt = g_dt * factor;
        int done2 = (si >= TT) ? 1 : 0;
        int sic2 = si < (TT - 1) ? si : (TT - 1);
        float tns2 = __ldg(ts + sic2);
        float h2 = done2 ? 0.f : fmaxf(fminf(g_dt, tns2 - g_t), 0.f);
        g_done = done2; g_sic = sic2; g_tns = tns2; g_h = h2;
      }
    }
    gsync();
  }
  update_phase(gid2, out);
}

// ---------------- init ----------------
__global__ void init_kernel(const float* __restrict__ ts, const float* __restrict__ y0,
                            const float* __restrict__ W0, const float* __restrict__ W1,
                            const float* __restrict__ W2, float* __restrict__ out)
{
  int idx = blockIdx.x * NTHR + threadIdx.x;
  if (idx < TT * NELEM) out[idx] = (idx < NELEM) ? y0[idx] : 0.f;
  if (idx < NELEM) {
    float v = y0[idx];
    g_y[idx] = v;
    bf16 h = __float2bfloat16(v);
    g_Xhi[idx] = h;
    g_Xlo[idx] = __float2bfloat16(v - __bfloat162float(h));
  }
  if (idx < WW * DD) {
    float w = W0[idx];
    bf16 h = __float2bfloat16(w);
    g_W0hi[idx] = h; g_W0lo[idx] = __float2bfloat16(w - __bfloat162float(h));
    float w2 = W2[idx];
    bf16 h2 = __float2bfloat16(w2);
    g_W2hi[idx] = h2; g_W2lo[idx] = __float2bfloat16(w2 - __bfloat162float(h2));
  }
  if (idx < WW * WW) {
    float w = W1[idx];
    bf16 h = __float2bfloat16(w);
    g_W1hi[idx] = h; g_W1lo[idx] = __float2bfloat16(w - __bfloat162float(h));
  }
  if (idx < NBLK * 32) gg_flag[idx] = 0u;
  if (idx < NBLK) g_errpart[idx] = 0.0;
  if (idx == 0) {
    float t0 = ts[0];
    float dt0 = ts[1] - ts[0];
    g_t = t0;
    g_dt = dt0;
    g_si = 1;
    g_accept = 0;
    g_hit = 0;
    g_wrow = 0;
    g_arrive = 0u;
    g_done = 0;
    g_sic = 1;
    float tns = ts[1];
    g_tns = tns;
    g_h = fmaxf(fminf(dt0, tns - t0), 0.f);
  }
}

extern "C" void kernel_launch(void* const* d_in, const int* in_sizes, int n_in,
                              void* d_out, int out_size) {
  const float* ts = (const float*)d_in[0];
  const float* y0 = (const float*)d_in[1];
  const float* W0 = (const float*)d_in[2];
  const float* b0 = (const float*)d_in[3];
  const float* W1 = (const float*)d_in[4];
  const float* b1 = (const float*)d_in[5];
  const float* W2 = (const float*)d_in[6];
  const float* b2 = (const float*)d_in[7];
  float* out = (float*)d_out;

  cudaFuncSetAttribute(solve_kernel, cudaFuncAttributeMaxDynamicSharedMemorySize, SMEM_DYN);

  init_kernel<<<(TT * NELEM) / NTHR, NTHR>>>(ts, y0, W0, W1, W2, out);
  solve_kernel<<<NBLK, NTHR, SMEM_DYN>>>(ts, b0, b1, b2, out);
}

// round 12
// speedup vs baseline: 1.7358x; 1.0777x over previous
#include <cuda_runtime.h>
#include <cuda_bf16.h>
#include <math.h>
#include <stdint.h>

typedef __nv_bfloat16 bf16;

#define BB 1024
#define DD 128
#define WW 512
#define TT 8
#define NELEM (BB*DD)
#define HELEM (BB*WW)
#define MAX_STEPS 48
#define NBLK 256
#define NTHR 256
#define GCTA 16
#define RTOLc 1e-3f
#define ATOLc 1e-6f

#define SROWB 144            // smem row stride bytes
#define OA_LO  9216          // 64*144
#define OB_HI 18432
#define OB_LO 23040          // +32*144
#define BUFS  27648          // bytes per buffer set
#define NSTG 3
#define SMEM_DYN (NSTG*BUFS) // 82944

#define A21f 0.161f
#define A31f (-0.008480655492356989f)
#define A32f 0.335480655492357f
#define A41f 2.8971530571054935f
#define A42f (-6.359448489975075f)
#define A43f 4.3622954328695815f
#define A51f 5.325864828439257f
#define A52f (-11.748883564062828f)
#define A53f 7.4955393428898365f
#define A54f (-0.09249506636175525f)
#define A61f 5.86145544294642f
#define A62f (-12.92096931784711f)
#define A63f 8.159367898576159f
#define A64f (-0.071584973281401f)
#define A65f (-0.028269050394068383f)
#define Bc1 0.09646076681806523f
#define Bc2 0.01f
#define Bc3 0.4798896504144996f
#define Bc4 1.379008574103742f
#define Bc5 (-3.290069515436081f)
#define Bc6 2.324710524099774f
#define Ec1 (-0.00178001105222577714f)
#define Ec2 (-0.0008164344596567469f)
#define Ec3 0.007880878010261995f
#define Ec4 (-0.1447110071732629f)
#define Ec5 0.5823571654525552f
#define Ec6 (-0.45808210592918697f)
#define Ec7 0.015151515151515152f

// ---------------- device state ----------------
__device__ __align__(16) float g_y[NELEM], g_ynew[NELEM], g_k[7][NELEM];
__device__ __align__(16) bf16 g_Xhi[NELEM], g_Xlo[NELEM];
__device__ __align__(16) bf16 g_H1hi[HELEM], g_H1lo[HELEM];
__device__ __align__(16) bf16 g_H2hi[HELEM], g_H2lo[HELEM];
__device__ __align__(16) bf16 g_W0hi[WW*DD], g_W0lo[WW*DD];
__device__ __align__(16) bf16 g_W1hi[WW*WW], g_W1lo[WW*WW];
__device__ __align__(16) bf16 g_W2hi[DD*WW], g_W2lo[DD*WW];
__device__ double g_errpart[NBLK];
__device__ volatile float g_t, g_dt, g_h, g_tns;
__device__ volatile int g_si, g_sic, g_done, g_accept, g_hit, g_wrow;
__device__ unsigned g_arrive;
__device__ volatile unsigned gg_flag[NBLK * 32];

__constant__ float c_coef[6][6] = {
  {A21f,0,0,0,0,0},
  {A31f,A32f,0,0,0,0},
  {A41f,A42f,A43f,0,0,0},
  {A51f,A52f,A53f,A54f,0,0},
  {A61f,A62f,A63f,A64f,A65f,0},
  {Bc1,Bc2,Bc3,Bc4,Bc5,Bc6},
};

// ---------------- helpers ----------------
__device__ __forceinline__ uint32_t smem_u32(const void* p) {
  uint32_t a;
  asm("{ .reg .u64 t; cvta.to.shared.u64 t, %1; cvt.u32.u64 %0, t; }" : "=r"(a) : "l"(p));
  return a;
}
__device__ __forceinline__ void cp16(uint32_t dst, const void* src) {
  asm volatile("cp.async.cg.shared.global [%0], [%1], 16;" :: "r"(dst), "l"(src) : "memory");
}
__device__ __forceinline__ void cp_commit() { asm volatile("cp.async.commit_group;" ::: "memory"); }
__device__ __forceinline__ void cp_wait1() { asm volatile("cp.async.wait_group 1;" ::: "memory"); }

#define LDMX4(r, addr) \
  asm volatile("ldmatrix.sync.aligned.m8n8.x4.shared.b16 {%0,%1,%2,%3}, [%4];" \
    : "=r"((r)[0]), "=r"((r)[1]), "=r"((r)[2]), "=r"((r)[3]) : "r"(addr))
#define LDMX2(r, addr) \
  asm volatile("ldmatrix.sync.aligned.m8n8.x2.shared.b16 {%0,%1}, [%2];" \
    : "=r"((r)[0]), "=r"((r)[1]) : "r"(addr))

__device__ __forceinline__ void mma16816(float* c, const uint32_t* a, const uint32_t* b) {
  asm volatile(
    "mma.sync.aligned.m16n8k16.row.col.f32.bf16.bf16.f32 "
    "{%0,%1,%2,%3}, {%4,%5,%6,%7}, {%8,%9}, {%0,%1,%2,%3};"
    : "+f"(c[0]), "+f"(c[1]), "+f"(c[2]), "+f"(c[3])
    : "r"(a[0]), "r"(a[1]), "r"(a[2]), "r"(a[3]), "r"(b[0]), "r"(b[1]));
}

// ---------------- barriers ----------------
__device__ __forceinline__ void gsync() {
  __syncthreads();
  if (threadIdx.x == 0) {
    __threadfence();
    unsigned t = atomicAdd(&g_arrive, 1u) + 1u;
    unsigned target = ((t + NBLK - 1u) / NBLK) * NBLK;
    while (*(volatile unsigned*)&g_arrive < target) {}
    __threadfence();
  }
  __syncthreads();
}
__device__ __forceinline__ void ggsync(int grp, unsigned ep) {
  __syncthreads();
  if (threadIdx.x == 0) {
    __threadfence();
    gg_flag[blockIdx.x * 32] = ep;
  }
  if (threadIdx.x < GCTA) {
    const volatile unsigned* f = &gg_flag[(grp * GCTA + threadIdx.x) * 32];
    while (*f < ep) {}
  }
  __syncthreads();
}

// -------- MUFU-free softplus (abs err ~2e-6) --------
__device__ __forceinline__ float softplus_f(float x) {
  float t = fabsf(x);
  float s = fminf(t * 1.4426950408889634f, 100.f);
  float n = floorf(s);
  float r = n - s;
  float p = 1.3215487e-6f;
  p = fmaf(p, r, 1.5252734e-5f);
  p = fmaf(p, r, 1.5403530e-4f);
  p = fmaf(p, r, 1.3333558e-3f);
  p = fmaf(p, r, 9.6181291e-3f);
  p = fmaf(p, r, 5.5504109e-2f);
  p = fmaf(p, r, 2.4022651e-1f);
  p = fmaf(p, r, 6.9314718e-1f);
  p = fmaf(p, r, 1.0f);
  float u = p * __uint_as_float((uint32_t)(127 - (int)n) << 23);
  float d = 2.f + u;
  float w = fmaf(-0.1635f, u, 0.4915f);
  w = w * fmaf(-d, w, 2.f);
  w = w * fmaf(-d, w, 2.f);
  float v = u * w;
  float v2 = v * v;
  float g = 0.09090909f;
  g = fmaf(g, v2, 0.11111111f);
  g = fmaf(g, v2, 0.14285714f);
  g = fmaf(g, v2, 0.2f);
  g = fmaf(g, v2, 0.33333333f);
  g = fmaf(g, v2, 1.0f);
  return fmaxf(x, 0.f) + 2.f * v * g;
}

__device__ __forceinline__ void split_pack(float x0, float x1, uint32_t& hv, uint32_t& lv) {
  bf16 h0 = __float2bfloat16(x0), h1 = __float2bfloat16(x1);
  bf16 l0 = __float2bfloat16(x0 - __bfloat162float(h0));
  bf16 l1 = __float2bfloat16(x1 - __bfloat162float(h1));
  hv = (uint32_t)__bfloat16_as_ushort(h0) | ((uint32_t)__bfloat16_as_ushort(h1) << 16);
  lv = (uint32_t)__bfloat16_as_ushort(l0) | ((uint32_t)__bfloat16_as_ushort(l1) << 16);
}

// ---------------- GEMM1/2: C[64,32] = act(A[64,K] @ B[32,K]^T + bias) -> bf16 hi/lo ----------------
// 3 independent accumulator chains (hi*hi, hi*lo, lo*hi), cp.async 3-stage ring.
template<bool SP>
__device__ __forceinline__ void mma_gemm(
    const bf16* __restrict__ Ahi, const bf16* __restrict__ Alo,
    const bf16* __restrict__ Bhi, const bf16* __restrict__ Blo,
    int ldk, int bm, int bn, int nchunk,
    const float* __restrict__ bias,
    bf16* __restrict__ Chi, bf16* __restrict__ Clo, int ldc,
    char* sm)
{
  const int tid = threadIdx.x;
  const int wid = tid >> 5;
  const int lane = tid & 31;
  const int grp = lane >> 2, tig = lane & 3;
  const int wm = wid >> 1, wn = wid & 1;   // 4 x 2 warps over 64x32

  float hh[2][4] = {}, hl[2][4] = {}, lh[2][4] = {};

  // fill index precompute
  int ar[4], as[4]; bool asel[4];
  #pragma unroll
  for (int i = 0; i < 4; ++i) {
    int lin = i * 256 + tid;
    asel[i] = lin >= 512;
    ar[i] = (lin >> 3) & 63;
    as[i] = (lin & 7) << 3;
  }
  int br[2], bs[2]; bool bsel[2];
  #pragma unroll
  for (int i = 0; i < 2; ++i) {
    int lin = i * 256 + tid;
    bsel[i] = lin >= 256;
    br[i] = (lin >> 3) & 31;
    bs[i] = (lin & 7) << 3;
  }
  const uint32_t smb = smem_u32(sm);
  uint32_t stA[4], stB[2];
  #pragma unroll
  for (int i = 0; i < 4; ++i) stA[i] = smb + (asel[i] ? OA_LO : 0) + ar[i] * SROWB + as[i] * 2;
  #pragma unroll
  for (int i = 0; i < 2; ++i) stB[i] = smb + (bsel[i] ? OB_LO : OB_HI) + br[i] * SROWB + bs[i] * 2;
  const bf16* gA[4]; const bf16* gB[2];
  #pragma unroll
  for (int i = 0; i < 4; ++i) gA[i] = (asel[i] ? Alo : Ahi) + (bm + ar[i]) * ldk + as[i];
  #pragma unroll
  for (int i = 0; i < 2; ++i) gB[i] = (bsel[i] ? Blo : Bhi) + (bn + br[i]) * ldk + bs[i];

  const uint32_t laA_hi = smb + (wm * 16 + (lane & 15)) * SROWB + ((lane >> 4) << 4);
  const uint32_t laA_lo = laA_hi + OA_LO;
  const uint32_t laB_hi = smb + OB_HI + (wn * 16 + (lane & 7)) * SROWB + (((lane >> 3) & 1) << 4);
  const uint32_t laB_lo = laB_hi + (OB_LO - OB_HI);

  // prologue: fill chunk0 -> stage0, chunk1 -> stage1
  #pragma unroll
  for (int i = 0; i < 4; ++i) cp16(stA[i], gA[i]);
  #pragma unroll
  for (int i = 0; i < 2; ++i) cp16(stB[i], gB[i]);
  cp_commit();
  if (nchunk > 1) {
    #pragma unroll
    for (int i = 0; i < 4; ++i) cp16(stA[i] + BUFS, gA[i] + 64);
    #pragma unroll
    for (int i = 0; i < 2; ++i) cp16(stB[i] + BUFS, gB[i] + 64);
  }
  cp_commit();

  for (int c = 0; c < nchunk; ++c) {
    cp_wait1();
    __syncthreads();
    const uint32_t bo = (uint32_t)(c % NSTG) * BUFS;
    #pragma unroll
    for (int ks = 0; ks < 4; ++ks) {
      uint32_t ah[4], al[4];
      LDMX4(ah, laA_hi + bo + ks * 32);
      LDMX4(al, laA_lo + bo + ks * 32);
      #pragma unroll
      for (int ni = 0; ni < 2; ++ni) {
        uint32_t bh[2], bl[2];
        LDMX2(bh, laB_hi + bo + ni * (8 * SROWB) + ks * 32);
        LDMX2(bl, laB_lo + bo + ni * (8 * SROWB) + ks * 32);
        mma16816(hh[ni], ah, bh);
        mma16816(hl[ni], ah, bl);
        mma16816(lh[ni], al, bh);
      }
    }
    if (c + 2 < nchunk) {
      const uint32_t bo2 = (uint32_t)((c + 2) % NSTG) * BUFS;
      int k0 = (c + 2) * 64;
      #pragma unroll
      for (int i = 0; i < 4; ++i) cp16(stA[i] + bo2, gA[i] + k0);
      #pragma unroll
      for (int i = 0; i < 2; ++i) cp16(stB[i] + bo2, gB[i] + k0);
    }
    cp_commit();
  }

  #pragma unroll
  for (int ni = 0; ni < 2; ++ni) {
    int m0 = bm + wm * 16 + grp;
    int n  = bn + wn * 16 + ni * 8 + tig * 2;
    float bv0 = __ldg(bias + n), bv1 = __ldg(bias + n + 1);
    float x0 = hh[ni][0] + hl[ni][0] + lh[ni][0] + bv0;
    float x1 = hh[ni][1] + hl[ni][1] + lh[ni][1] + bv1;
    float x2 = hh[ni][2] + hl[ni][2] + lh[ni][2] + bv0;
    float x3 = hh[ni][3] + hl[ni][3] + lh[ni][3] + bv1;
    if (SP) { x0 = softplus_f(x0); x1 = softplus_f(x1); x2 = softplus_f(x2); x3 = softplus_f(x3); }
    uint32_t hv, lv;
    split_pack(x0, x1, hv, lv);
    __stcg((uint32_t*)(Chi + m0 * ldc + n), hv);
    __stcg((uint32_t*)(Clo + m0 * ldc + n), lv);
    split_pack(x2, x3, hv, lv);
    __stcg((uint32_t*)(Chi + (m0 + 8) * ldc + n), hv);
    __stcg((uint32_t*)(Clo + (m0 + 8) * ldc + n), lv);
  }
}

// ---------------- GEMM3 (stage S): k_S[64,8] tile, K=512, fused RK epilogue ----------------
template<int S>
__device__ __forceinline__ void gemm3_stage(
    char* sm, float* sred,
    int bm, int bn, const float* __restrict__ b2, double* sd)
{
  const int tid = threadIdx.x;
  const int wid = tid >> 5, lane = tid & 31;
  const int wm = wid & 3, wk = wid >> 2;       // 4 m-warps x 2 k-halves
  const int grp = lane >> 2, tig = lane & 3;

  float hh[4] = {}, hl[4] = {}, lh[4] = {};

  int ar[4], as[4]; bool asel[4];
  #pragma unroll
  for (int i = 0; i < 4; ++i) {
    int lin = i * 256 + tid;
    asel[i] = lin >= 512;
    ar[i] = (lin >> 3) & 63;
    as[i] = (lin & 7) << 3;
  }
  const bool bon = tid < 128;
  const bool bsel = tid >= 64;
  const int brow = (tid >> 3) & 7;
  const int bseg = (tid & 7) << 3;

  const uint32_t smb = smem_u32(sm);
  uint32_t stA[4];
  #pragma unroll
  for (int i = 0; i < 4; ++i) stA[i] = smb + (asel[i] ? OA_LO : 0) + ar[i] * SROWB + as[i] * 2;
  const uint32_t stB = smb + (bsel ? OB_LO : OB_HI) + brow * SROWB + bseg * 2;
  const bf16* gA[4];
  #pragma unroll
  for (int i = 0; i < 4; ++i) gA[i] = (asel[i] ? g_H2lo : g_H2hi) + (bm + ar[i]) * WW + as[i];
  const bf16* gB = (bsel ? g_W2lo : g_W2hi) + (bn + brow) * WW + bseg;

  const uint32_t laA_hi = smb + (wm * 16 + (lane & 15)) * SROWB + ((lane >> 4) << 4);
  const uint32_t laA_lo = laA_hi + OA_LO;
  const uint32_t laB_hi = smb + OB_HI + (lane & 7) * SROWB + (((lane >> 3) & 1) << 4);
  const uint32_t laB_lo = laB_hi + (OB_LO - OB_HI);

  #pragma unroll
  for (int i = 0; i < 4; ++i) cp16(stA[i], gA[i]);
  if (bon) cp16(stB, gB);
  cp_commit();
  #pragma unroll
  for (int i = 0; i < 4; ++i) cp16(stA[i] + BUFS, gA[i] + 64);
  if (bon) cp16(stB + BUFS, gB + 64);
  cp_commit();

  for (int c = 0; c < 8; ++c) {
    cp_wait1();
    __syncthreads();
    const uint32_t bo = (uint32_t)(c % NSTG) * BUFS;
    #pragma unroll
    for (int ks2 = 0; ks2 < 2; ++ks2) {
      const int ks = wk * 2 + ks2;
      uint32_t ah[4], al[4], bh[2], bl[2];
      LDMX4(ah, laA_hi + bo + ks * 32);
      LDMX4(al, laA_lo + bo + ks * 32);
      LDMX2(bh, laB_hi + bo + ks * 32);
      LDMX2(bl, laB_lo + bo + ks * 32);
      mma16816(hh, ah, bh);
      mma16816(hl, ah, bl);
      mma16816(lh, al, bh);
    }
    if (c + 2 < 8) {
      const uint32_t bo2 = (uint32_t)((c + 2) % NSTG) * BUFS;
      int k0 = (c + 2) * 64;
      #pragma unroll
      for (int i = 0; i < 4; ++i) cp16(stA[i] + bo2, gA[i] + k0);
      if (bon) cp16(stB + bo2, gB + k0);
    }
    cp_commit();
  }

  float acc[4];
  #pragma unroll
  for (int j = 0; j < 4; ++j) acc[j] = hh[j] + hl[j] + lh[j];

  // reduce across the two k-half warp sets
  const int ml = wm * 16 + grp;
  const int nl = tig * 2;
  if (wk == 1) {
    sred[ml * 8 + nl]           = acc[0];
    sred[ml * 8 + nl + 1]       = acc[1];
    sred[(ml + 8) * 8 + nl]     = acc[2];
    sred[(ml + 8) * 8 + nl + 1] = acc[3];
  }
  __syncthreads();
  double ss = 0.0;
  if (wk == 0) {
    acc[0] += sred[ml * 8 + nl];
    acc[1] += sred[ml * 8 + nl + 1];
    acc[2] += sred[(ml + 8) * 8 + nl];
    acc[3] += sred[(ml + 8) * 8 + nl + 1];

    const int n0 = bn + nl;
    const int m0 = bm + ml;
    const float h = g_h;
    const int i0 = m0 * DD + n0;
    const int i1 = (m0 + 8) * DD + n0;
    float bv0 = __ldg(b2 + n0), bv1 = __ldg(b2 + n0 + 1);
    float2 v0 = {acc[0] + bv0, acc[1] + bv1};
    float2 v1 = {acc[2] + bv0, acc[3] + bv1};
    __stcg((float2*)(g_k[S] + i0), v0);
    __stcg((float2*)(g_k[S] + i1), v1);

    const int idxs[2] = {i0, i1};
    const float2 vs[2] = {v0, v1};
    if constexpr (S <= 5) {
      #pragma unroll
      for (int r = 0; r < 2; ++r) {
        int ix = idxs[r];
        float2 y2 = __ldcg((const float2*)(g_y + ix));
        float cS = c_coef[S][S];
        float ax = cS * vs[r].x, ay = cS * vs[r].y;
        #pragma unroll
        for (int j = 0; j < S; ++j) {
          float cj = c_coef[S][j];
          float2 kj = __ldcg((const float2*)(g_k[j] + ix));
          ax = fmaf(cj, kj.x, ax);
          ay = fmaf(cj, kj.y, ay);
        }
        float Xx = fmaf(h, ax, y2.x);
        float Xy = fmaf(h, ay, y2.y);
        if constexpr (S == 5) {
          float2 yn = {Xx, Xy};
          __stcg((float2*)(g_ynew + ix), yn);
        }
        uint32_t hv, lv;
        split_pack(Xx, Xy, hv, lv);
        __stcg((uint32_t*)(g_Xhi + ix), hv);
        __stcg((uint32_t*)(g_Xlo + ix), lv);
      }
    } else {
      #pragma unroll
      for (int r = 0; r < 2; ++r) {
        int ix = idxs[r];
        float2 k0 = __ldcg((const float2*)(g_k[0] + ix));
        float2 k1 = __ldcg((const float2*)(g_k[1] + ix));
        float2 k2 = __ldcg((const float2*)(g_k[2] + ix));
        float2 k3 = __ldcg((const float2*)(g_k[3] + ix));
        float2 k4 = __ldcg((const float2*)(g_k[4] + ix));
        float2 k5 = __ldcg((const float2*)(g_k[5] + ix));
        float2 y2 = __ldcg((const float2*)(g_y + ix));
        float2 yn = __ldcg((const float2*)(g_ynew + ix));
        #pragma unroll
        for (int cc = 0; cc < 2; ++cc) {
          float e = Ec1 * (cc ? k0.y : k0.x);
          e = fmaf(Ec2, cc ? k1.y : k1.x, e);
          e = fmaf(Ec3, cc ? k2.y : k2.x, e);
          e = fmaf(Ec4, cc ? k3.y : k3.x, e);
          e = fmaf(Ec5, cc ? k4.y : k4.x, e);
          e = fmaf(Ec6, cc ? k5.y : k5.x, e);
          e = fmaf(Ec7, cc ? vs[r].y : vs[r].x, e);
          float err = h * e;
          float yv = cc ? y2.y : y2.x, ynv = cc ? yn.y : yn.x;
          float scale = ATOLc + RTOLc * fmaxf(fabsf(yv), fabsf(ynv));
          float rr = err / scale;
          ss += (double)rr * (double)rr;
        }
      }
    }
  }
  if constexpr (S == 6) {
    sd[tid] = ss;
    __syncthreads();
    #pragma unroll
    for (int s2 = 128; s2 > 0; s2 >>= 1) {
      if (tid < s2) sd[tid] += sd[tid + s2];
      __syncthreads();
    }
    if (tid == 0) ((volatile double*)g_errpart)[blockIdx.x] = sd[0];
  }
}

// ---------------- one RK stage (group-local syncs) ----------------
template<int S>
__device__ __forceinline__ void do_stage(int grp_id, int lbid, unsigned& ep,
    const float* b0, const float* b1, const float* b2,
    char* sm, float* sred, double* sd)
{
  const int bm = grp_id << 6;
  const int bn = lbid << 5;
  mma_gemm<true>(g_Xhi, g_Xlo, g_W0hi, g_W0lo, DD, bm, bn, 2, b0, g_H1hi, g_H1lo, WW, sm);
  ggsync(grp_id, ep++);
  mma_gemm<true>(g_H1hi, g_H1lo, g_W1hi, g_W1lo, WW, bm, bn, 8, b1, g_H2hi, g_H2lo, WW, sm);
  ggsync(grp_id, ep++);
  gemm3_stage<S>(sm, sred, bm, lbid << 3, b2, sd);
  if (S < 6) ggsync(grp_id, ep++);
}

__device__ __forceinline__ void update_phase(int gid2, float* __restrict__ out) {
  float2 v;
  if (g_accept) {
    v = __ldcg((const float2*)(g_ynew + gid2));
    __stcg((float2*)(g_y + gid2), v);
    if (g_hit) *(float2*)(out + g_wrow * NELEM + gid2) = v;
  } else {
    v = __ldcg((const float2*)(g_y + gid2));
  }
  uint32_t hv, lv;
  split_pack(v.x, v.y, hv, lv);
  __stcg((uint32_t*)(g_Xhi + gid2), hv);
  __stcg((uint32_t*)(g_Xlo + gid2), lv);
}

// ---------------- persistent solver ----------------
__global__ void __launch_bounds__(NTHR, 2) solve_kernel(
    const float* __restrict__ ts,
    const float* __restrict__ b0, const float* __restrict__ b1,
    const float* __restrict__ b2, float* __restrict__ out)
{
  extern __shared__ __align__(16) char sm[];
  __shared__ float sred[64 * 8];
  __shared__ double sd[NTHR];

  const int bid = blockIdx.x;
  const int tid = threadIdx.x;
  const int grp_id = bid >> 4;
  const int lbid = bid & 15;
  const int gid2 = (bid * NTHR + tid) * 2;
  unsigned ep = 1;

  for (int step = 0; step < MAX_STEPS; ++step) {
    update_phase(gid2, out);
    ggsync(grp_id, ep++);

    do_stage<0>(grp_id, lbid, ep, b0, b1, b2, sm, sred, sd);
    do_stage<1>(grp_id, lbid, ep, b0, b1, b2, sm, sred, sd);
    do_stage<2>(grp_id, lbid, ep, b0, b1, b2, sm, sred, sd);
    do_stage<3>(grp_id, lbid, ep, b0, b1, b2, sm, sred, sd);
    do_stage<4>(grp_id, lbid, ep, b0, b1, b2, sm, sred, sd);
    do_stage<5>(grp_id, lbid, ep, b0, b1, b2, sm, sred, sd);
    do_stage<6>(grp_id, lbid, ep, b0, b1, b2, sm, sred, sd);

    gsync();

    if (bid == 0) {
      double v = ((volatile double*)g_errpart)[tid];
      sd[tid] = v;
      __syncthreads();
      #pragma unroll
      for (int s2 = 128; s2 > 0; s2 >>= 1) {
        if (tid < s2) sd[tid] += sd[tid + s2];
        __syncthreads();
      }
      if (tid == 0) {
        float enorm = sqrtf((float)(sd[0] / (double)NELEM));
        int done = g_done;
        float h = g_h;
        int accept = (enorm <= 1.0f) && !done;
        float t_new = g_t + h;
        int hit = accept && (t_new >= g_tns - 1e-6f);
        if (accept) g_t = t_new;
        g_accept = accept;
        g_hit = hit;
        g_wrow = g_sic;
        int si = g_si + hit;
        g_si = si;
        float factor;
        if (enorm > 0.f) {
          factor = 0.9f * powf(enorm, -0.2f);
          factor = fminf(fmaxf(factor, 0.2f), 10.f);
        } else factor = 10.f;
        if (!done) g_dt = g_dt * factor;
        int done2 = (si >= TT) ? 1 : 0;
        int sic2 = si < (TT - 1) ? si : (TT - 1);
        float tns2 = __ldg(ts + sic2);
        float h2 = done2 ? 0.f : fmaxf(fminf(g_dt, tns2 - g_t), 0.f);
        g_done = done2; g_sic = sic2; g_tns = tns2; g_h = h2;
      }
    }
    gsync();
  }
  update_phase(gid2, out);
}

// ---------------- init ----------------
__global__ void init_kernel(const float* __restrict__ ts, const float* __restrict__ y0,
                            const float* __restrict__ W0, const float* __restrict__ W1,
                            const float* __restrict__ W2, float* __restrict__ out)
{
  int idx = blockIdx.x * NTHR + threadIdx.x;
  if (idx < TT * NELEM) out[idx] = (idx < NELEM) ? y0[idx] : 0.f;
  if (idx < NELEM) {
    float v = y0[idx];
    g_y[idx] = v;
    bf16 h = __float2bfloat16(v);
    g_Xhi[idx] = h;
    g_Xlo[idx] = __float2bfloat16(v - __bfloat162float(h));
  }
  if (idx < WW * DD) {
    float w = W0[idx];
    bf16 h = __float2bfloat16(w);
    g_W0hi[idx] = h; g_W0lo[idx] = __float2bfloat16(w - __bfloat162float(h));
    float w2 = W2[idx];
    bf16 h2 = __float2bfloat16(w2);
    g_W2hi[idx] = h2; g_W2lo[idx] = __float2bfloat16(w2 - __bfloat162float(h2));
  }
  if (idx < WW * WW) {
    float w = W1[idx];
    bf16 h = __float2bfloat16(w);
    g_W1hi[idx] = h; g_W1lo[idx] = __float2bfloat16(w - __bfloat162float(h));
  }
  if (idx < NBLK * 32) gg_flag[idx] = 0u;
  if (idx < NBLK) g_errpart[idx] = 0.0;
  if (idx == 0) {
    float t0 = ts[0];
    float dt0 = ts[1] - ts[0];
    g_t = t0;
    g_dt = dt0;
    g_si = 1;
    g_accept = 0;
    g_hit = 0;
    g_wrow = 0;
    g_arrive = 0u;
    g_done = 0;
    g_sic = 1;
    float tns = ts[1];
    g_tns = tns;
    g_h = fmaxf(fminf(dt0, tns - t0), 0.f);
  }
}

extern "C" void kernel_launch(void* const* d_in, const int* in_sizes, int n_in,
                              void* d_out, int out_size) {
  const float* ts = (const float*)d_in[0];
  const float* y0 = (const float*)d_in[1];
  const float* W0 = (const float*)d_in[2];
  const float* b0 = (const float*)d_in[3];
  const float* W1 = (const float*)d_in[4];
  const float* b1 = (const float*)d_in[5];
  const float* W2 = (const float*)d_in[6];
  const float* b2 = (const float*)d_in[7];
  float* out = (float*)d_out;

  cudaFuncSetAttribute(solve_kernel, cudaFuncAttributeMaxDynamicSharedMemorySize, SMEM_DYN);

  init_kernel<<<(TT * NELEM) / NTHR, NTHR>>>(ts, y0, W0, W1, W2, out);
  solve_kernel<<<NBLK, NTHR, SMEM_DYN>>>(ts, b0, b1, b2, out);
}

// round 13
// speedup vs baseline: 1.8201x; 1.0486x over previous
#include <cuda_runtime.h>
#include <cuda_bf16.h>
#include <math.h>
#include <stdint.h>

typedef __nv_bfloat16 bf16;

#define BB 1024
#define DD 128
#define WW 512
#define TT 8
#define NELEM (BB*DD)
#define HELEM (BB*WW)
#define MAX_STEPS 48
#define NBLK 256
#define NTHR 256
#define GCTA 16
#define RTOLc 1e-3f
#define ATOLc 1e-6f

#define SROWB 144            // smem row stride bytes
#define OA_LO  9216          // 64*144
#define OB_HI 18432
#define OB_LO 23040          // +32*144
#define BUFS  27648          // bytes per buffer set
#define NSTG 3
#define SMEM_DYN (NSTG*BUFS) // 82944

#define A21f 0.161f
#define A31f (-0.008480655492356989f)
#define A32f 0.335480655492357f
#define A41f 2.8971530571054935f
#define A42f (-6.359448489975075f)
#define A43f 4.3622954328695815f
#define A51f 5.325864828439257f
#define A52f (-11.748883564062828f)
#define A53f 7.4955393428898365f
#define A54f (-0.09249506636175525f)
#define A61f 5.86145544294642f
#define A62f (-12.92096931784711f)
#define A63f 8.159367898576159f
#define A64f (-0.071584973281401f)
#define A65f (-0.028269050394068383f)
#define Bc1 0.09646076681806523f
#define Bc2 0.01f
#define Bc3 0.4798896504144996f
#define Bc4 1.379008574103742f
#define Bc5 (-3.290069515436081f)
#define Bc6 2.324710524099774f
#define Ec1 (-0.00178001105222577714f)
#define Ec2 (-0.0008164344596567469f)
#define Ec3 0.007880878010261995f
#define Ec4 (-0.1447110071732629f)
#define Ec5 0.5823571654525552f
#define Ec6 (-0.45808210592918697f)
#define Ec7 0.015151515151515152f

// ---------------- device state ----------------
__device__ __align__(16) float g_y[NELEM], g_ynew[NELEM], g_k[7][NELEM];
__device__ __align__(16) bf16 g_Xhi[NELEM], g_Xlo[NELEM];
__device__ __align__(16) bf16 g_H1hi[HELEM], g_H1lo[HELEM];
__device__ __align__(16) bf16 g_H2hi[HELEM], g_H2lo[HELEM];
__device__ __align__(16) bf16 g_W0hi[WW*DD], g_W0lo[WW*DD];
__device__ __align__(16) bf16 g_W1hi[WW*WW], g_W1lo[WW*WW];
__device__ __align__(16) bf16 g_W2hi[DD*WW], g_W2lo[DD*WW];
__device__ double g_errpart[NBLK];
__device__ volatile float g_t, g_dt, g_h, g_tns;
__device__ volatile int g_si, g_sic, g_done, g_accept, g_hit, g_wrow;
__device__ unsigned g_arrive;
__device__ volatile unsigned gg_flag[NBLK * 32];

__constant__ float c_coef[6][6] = {
  {A21f,0,0,0,0,0},
  {A31f,A32f,0,0,0,0},
  {A41f,A42f,A43f,0,0,0},
  {A51f,A52f,A53f,A54f,0,0},
  {A61f,A62f,A63f,A64f,A65f,0},
  {Bc1,Bc2,Bc3,Bc4,Bc5,Bc6},
};

// ---------------- helpers ----------------
__device__ __forceinline__ uint32_t smem_u32(const void* p) {
  uint32_t a;
  asm("{ .reg .u64 t; cvta.to.shared.u64 t, %1; cvt.u32.u64 %0, t; }" : "=r"(a) : "l"(p));
  return a;
}
__device__ __forceinline__ void cp16(uint32_t dst, const void* src) {
  asm volatile("cp.async.cg.shared.global [%0], [%1], 16;" :: "r"(dst), "l"(src) : "memory");
}
__device__ __forceinline__ void cp16ca(uint32_t dst, const void* src) {
  asm volatile("cp.async.ca.shared.global [%0], [%1], 16;" :: "r"(dst), "l"(src) : "memory");
}
__device__ __forceinline__ void cp_commit() { asm volatile("cp.async.commit_group;" ::: "memory"); }
__device__ __forceinline__ void cp_wait1() { asm volatile("cp.async.wait_group 1;" ::: "memory"); }

#define LDMX4(r, addr) \
  asm volatile("ldmatrix.sync.aligned.m8n8.x4.shared.b16 {%0,%1,%2,%3}, [%4];" \
    : "=r"((r)[0]), "=r"((r)[1]), "=r"((r)[2]), "=r"((r)[3]) : "r"(addr))
#define LDMX2(r, addr) \
  asm volatile("ldmatrix.sync.aligned.m8n8.x2.shared.b16 {%0,%1}, [%2];" \
    : "=r"((r)[0]), "=r"((r)[1]) : "r"(addr))

__device__ __forceinline__ void mma16816(float* c, const uint32_t* a, const uint32_t* b) {
  asm volatile(
    "mma.sync.aligned.m16n8k16.row.col.f32.bf16.bf16.f32 "
    "{%0,%1,%2,%3}, {%4,%5,%6,%7}, {%8,%9}, {%0,%1,%2,%3};"
    : "+f"(c[0]), "+f"(c[1]), "+f"(c[2]), "+f"(c[3])
    : "r"(a[0]), "r"(a[1]), "r"(a[2]), "r"(a[3]), "r"(b[0]), "r"(b[1]));
}

// ---------------- barriers ----------------
__device__ __forceinline__ void gsync() {
  __syncthreads();
  if (threadIdx.x == 0) {
    __threadfence();
    unsigned t = atomicAdd(&g_arrive, 1u) + 1u;
    unsigned target = ((t + NBLK - 1u) / NBLK) * NBLK;
    while (*(volatile unsigned*)&g_arrive < target) {}
    __threadfence();
  }
  __syncthreads();
}
__device__ __forceinline__ void ggsync(int grp, unsigned ep) {
  __syncthreads();
  if (threadIdx.x == 0) {
    __threadfence();
    gg_flag[blockIdx.x * 32] = ep;
  }
  if (threadIdx.x < GCTA) {
    const volatile unsigned* f = &gg_flag[(grp * GCTA + threadIdx.x) * 32];
    while (*f < ep) {}
  }
  __syncthreads();
}

// -------- MUFU-free softplus (abs err ~2e-6) --------
__device__ __forceinline__ float softplus_f(float x) {
  float t = fabsf(x);
  float s = fminf(t * 1.4426950408889634f, 100.f);
  float n = floorf(s);
  float r = n - s;
  float p = 1.3215487e-6f;
  p = fmaf(p, r, 1.5252734e-5f);
  p = fmaf(p, r, 1.5403530e-4f);
  p = fmaf(p, r, 1.3333558e-3f);
  p = fmaf(p, r, 9.6181291e-3f);
  p = fmaf(p, r, 5.5504109e-2f);
  p = fmaf(p, r, 2.4022651e-1f);
  p = fmaf(p, r, 6.9314718e-1f);
  p = fmaf(p, r, 1.0f);
  float u = p * __uint_as_float((uint32_t)(127 - (int)n) << 23);
  float d = 2.f + u;
  float w = fmaf(-0.1635f, u, 0.4915f);
  w = w * fmaf(-d, w, 2.f);
  w = w * fmaf(-d, w, 2.f);
  float v = u * w;
  float v2 = v * v;
  float g = 0.09090909f;
  g = fmaf(g, v2, 0.11111111f);
  g = fmaf(g, v2, 0.14285714f);
  g = fmaf(g, v2, 0.2f);
  g = fmaf(g, v2, 0.33333333f);
  g = fmaf(g, v2, 1.0f);
  return fmaxf(x, 0.f) + 2.f * v * g;
}

__device__ __forceinline__ void split_pack(float x0, float x1, uint32_t& hv, uint32_t& lv) {
  bf16 h0 = __float2bfloat16(x0), h1 = __float2bfloat16(x1);
  bf16 l0 = __float2bfloat16(x0 - __bfloat162float(h0));
  bf16 l1 = __float2bfloat16(x1 - __bfloat162float(h1));
  hv = (uint32_t)__bfloat16_as_ushort(h0) | ((uint32_t)__bfloat16_as_ushort(h1) << 16);
  lv = (uint32_t)__bfloat16_as_ushort(l0) | ((uint32_t)__bfloat16_as_ushort(l1) << 16);
}

// ---------------- GEMM1/2: C[64,32] = act(A[64,K] @ B[32,K]^T + bias) -> bf16 hi/lo ----------------
template<bool SP>
__device__ __forceinline__ void mma_gemm(
    const bf16* __restrict__ Ahi, const bf16* __restrict__ Alo,
    const bf16* __restrict__ Bhi, const bf16* __restrict__ Blo,
    int ldk, int bm, int bn, int nchunk,
    const float* __restrict__ bias,
    bf16* __restrict__ Chi, bf16* __restrict__ Clo, int ldc,
    char* sm)
{
  const int tid = threadIdx.x;
  const int wid = tid >> 5;
  const int lane = tid & 31;
  const int grp = lane >> 2, tig = lane & 3;
  const int wm = wid >> 1, wn = wid & 1;   // 4 x 2 warps over 64x32

  float hh[2][4] = {}, hl[2][4] = {}, lh[2][4] = {};

  int ar[4], as[4]; bool asel[4];
  #pragma unroll
  for (int i = 0; i < 4; ++i) {
    int lin = i * 256 + tid;
    asel[i] = lin >= 512;
    ar[i] = (lin >> 3) & 63;
    as[i] = (lin & 7) << 3;
  }
  int br[2], bs[2]; bool bsel[2];
  #pragma unroll
  for (int i = 0; i < 2; ++i) {
    int lin = i * 256 + tid;
    bsel[i] = lin >= 256;
    br[i] = (lin >> 3) & 31;
    bs[i] = (lin & 7) << 3;
  }
  const uint32_t smb = smem_u32(sm);
  uint32_t stA[4], stB[2];
  #pragma unroll
  for (int i = 0; i < 4; ++i) stA[i] = smb + (asel[i] ? OA_LO : 0) + ar[i] * SROWB + as[i] * 2;
  #pragma unroll
  for (int i = 0; i < 2; ++i) stB[i] = smb + (bsel[i] ? OB_LO : OB_HI) + br[i] * SROWB + bs[i] * 2;
  const bf16* gA[4]; const bf16* gB[2];
  #pragma unroll
  for (int i = 0; i < 4; ++i) gA[i] = (asel[i] ? Alo : Ahi) + (bm + ar[i]) * ldk + as[i];
  #pragma unroll
  for (int i = 0; i < 2; ++i) gB[i] = (bsel[i] ? Blo : Bhi) + (bn + br[i]) * ldk + bs[i];

  const uint32_t laA_hi = smb + (wm * 16 + (lane & 15)) * SROWB + ((lane >> 4) << 4);
  const uint32_t laA_lo = laA_hi + OA_LO;
  // x4 B: lanes 0-7 -> rows wn*16+0..7 (k lo), 8-15 -> same rows k hi, 16-23 -> rows +8 k lo, 24-31 -> rows +8 k hi
  const uint32_t laB4_hi = smb + OB_HI + (wn * 16 + ((lane >> 4) << 3) + (lane & 7)) * SROWB
                           + (((lane >> 3) & 1) << 4);
  const uint32_t laB4_lo = laB4_hi + (OB_LO - OB_HI);

  #pragma unroll
  for (int i = 0; i < 4; ++i) cp16(stA[i], gA[i]);
  #pragma unroll
  for (int i = 0; i < 2; ++i) cp16ca(stB[i], gB[i]);
  cp_commit();
  if (nchunk > 1) {
    #pragma unroll
    for (int i = 0; i < 4; ++i) cp16(stA[i] + BUFS, gA[i] + 64);
    #pragma unroll
    for (int i = 0; i < 2; ++i) cp16ca(stB[i] + BUFS, gB[i] + 64);
  }
  cp_commit();

  for (int c = 0; c < nchunk; ++c) {
    cp_wait1();
    __syncthreads();
    const uint32_t bo = (uint32_t)(c % NSTG) * BUFS;
    #pragma unroll
    for (int ks = 0; ks < 4; ++ks) {
      uint32_t ah[4], al[4], b4h[4], b4l[4];
      LDMX4(ah, laA_hi + bo + ks * 32);
      LDMX4(al, laA_lo + bo + ks * 32);
      LDMX4(b4h, laB4_hi + bo + ks * 32);
      LDMX4(b4l, laB4_lo + bo + ks * 32);
      mma16816(hh[0], ah, b4h);
      mma16816(hl[0], ah, b4l);
      mma16816(lh[0], al, b4h);
      mma16816(hh[1], ah, b4h + 2);
      mma16816(hl[1], ah, b4l + 2);
      mma16816(lh[1], al, b4h + 2);
    }
    if (c + 2 < nchunk) {
      const uint32_t bo2 = (uint32_t)((c + 2) % NSTG) * BUFS;
      int k0 = (c + 2) * 64;
      #pragma unroll
      for (int i = 0; i < 4; ++i) cp16(stA[i] + bo2, gA[i] + k0);
      #pragma unroll
      for (int i = 0; i < 2; ++i) cp16ca(stB[i] + bo2, gB[i] + k0);
    }
    cp_commit();
  }

  #pragma unroll
  for (int ni = 0; ni < 2; ++ni) {
    int m0 = bm + wm * 16 + grp;
    int n  = bn + wn * 16 + ni * 8 + tig * 2;
    float bv0 = __ldg(bias + n), bv1 = __ldg(bias + n + 1);
    float x0 = hh[ni][0] + hl[ni][0] + lh[ni][0] + bv0;
    float x1 = hh[ni][1] + hl[ni][1] + lh[ni][1] + bv1;
    float x2 = hh[ni][2] + hl[ni][2] + lh[ni][2] + bv0;
    float x3 = hh[ni][3] + hl[ni][3] + lh[ni][3] + bv1;
    if (SP) { x0 = softplus_f(x0); x1 = softplus_f(x1); x2 = softplus_f(x2); x3 = softplus_f(x3); }
    uint32_t hv, lv;
    split_pack(x0, x1, hv, lv);
    __stcg((uint32_t*)(Chi + m0 * ldc + n), hv);
    __stcg((uint32_t*)(Clo + m0 * ldc + n), lv);
    split_pack(x2, x3, hv, lv);
    __stcg((uint32_t*)(Chi + (m0 + 8) * ldc + n), hv);
    __stcg((uint32_t*)(Clo + (m0 + 8) * ldc + n), lv);
  }
}

// ---------------- GEMM3 (stage S): k_S[16,32] tile, K=512, fused RK epilogue ----------------
// bm3 = group*64 + (lbid>>2)*16 (4 M-slices), bn3 = (lbid&3)*32 (4 N-slices).
template<int S>
__device__ __forceinline__ void gemm3_stage(
    char* sm, float* sred,
    int bm, int bn, const float* __restrict__ b2, double* sd)
{
  const int tid = threadIdx.x;
  const int wid = tid >> 5, lane = tid & 31;
  const int wn = wid & 3, wk = wid >> 2;       // 4 n8-slices x 2 k-halves
  const int grp = lane >> 2, tig = lane & 3;

  float hh[4] = {}, hl[4] = {}, lh[4] = {};

  // A fill: 2 arrays x 16 rows x 8 segs = 256 cp16 -> 1/thread
  const bool aselt = tid >= 128;
  const int arow = (tid >> 3) & 15;
  const int aseg = (tid & 7) << 3;
  // B fill: 2 arrays x 32 rows x 8 segs = 512 -> 2/thread
  int br[2], bs[2]; bool bsel[2];
  #pragma unroll
  for (int i = 0; i < 2; ++i) {
    int lin = i * 256 + tid;
    bsel[i] = lin >= 256;
    br[i] = (lin >> 3) & 31;
    bs[i] = (lin & 7) << 3;
  }

  const uint32_t smb = smem_u32(sm);
  const uint32_t stA = smb + (aselt ? OA_LO : 0) + arow * SROWB + aseg * 2;
  uint32_t stB[2];
  #pragma unroll
  for (int i = 0; i < 2; ++i) stB[i] = smb + (bsel[i] ? OB_LO : OB_HI) + br[i] * SROWB + bs[i] * 2;
  const bf16* gA = (aselt ? g_H2lo : g_H2hi) + (bm + arow) * WW + aseg;
  const bf16* gB[2];
  #pragma unroll
  for (int i = 0; i < 2; ++i) gB[i] = (bsel[i] ? g_W2lo : g_W2hi) + (bn + br[i]) * WW + bs[i];

  const uint32_t laA_hi = smb + (lane & 15) * SROWB + ((lane >> 4) << 4);
  const uint32_t laA_lo = laA_hi + OA_LO;
  const uint32_t laB_hi = smb + OB_HI + (wn * 8 + (lane & 7)) * SROWB + (((lane >> 3) & 1) << 4);
  const uint32_t laB_lo = laB_hi + (OB_LO - OB_HI);

  cp16(stA, gA);
  #pragma unroll
  for (int i = 0; i < 2; ++i) cp16ca(stB[i], gB[i]);
  cp_commit();
  cp16(stA + BUFS, gA + 64);
  #pragma unroll
  for (int i = 0; i < 2; ++i) cp16ca(stB[i] + BUFS, gB[i] + 64);
  cp_commit();

  for (int c = 0; c < 8; ++c) {
    cp_wait1();
    __syncthreads();
    const uint32_t bo = (uint32_t)(c % NSTG) * BUFS;
    #pragma unroll
    for (int ks2 = 0; ks2 < 2; ++ks2) {
      const int ks = wk * 2 + ks2;
      uint32_t ah[4], al[4], bh[2], bl[2];
      LDMX4(ah, laA_hi + bo + ks * 32);
      LDMX4(al, laA_lo + bo + ks * 32);
      LDMX2(bh, laB_hi + bo + ks * 32);
      LDMX2(bl, laB_lo + bo + ks * 32);
      mma16816(hh, ah, bh);
      mma16816(hl, ah, bl);
      mma16816(lh, al, bh);
    }
    if (c + 2 < 8) {
      const uint32_t bo2 = (uint32_t)((c + 2) % NSTG) * BUFS;
      int k0 = (c + 2) * 64;
      cp16(stA + bo2, gA + k0);
      #pragma unroll
      for (int i = 0; i < 2; ++i) cp16ca(stB[i] + bo2, gB[i] + k0);
    }
    cp_commit();
  }

  float acc[4];
  #pragma unroll
  for (int j = 0; j < 4; ++j) acc[j] = hh[j] + hl[j] + lh[j];

  // cross k-half reduce via sred (16 x 32)
  const int nl = wn * 8 + tig * 2;
  if (wk == 1) {
    sred[grp * 32 + nl]           = acc[0];
    sred[grp * 32 + nl + 1]       = acc[1];
    sred[(grp + 8) * 32 + nl]     = acc[2];
    sred[(grp + 8) * 32 + nl + 1] = acc[3];
  }
  __syncthreads();
  double ss = 0.0;
  if (wk == 0) {
    acc[0] += sred[grp * 32 + nl];
    acc[1] += sred[grp * 32 + nl + 1];
    acc[2] += sred[(grp + 8) * 32 + nl];
    acc[3] += sred[(grp + 8) * 32 + nl + 1];

    const int n0 = bn + nl;
    const int m0 = bm + grp;
    const float h = g_h;
    const int i0 = m0 * DD + n0;
    const int i1 = (m0 + 8) * DD + n0;
    float bv0 = __ldg(b2 + n0), bv1 = __ldg(b2 + n0 + 1);
    float2 v0 = {acc[0] + bv0, acc[1] + bv1};
    float2 v1 = {acc[2] + bv0, acc[3] + bv1};
    __stcg((float2*)(g_k[S] + i0), v0);
    __stcg((float2*)(g_k[S] + i1), v1);

    const int idxs[2] = {i0, i1};
    const float2 vs[2] = {v0, v1};
    if constexpr (S <= 5) {
      #pragma unroll
      for (int r = 0; r < 2; ++r) {
        int ix = idxs[r];
        float2 y2 = __ldcg((const float2*)(g_y + ix));
        float cS = c_coef[S][S];
        float ax = cS * vs[r].x, ay = cS * vs[r].y;
        #pragma unroll
        for (int j = 0; j < S; ++j) {
          float cj = c_coef[S][j];
          float2 kj = __ldcg((const float2*)(g_k[j] + ix));
          ax = fmaf(cj, kj.x, ax);
          ay = fmaf(cj, kj.y, ay);
        }
        float Xx = fmaf(h, ax, y2.x);
        float Xy = fmaf(h, ay, y2.y);
        if constexpr (S == 5) {
          float2 yn = {Xx, Xy};
          __stcg((float2*)(g_ynew + ix), yn);
        }
        uint32_t hv, lv;
        split_pack(Xx, Xy, hv, lv);
        __stcg((uint32_t*)(g_Xhi + ix), hv);
        __stcg((uint32_t*)(g_Xlo + ix), lv);
      }
    } else {
      #pragma unroll
      for (int r = 0; r < 2; ++r) {
        int ix = idxs[r];
        float2 k0 = __ldcg((const float2*)(g_k[0] + ix));
        float2 k1 = __ldcg((const float2*)(g_k[1] + ix));
        float2 k2 = __ldcg((const float2*)(g_k[2] + ix));
        float2 k3 = __ldcg((const float2*)(g_k[3] + ix));
        float2 k4 = __ldcg((const float2*)(g_k[4] + ix));
        float2 k5 = __ldcg((const float2*)(g_k[5] + ix));
        float2 y2 = __ldcg((const float2*)(g_y + ix));
        float2 yn = __ldcg((const float2*)(g_ynew + ix));
        #pragma unroll
        for (int cc = 0; cc < 2; ++cc) {
          float e = Ec1 * (cc ? k0.y : k0.x);
          e = fmaf(Ec2, cc ? k1.y : k1.x, e);
          e = fmaf(Ec3, cc ? k2.y : k2.x, e);
          e = fmaf(Ec4, cc ? k3.y : k3.x, e);
          e = fmaf(Ec5, cc ? k4.y : k4.x, e);
          e = fmaf(Ec6, cc ? k5.y : k5.x, e);
          e = fmaf(Ec7, cc ? vs[r].y : vs[r].x, e);
          float err = h * e;
          float yv = cc ? y2.y : y2.x, ynv = cc ? yn.y : yn.x;
          float scale = ATOLc + RTOLc * fmaxf(fabsf(yv), fabsf(ynv));
          float rr = err / scale;
          ss += (double)rr * (double)rr;
        }
      }
    }
  }
  if constexpr (S == 6) {
    sd[tid] = ss;
    __syncthreads();
    #pragma unroll
    for (int s2 = 128; s2 > 0; s2 >>= 1) {
      if (tid < s2) sd[tid] += sd[tid + s2];
      __syncthreads();
    }
    if (tid == 0) ((volatile double*)g_errpart)[blockIdx.x] = sd[0];
  }
}

// ---------------- one RK stage (group-local syncs) ----------------
template<int S>
__device__ __forceinline__ void do_stage(int grp_id, int lbid, unsigned& ep,
    const float* b0, const float* b1, const float* b2,
    char* sm, float* sred, double* sd)
{
  const int bm = grp_id << 6;
  const int bn = lbid << 5;
  mma_gemm<true>(g_Xhi, g_Xlo, g_W0hi, g_W0lo, DD, bm, bn, 2, b0, g_H1hi, g_H1lo, WW, sm);
  ggsync(grp_id, ep++);
  mma_gemm<true>(g_H1hi, g_H1lo, g_W1hi, g_W1lo, WW, bm, bn, 8, b1, g_H2hi, g_H2lo, WW, sm);
  ggsync(grp_id, ep++);
  gemm3_stage<S>(sm, sred, bm + ((lbid >> 2) << 4), (lbid & 3) << 5, b2, sd);
  if (S < 6) ggsync(grp_id, ep++);
}

__device__ __forceinline__ void update_phase(int gid2, float* __restrict__ out) {
  float2 v;
  if (g_accept) {
    v = __ldcg((const float2*)(g_ynew + gid2));
    __stcg((float2*)(g_y + gid2), v);
    if (g_hit) *(float2*)(out + g_wrow * NELEM + gid2) = v;
  } else {
    v = __ldcg((const float2*)(g_y + gid2));
  }
  uint32_t hv, lv;
  split_pack(v.x, v.y, hv, lv);
  __stcg((uint32_t*)(g_Xhi + gid2), hv);
  __stcg((uint32_t*)(g_Xlo + gid2), lv);
}

// ---------------- persistent solver ----------------
__global__ void __launch_bounds__(NTHR, 2) solve_kernel(
    const float* __restrict__ ts,
    const float* __restrict__ b0, const float* __restrict__ b1,
    const float* __restrict__ b2, float* __restrict__ out)
{
  extern __shared__ __align__(16) char sm[];
  __shared__ float sred[16 * 32];
  __shared__ double sd[NTHR];

  const int bid = blockIdx.x;
  const int tid = threadIdx.x;
  const int grp_id = bid >> 4;
  const int lbid = bid & 15;
  const int gid2 = (bid * NTHR + tid) * 2;
  unsigned ep = 1;

  for (int step = 0; step < MAX_STEPS; ++step) {
    update_phase(gid2, out);
    ggsync(grp_id, ep++);

    do_stage<0>(grp_id, lbid, ep, b0, b1, b2, sm, sred, sd);
    do_stage<1>(grp_id, lbid, ep, b0, b1, b2, sm, sred, sd);
    do_stage<2>(grp_id, lbid, ep, b0, b1, b2, sm, sred, sd);
    do_stage<3>(grp_id, lbid, ep, b0, b1, b2, sm, sred, sd);
    do_stage<4>(grp_id, lbid, ep, b0, b1, b2, sm, sred, sd);
    do_stage<5>(grp_id, lbid, ep, b0, b1, b2, sm, sred, sd);
    do_stage<6>(grp_id, lbid, ep, b0, b1, b2, sm, sred, sd);

    gsync();

    if (bid == 0) {
      double v = ((volatile double*)g_errpart)[tid];
      sd[tid] = v;
      __syncthreads();
      #pragma unroll
      for (int s2 = 128; s2 > 0; s2 >>= 1) {
        if (tid < s2) sd[tid] += sd[tid + s2];
        __syncthreads();
      }
      if (tid == 0) {
        float enorm = sqrtf((float)(sd[0] / (double)NELEM));
        int done = g_done;
        float h = g_h;
        int accept = (enorm <= 1.0f) && !done;
        float t_new = g_t + h;
        int hit = accept && (t_new >= g_tns - 1e-6f);
        if (accept) g_t = t_new;
        g_accept = accept;
        g_hit = hit;
        g_wrow = g_sic;
        int si = g_si + hit;
        g_si = si;
        float factor;
        if (enorm > 0.f) {
          factor = 0.9f * powf(enorm, -0.2f);
          factor = fminf(fmaxf(factor, 0.2f), 10.f);
        } else factor = 10.f;
        if (!done) g_dt = g_dt * factor;
        int done2 = (si >= TT) ? 1 : 0;
        int sic2 = si < (TT - 1) ? si : (TT - 1);
        float tns2 = __ldg(ts + sic2);
        float h2 = done2 ? 0.f : fmaxf(fminf(g_dt, tns2 - g_t), 0.f);
        g_done = done2; g_sic = sic2; g_tns = tns2; g_h = h2;
      }
    }
    gsync();
  }
  update_phase(gid2, out);
}

// ---------------- init ----------------
__global__ void init_kernel(const float* __restrict__ ts, const float* __restrict__ y0,
                            const float* __restrict__ W0, const float* __restrict__ W1,
                            const float* __restrict__ W2, float* __restrict__ out)
{
  int idx = blockIdx.x * NTHR + threadIdx.x;
  if (idx < TT * NELEM) out[idx] = (idx < NELEM) ? y0[idx] : 0.f;
  if (idx < NELEM) {
    float v = y0[idx];
    g_y[idx] = v;
    bf16 h = __float2bfloat16(v);
    g_Xhi[idx] = h;
    g_Xlo[idx] = __float2bfloat16(v - __bfloat162float(h));
  }
  if (idx < WW * DD) {
    float w = W0[idx];
    bf16 h = __float2bfloat16(w);
    g_W0hi[idx] = h; g_W0lo[idx] = __float2bfloat16(w - __bfloat162float(h));
    float w2 = W2[idx];
    bf16 h2 = __float2bfloat16(w2);
    g_W2hi[idx] = h2; g_W2lo[idx] = __float2bfloat16(w2 - __bfloat162float(h2));
  }
  if (idx < WW * WW) {
    float w = W1[idx];
    bf16 h = __float2bfloat16(w);
    g_W1hi[idx] = h; g_W1lo[idx] = __float2bfloat16(w - __bfloat162float(h));
  }
  if (idx < NBLK * 32) gg_flag[idx] = 0u;
  if (idx < NBLK) g_errpart[idx] = 0.0;
  if (idx == 0) {
    float t0 = ts[0];
    float dt0 = ts[1] - ts[0];
    g_t = t0;
    g_dt = dt0;
    g_si = 1;
    g_accept = 0;
    g_hit = 0;
    g_wrow = 0;
    g_arrive = 0u;
    g_done = 0;
    g_sic = 1;
    float tns = ts[1];
    g_tns = tns;
    g_h = fmaxf(fminf(dt0, tns - t0), 0.f);
  }
}

extern "C" void kernel_launch(void* const* d_in, const int* in_sizes, int n_in,
                              void* d_out, int out_size) {
  const float* ts = (const float*)d_in[0];
  const float* y0 = (const float*)d_in[1];
  const float* W0 = (const float*)d_in[2];
  const float* b0 = (const float*)d_in[3];
  const float* W1 = (const float*)d_in[4];
  const float* b1 = (const float*)d_in[5];
  const float* W2 = (const float*)d_in[6];
  const float* b2 = (const float*)d_in[7];
  float* out = (float*)d_out;

  cudaFuncSetAttribute(solve_kernel, cudaFuncAttributeMaxDynamicSharedMemorySize, SMEM_DYN);

  init_kernel<<<(TT * NELEM) / NTHR, NTHR>>>(ts, y0, W0, W1, W2, out);
  solve_kernel<<<NBLK, NTHR, SMEM_DYN>>>(ts, b0, b1, b2, out);
}

// round 14
// speedup vs baseline: 12.2924x; 6.7536x over previous
#include <cuda_runtime.h>
#include <cuda_bf16.h>
#include <math.h>
#include <stdint.h>

typedef __nv_bfloat16 bf16;

#define BB 1024
#define DD 128
#define WW 512
#define TT 8
#define NELEM (BB*DD)
#define HELEM (BB*WW)
#define MAX_STEPS 48
#define NBLK 256
#define NTHR 256
#define GCTA 16
#define RTOLc 1e-3f
#define ATOLc 1e-6f

#define SROWB 144            // smem row stride bytes
#define OA_LO  9216          // 64*144
#define OB_HI 18432
#define OB_LO 23040          // +32*144
#define BUFS  27648          // bytes per buffer set
#define NSTG 3
#define SMEM_DYN (NSTG*BUFS) // 82944

#define A21f 0.161f
#define A31f (-0.008480655492356989f)
#define A32f 0.335480655492357f
#define A41f 2.8971530571054935f
#define A42f (-6.359448489975075f)
#define A43f 4.3622954328695815f
#define A51f 5.325864828439257f
#define A52f (-11.748883564062828f)
#define A53f 7.4955393428898365f
#define A54f (-0.09249506636175525f)
#define A61f 5.86145544294642f
#define A62f (-12.92096931784711f)
#define A63f 8.159367898576159f
#define A64f (-0.071584973281401f)
#define A65f (-0.028269050394068383f)
#define Bc1 0.09646076681806523f
#define Bc2 0.01f
#define Bc3 0.4798896504144996f
#define Bc4 1.379008574103742f
#define Bc5 (-3.290069515436081f)
#define Bc6 2.324710524099774f
#define Ec1 (-0.00178001105222577714f)
#define Ec2 (-0.0008164344596567469f)
#define Ec3 0.007880878010261995f
#define Ec4 (-0.1447110071732629f)
#define Ec5 0.5823571654525552f
#define Ec6 (-0.45808210592918697f)
#define Ec7 0.015151515151515152f

// ---------------- device state ----------------
__device__ __align__(16) float g_y[NELEM], g_ynew[NELEM], g_k[7][NELEM];
__device__ __align__(16) bf16 g_Xhi[NELEM], g_Xlo[NELEM];
__device__ __align__(16) bf16 g_H1hi[HELEM], g_H1lo[HELEM];
__device__ __align__(16) bf16 g_H2hi[HELEM], g_H2lo[HELEM];
__device__ __align__(16) bf16 g_W0hi[WW*DD], g_W0lo[WW*DD];
__device__ __align__(16) bf16 g_W1hi[WW*WW], g_W1lo[WW*WW];
__device__ __align__(16) bf16 g_W2hi[DD*WW], g_W2lo[DD*WW];
__device__ double g_errpart[NBLK];
__device__ volatile float g_t, g_dt, g_h, g_tns;
__device__ volatile int g_si, g_sic, g_done, g_accept, g_hit, g_wrow;
__device__ unsigned g_arrive;
__device__ volatile unsigned gg_flag[NBLK * 32];

__constant__ float c_coef[6][6] = {
  {A21f,0,0,0,0,0},
  {A31f,A32f,0,0,0,0},
  {A41f,A42f,A43f,0,0,0},
  {A51f,A52f,A53f,A54f,0,0},
  {A61f,A62f,A63f,A64f,A65f,0},
  {Bc1,Bc2,Bc3,Bc4,Bc5,Bc6},
};

// ---------------- helpers ----------------
__device__ __forceinline__ uint32_t smem_u32(const void* p) {
  uint32_t a;
  asm("{ .reg .u64 t; cvta.to.shared.u64 t, %1; cvt.u32.u64 %0, t; }" : "=r"(a) : "l"(p));
  return a;
}
__device__ __forceinline__ void cp16(uint32_t dst, const void* src) {
  asm volatile("cp.async.cg.shared.global [%0], [%1], 16;" :: "r"(dst), "l"(src) : "memory");
}
__device__ __forceinline__ void cp16ca(uint32_t dst, const void* src) {
  asm volatile("cp.async.ca.shared.global [%0], [%1], 16;" :: "r"(dst), "l"(src) : "memory");
}
__device__ __forceinline__ void cp_commit() { asm volatile("cp.async.commit_group;" ::: "memory"); }
__device__ __forceinline__ void cp_wait1() { asm volatile("cp.async.wait_group 1;" ::: "memory"); }

#define LDMX4(r, addr) \
  asm volatile("ldmatrix.sync.aligned.m8n8.x4.shared.b16 {%0,%1,%2,%3}, [%4];" \
    : "=r"((r)[0]), "=r"((r)[1]), "=r"((r)[2]), "=r"((r)[3]) : "r"(addr))
#define LDMX2(r, addr) \
  asm volatile("ldmatrix.sync.aligned.m8n8.x2.shared.b16 {%0,%1}, [%2];" \
    : "=r"((r)[0]), "=r"((r)[1]) : "r"(addr))

__device__ __forceinline__ void mma16816(float* c, const uint32_t* a, const uint32_t* b) {
  asm volatile(
    "mma.sync.aligned.m16n8k16.row.col.f32.bf16.bf16.f32 "
    "{%0,%1,%2,%3}, {%4,%5,%6,%7}, {%8,%9}, {%0,%1,%2,%3};"
    : "+f"(c[0]), "+f"(c[1]), "+f"(c[2]), "+f"(c[3])
    : "r"(a[0]), "r"(a[1]), "r"(a[2]), "r"(a[3]), "r"(b[0]), "r"(b[1]));
}

// ---------------- barriers ----------------
__device__ __forceinline__ void gsync() {
  __syncthreads();
  if (threadIdx.x == 0) {
    __threadfence();
    unsigned t = atomicAdd(&g_arrive, 1u) + 1u;
    unsigned target = ((t + NBLK - 1u) / NBLK) * NBLK;
    while (*(volatile unsigned*)&g_arrive < target) {}
    __threadfence();
  }
  __syncthreads();
}
__device__ __forceinline__ void ggsync(int grp, unsigned ep) {
  __syncthreads();
  if (threadIdx.x == 0) {
    __threadfence();
    gg_flag[blockIdx.x * 32] = ep;
  }
  if (threadIdx.x < GCTA) {
    const volatile unsigned* f = &gg_flag[(grp * GCTA + threadIdx.x) * 32];
    while (*f < ep) {}
  }
  __syncthreads();
}

// -------- MUFU-free softplus (abs err ~2e-6) --------
__device__ __forceinline__ float softplus_f(float x) {
  float t = fabsf(x);
  float s = fminf(t * 1.4426950408889634f, 100.f);
  float n = floorf(s);
  float r = n - s;
  float p = 1.3215487e-6f;
  p = fmaf(p, r, 1.5252734e-5f);
  p = fmaf(p, r, 1.5403530e-4f);
  p = fmaf(p, r, 1.3333558e-3f);
  p = fmaf(p, r, 9.6181291e-3f);
  p = fmaf(p, r, 5.5504109e-2f);
  p = fmaf(p, r, 2.4022651e-1f);
  p = fmaf(p, r, 6.9314718e-1f);
  p = fmaf(p, r, 1.0f);
  float u = p * __uint_as_float((uint32_t)(127 - (int)n) << 23);
  float d = 2.f + u;
  float w = fmaf(-0.1635f, u, 0.4915f);
  w = w * fmaf(-d, w, 2.f);
  w = w * fmaf(-d, w, 2.f);
  float v = u * w;
  float v2 = v * v;
  float g = 0.09090909f;
  g = fmaf(g, v2, 0.11111111f);
  g = fmaf(g, v2, 0.14285714f);
  g = fmaf(g, v2, 0.2f);
  g = fmaf(g, v2, 0.33333333f);
  g = fmaf(g, v2, 1.0f);
  return fmaxf(x, 0.f) + 2.f * v * g;
}

__device__ __forceinline__ void split_pack(float x0, float x1, uint32_t& hv, uint32_t& lv) {
  bf16 h0 = __float2bfloat16(x0), h1 = __float2bfloat16(x1);
  bf16 l0 = __float2bfloat16(x0 - __bfloat162float(h0));
  bf16 l1 = __float2bfloat16(x1 - __bfloat162float(h1));
  hv = (uint32_t)__bfloat16_as_ushort(h0) | ((uint32_t)__bfloat16_as_ushort(h1) << 16);
  lv = (uint32_t)__bfloat16_as_ushort(l0) | ((uint32_t)__bfloat16_as_ushort(l1) << 16);
}

// ---------------- GEMM1/2: C[64,32] = act(A[64,K] @ B[32,K]^T + bias) -> bf16 hi/lo ----------------
template<bool SP>
__device__ __forceinline__ void mma_gemm(
    const bf16* __restrict__ Ahi, const bf16* __restrict__ Alo,
    const bf16* __restrict__ Bhi, const bf16* __restrict__ Blo,
    int ldk, int bm, int bn, int nchunk,
    const float* __restrict__ bias,
    bf16* __restrict__ Chi, bf16* __restrict__ Clo, int ldc,
    char* sm)
{
  const int tid = threadIdx.x;
  const int wid = tid >> 5;
  const int lane = tid & 31;
  const int grp = lane >> 2, tig = lane & 3;
  const int wm = wid >> 1, wn = wid & 1;   // 4 x 2 warps over 64x32

  float hh[2][4] = {}, hl[2][4] = {}, lh[2][4] = {};

  int ar[4], as[4]; bool asel[4];
  #pragma unroll
  for (int i = 0; i < 4; ++i) {
    int lin = i * 256 + tid;
    asel[i] = lin >= 512;
    ar[i] = (lin >> 3) & 63;
    as[i] = (lin & 7) << 3;
  }
  int br[2], bs[2]; bool bsel[2];
  #pragma unroll
  for (int i = 0; i < 2; ++i) {
    int lin = i * 256 + tid;
    bsel[i] = lin >= 256;
    br[i] = (lin >> 3) & 31;
    bs[i] = (lin & 7) << 3;
  }
  const uint32_t smb = smem_u32(sm);
  uint32_t stA[4], stB[2];
  #pragma unroll
  for (int i = 0; i < 4; ++i) stA[i] = smb + (asel[i] ? OA_LO : 0) + ar[i] * SROWB + as[i] * 2;
  #pragma unroll
  for (int i = 0; i < 2; ++i) stB[i] = smb + (bsel[i] ? OB_LO : OB_HI) + br[i] * SROWB + bs[i] * 2;
  const bf16* gA[4]; const bf16* gB[2];
  #pragma unroll
  for (int i = 0; i < 4; ++i) gA[i] = (asel[i] ? Alo : Ahi) + (bm + ar[i]) * ldk + as[i];
  #pragma unroll
  for (int i = 0; i < 2; ++i) gB[i] = (bsel[i] ? Blo : Bhi) + (bn + br[i]) * ldk + bs[i];

  const uint32_t laA_hi = smb + (wm * 16 + (lane & 15)) * SROWB + ((lane >> 4) << 4);
  const uint32_t laA_lo = laA_hi + OA_LO;
  const uint32_t laB4_hi = smb + OB_HI + (wn * 16 + ((lane >> 4) << 3) + (lane & 7)) * SROWB
                           + (((lane >> 3) & 1) << 4);
  const uint32_t laB4_lo = laB4_hi + (OB_LO - OB_HI);

  #pragma unroll
  for (int i = 0; i < 4; ++i) cp16(stA[i], gA[i]);
  #pragma unroll
  for (int i = 0; i < 2; ++i) cp16ca(stB[i], gB[i]);
  cp_commit();
  if (nchunk > 1) {
    #pragma unroll
    for (int i = 0; i < 4; ++i) cp16(stA[i] + BUFS, gA[i] + 64);
    #pragma unroll
    for (int i = 0; i < 2; ++i) cp16ca(stB[i] + BUFS, gB[i] + 64);
  }
  cp_commit();

  for (int c = 0; c < nchunk; ++c) {
    cp_wait1();
    __syncthreads();
    const uint32_t bo = (uint32_t)(c % NSTG) * BUFS;
    #pragma unroll
    for (int ks = 0; ks < 4; ++ks) {
      uint32_t ah[4], al[4], b4h[4], b4l[4];
      LDMX4(ah, laA_hi + bo + ks * 32);
      LDMX4(al, laA_lo + bo + ks * 32);
      LDMX4(b4h, laB4_hi + bo + ks * 32);
      LDMX4(b4l, laB4_lo + bo + ks * 32);
      mma16816(hh[0], ah, b4h);
      mma16816(hl[0], ah, b4l);
      mma16816(lh[0], al, b4h);
      mma16816(hh[1], ah, b4h + 2);
      mma16816(hl[1], ah, b4l + 2);
      mma16816(lh[1], al, b4h + 2);
    }
    if (c + 2 < nchunk) {
      const uint32_t bo2 = (uint32_t)((c + 2) % NSTG) * BUFS;
      int k0 = (c + 2) * 64;
      #pragma unroll
      for (int i = 0; i < 4; ++i) cp16(stA[i] + bo2, gA[i] + k0);
      #pragma unroll
      for (int i = 0; i < 2; ++i) cp16ca(stB[i] + bo2, gB[i] + k0);
    }
    cp_commit();
  }

  #pragma unroll
  for (int ni = 0; ni < 2; ++ni) {
    int m0 = bm + wm * 16 + grp;
    int n  = bn + wn * 16 + ni * 8 + tig * 2;
    float bv0 = __ldg(bias + n), bv1 = __ldg(bias + n + 1);
    float x0 = hh[ni][0] + hl[ni][0] + lh[ni][0] + bv0;
    float x1 = hh[ni][1] + hl[ni][1] + lh[ni][1] + bv1;
    float x2 = hh[ni][2] + hl[ni][2] + lh[ni][2] + bv0;
    float x3 = hh[ni][3] + hl[ni][3] + lh[ni][3] + bv1;
    if (SP) { x0 = softplus_f(x0); x1 = softplus_f(x1); x2 = softplus_f(x2); x3 = softplus_f(x3); }
    uint32_t hv, lv;
    split_pack(x0, x1, hv, lv);
    __stcg((uint32_t*)(Chi + m0 * ldc + n), hv);
    __stcg((uint32_t*)(Clo + m0 * ldc + n), lv);
    split_pack(x2, x3, hv, lv);
    __stcg((uint32_t*)(Chi + (m0 + 8) * ldc + n), hv);
    __stcg((uint32_t*)(Clo + (m0 + 8) * ldc + n), lv);
  }
}

// ---------------- GEMM3 (stage S): k_S[16,32] tile, K=512, fused RK epilogue ----------------
template<int S>
__device__ __forceinline__ void gemm3_stage(
    char* sm, float* sred,
    int bm, int bn, const float* __restrict__ b2, double* sd)
{
  const int tid = threadIdx.x;
  const int wid = tid >> 5, lane = tid & 31;
  const int wn = wid & 3, wk = wid >> 2;       // 4 n8-slices x 2 k-halves
  const int grp = lane >> 2, tig = lane & 3;

  float hh[4] = {}, hl[4] = {}, lh[4] = {};

  const bool aselt = tid >= 128;
  const int arow = (tid >> 3) & 15;
  const int aseg = (tid & 7) << 3;
  int br[2], bs[2]; bool bsel[2];
  #pragma unroll
  for (int i = 0; i < 2; ++i) {
    int lin = i * 256 + tid;
    bsel[i] = lin >= 256;
    br[i] = (lin >> 3) & 31;
    bs[i] = (lin & 7) << 3;
  }

  const uint32_t smb = smem_u32(sm);
  const uint32_t stA = smb + (aselt ? OA_LO : 0) + arow * SROWB + aseg * 2;
  uint32_t stB[2];
  #pragma unroll
  for (int i = 0; i < 2; ++i) stB[i] = smb + (bsel[i] ? OB_LO : OB_HI) + br[i] * SROWB + bs[i] * 2;
  const bf16* gA = (aselt ? g_H2lo : g_H2hi) + (bm + arow) * WW + aseg;
  const bf16* gB[2];
  #pragma unroll
  for (int i = 0; i < 2; ++i) gB[i] = (bsel[i] ? g_W2lo : g_W2hi) + (bn + br[i]) * WW + bs[i];

  const uint32_t laA_hi = smb + (lane & 15) * SROWB + ((lane >> 4) << 4);
  const uint32_t laA_lo = laA_hi + OA_LO;
  const uint32_t laB_hi = smb + OB_HI + (wn * 8 + (lane & 7)) * SROWB + (((lane >> 3) & 1) << 4);
  const uint32_t laB_lo = laB_hi + (OB_LO - OB_HI);

  cp16(stA, gA);
  #pragma unroll
  for (int i = 0; i < 2; ++i) cp16ca(stB[i], gB[i]);
  cp_commit();
  cp16(stA + BUFS, gA + 64);
  #pragma unroll
  for (int i = 0; i < 2; ++i) cp16ca(stB[i] + BUFS, gB[i] + 64);
  cp_commit();

  for (int c = 0; c < 8; ++c) {
    cp_wait1();
    __syncthreads();
    const uint32_t bo = (uint32_t)(c % NSTG) * BUFS;
    #pragma unroll
    for (int ks2 = 0; ks2 < 2; ++ks2) {
      const int ks = wk * 2 + ks2;
      uint32_t ah[4], al[4], bh[2], bl[2];
      LDMX4(ah, laA_hi + bo + ks * 32);
      LDMX4(al, laA_lo + bo + ks * 32);
      LDMX2(bh, laB_hi + bo + ks * 32);
      LDMX2(bl, laB_lo + bo + ks * 32);
      mma16816(hh, ah, bh);
      mma16816(hl, ah, bl);
      mma16816(lh, al, bh);
    }
    if (c + 2 < 8) {
      const uint32_t bo2 = (uint32_t)((c + 2) % NSTG) * BUFS;
      int k0 = (c + 2) * 64;
      cp16(stA + bo2, gA + k0);
      #pragma unroll
      for (int i = 0; i < 2; ++i) cp16ca(stB[i] + bo2, gB[i] + k0);
    }
    cp_commit();
  }

  float acc[4];
  #pragma unroll
  for (int j = 0; j < 4; ++j) acc[j] = hh[j] + hl[j] + lh[j];

  const int nl = wn * 8 + tig * 2;
  if (wk == 1) {
    sred[grp * 32 + nl]           = acc[0];
    sred[grp * 32 + nl + 1]       = acc[1];
    sred[(grp + 8) * 32 + nl]     = acc[2];
    sred[(grp + 8) * 32 + nl + 1] = acc[3];
  }
  __syncthreads();
  double ss = 0.0;
  if (wk == 0) {
    acc[0] += sred[grp * 32 + nl];
    acc[1] += sred[grp * 32 + nl + 1];
    acc[2] += sred[(grp + 8) * 32 + nl];
    acc[3] += sred[(grp + 8) * 32 + nl + 1];

    const int n0 = bn + nl;
    const int m0 = bm + grp;
    const float h = g_h;
    const int i0 = m0 * DD + n0;
    const int i1 = (m0 + 8) * DD + n0;
    float bv0 = __ldg(b2 + n0), bv1 = __ldg(b2 + n0 + 1);
    float2 v0 = {acc[0] + bv0, acc[1] + bv1};
    float2 v1 = {acc[2] + bv0, acc[3] + bv1};
    __stcg((float2*)(g_k[S] + i0), v0);
    __stcg((float2*)(g_k[S] + i1), v1);

    const int idxs[2] = {i0, i1};
    const float2 vs[2] = {v0, v1};
    if constexpr (S <= 5) {
      #pragma unroll
      for (int r = 0; r < 2; ++r) {
        int ix = idxs[r];
        float2 y2 = __ldcg((const float2*)(g_y + ix));
        float cS = c_coef[S][S];
        float ax = cS * vs[r].x, ay = cS * vs[r].y;
        #pragma unroll
        for (int j = 0; j < S; ++j) {
          float cj = c_coef[S][j];
          float2 kj = __ldcg((const float2*)(g_k[j] + ix));
          ax = fmaf(cj, kj.x, ax);
          ay = fmaf(cj, kj.y, ay);
        }
        float Xx = fmaf(h, ax, y2.x);
        float Xy = fmaf(h, ay, y2.y);
        if constexpr (S == 5) {
          float2 yn = {Xx, Xy};
          __stcg((float2*)(g_ynew + ix), yn);
        }
        uint32_t hv, lv;
        split_pack(Xx, Xy, hv, lv);
        __stcg((uint32_t*)(g_Xhi + ix), hv);
        __stcg((uint32_t*)(g_Xlo + ix), lv);
      }
    } else {
      #pragma unroll
      for (int r = 0; r < 2; ++r) {
        int ix = idxs[r];
        float2 k0 = __ldcg((const float2*)(g_k[0] + ix));
        float2 k1 = __ldcg((const float2*)(g_k[1] + ix));
        float2 k2 = __ldcg((const float2*)(g_k[2] + ix));
        float2 k3 = __ldcg((const float2*)(g_k[3] + ix));
        float2 k4 = __ldcg((const float2*)(g_k[4] + ix));
        float2 k5 = __ldcg((const float2*)(g_k[5] + ix));
        float2 y2 = __ldcg((const float2*)(g_y + ix));
        float2 yn = __ldcg((const float2*)(g_ynew + ix));
        #pragma unroll
        for (int cc = 0; cc < 2; ++cc) {
          float e = Ec1 * (cc ? k0.y : k0.x);
          e = fmaf(Ec2, cc ? k1.y : k1.x, e);
          e = fmaf(Ec3, cc ? k2.y : k2.x, e);
          e = fmaf(Ec4, cc ? k3.y : k3.x, e);
          e = fmaf(Ec5, cc ? k4.y : k4.x, e);
          e = fmaf(Ec6, cc ? k5.y : k5.x, e);
          e = fmaf(Ec7, cc ? vs[r].y : vs[r].x, e);
          float err = h * e;
          float yv = cc ? y2.y : y2.x, ynv = cc ? yn.y : yn.x;
          float scale = ATOLc + RTOLc * fmaxf(fabsf(yv), fabsf(ynv));
          float rr = err / scale;
          ss += (double)rr * (double)rr;
        }
      }
    }
  }
  if constexpr (S == 6) {
    sd[tid] = ss;
    __syncthreads();
    #pragma unroll
    for (int s2 = 128; s2 > 0; s2 >>= 1) {
      if (tid < s2) sd[tid] += sd[tid + s2];
      __syncthreads();
    }
    if (tid == 0) ((volatile double*)g_errpart)[blockIdx.x] = sd[0];
  }
}

// ---------------- one RK stage (group-local syncs) ----------------
template<int S>
__device__ __forceinline__ void do_stage(int grp_id, int lbid, unsigned& ep,
    const float* b0, const float* b1, const float* b2,
    char* sm, float* sred, double* sd)
{
  const int bm = grp_id << 6;
  const int bn = lbid << 5;
  mma_gemm<true>(g_Xhi, g_Xlo, g_W0hi, g_W0lo, DD, bm, bn, 2, b0, g_H1hi, g_H1lo, WW, sm);
  ggsync(grp_id, ep++);
  mma_gemm<true>(g_H1hi, g_H1lo, g_W1hi, g_W1lo, WW, bm, bn, 8, b1, g_H2hi, g_H2lo, WW, sm);
  ggsync(grp_id, ep++);
  gemm3_stage<S>(sm, sred, bm + ((lbid >> 2) << 4), (lbid & 3) << 5, b2, sd);
  if (S < 6) ggsync(grp_id, ep++);
}

__device__ __forceinline__ void update_phase(int gid2, float* __restrict__ out) {
  float2 v;
  if (g_accept) {
    v = __ldcg((const float2*)(g_ynew + gid2));
    __stcg((float2*)(g_y + gid2), v);
    if (g_hit) *(float2*)(out + g_wrow * NELEM + gid2) = v;
  } else {
    v = __ldcg((const float2*)(g_y + gid2));
  }
  uint32_t hv, lv;
  split_pack(v.x, v.y, hv, lv);
  __stcg((uint32_t*)(g_Xhi + gid2), hv);
  __stcg((uint32_t*)(g_Xlo + gid2), lv);
}

// ---------------- persistent solver ----------------
__global__ void __launch_bounds__(NTHR, 2) solve_kernel(
    const float* __restrict__ ts,
    const float* __restrict__ b0, const float* __restrict__ b1,
    const float* __restrict__ b2, float* __restrict__ out)
{
  extern __shared__ __align__(16) char sm[];
  __shared__ float sred[16 * 32];
  __shared__ double sd[NTHR];

  const int bid = blockIdx.x;
  const int tid = threadIdx.x;
  const int grp_id = bid >> 4;
  const int lbid = bid & 15;
  const int gid2 = (bid * NTHR + tid) * 2;
  unsigned ep = 1;

  for (int step = 0; step < MAX_STEPS; ++step) {
    // Early exit: once done, remaining reference iterations are provable no-ops
    // (accept=false forever, all state frozen). g_done is consistent across CTAs
    // after the previous step's trailing gsync.
    if (g_done) break;

    update_phase(gid2, out);
    ggsync(grp_id, ep++);

    do_stage<0>(grp_id, lbid, ep, b0, b1, b2, sm, sred, sd);
    do_stage<1>(grp_id, lbid, ep, b0, b1, b2, sm, sred, sd);
    do_stage<2>(grp_id, lbid, ep, b0, b1, b2, sm, sred, sd);
    do_stage<3>(grp_id, lbid, ep, b0, b1, b2, sm, sred, sd);
    do_stage<4>(grp_id, lbid, ep, b0, b1, b2, sm, sred, sd);
    do_stage<5>(grp_id, lbid, ep, b0, b1, b2, sm, sred, sd);
    do_stage<6>(grp_id, lbid, ep, b0, b1, b2, sm, sred, sd);

    gsync();

    if (bid == 0) {
      double v = ((volatile double*)g_errpart)[tid];
      sd[tid] = v;
      __syncthreads();
      #pragma unroll
      for (int s2 = 128; s2 > 0; s2 >>= 1) {
        if (tid < s2) sd[tid] += sd[tid + s2];
        __syncthreads();
      }
      if (tid == 0) {
        float enorm = sqrtf((float)(sd[0] / (double)NELEM));
        int done = g_done;
        float h = g_h;
        int accept = (enorm <= 1.0f) && !done;
        float t_new = g_t + h;
        int hit = accept && (t_new >= g_tns - 1e-6f);
        if (accept) g_t = t_new;
        g_accept = accept;
        g_hit = hit;
        g_wrow = g_sic;
        int si = g_si + hit;
        g_si = si;
        float factor;
        if (enorm > 0.f) {
          factor = 0.9f * powf(enorm, -0.2f);
          factor = fminf(fmaxf(factor, 0.2f), 10.f);
        } else factor = 10.f;
        if (!done) g_dt = g_dt * factor;
        int done2 = (si >= TT) ? 1 : 0;
        int sic2 = si < (TT - 1) ? si : (TT - 1);
        float tns2 = __ldg(ts + sic2);
        float h2 = done2 ? 0.f : fmaxf(fminf(g_dt, tns2 - g_t), 0.f);
        g_done = done2; g_sic = sic2; g_tns = tns2; g_h = h2;
      }
    }
    gsync();
  }
  // apply the final step's accept (no-op if last step rejected)
  update_phase(gid2, out);
}

// ---------------- init ----------------
__global__ void init_kernel(const float* __restrict__ ts, const float* __restrict__ y0,
                            const float* __restrict__ W0, const float* __restrict__ W1,
                            const float* __restrict__ W2, float* __restrict__ out)
{
  int idx = blockIdx.x * NTHR + threadIdx.x;
  if (idx < TT * NELEM) out[idx] = (idx < NELEM) ? y0[idx] : 0.f;
  if (idx < NELEM) {
    float v = y0[idx];
    g_y[idx] = v;
    bf16 h = __float2bfloat16(v);
    g_Xhi[idx] = h;
    g_Xlo[idx] = __float2bfloat16(v - __bfloat162float(h));
  }
  if (idx < WW * DD) {
    float w = W0[idx];
    bf16 h = __float2bfloat16(w);
    g_W0hi[idx] = h; g_W0lo[idx] = __float2bfloat16(w - __bfloat162float(h));
    float w2 = W2[idx];
    bf16 h2 = __float2bfloat16(w2);
    g_W2hi[idx] = h2; g_W2lo[idx] = __float2bfloat16(w2 - __bfloat162float(h2));
  }
  if (idx < WW * WW) {
    float w = W1[idx];
    bf16 h = __float2bfloat16(w);
    g_W1hi[idx] = h; g_W1lo[idx] = __float2bfloat16(w - __bfloat162float(h));
  }
  if (idx < NBLK * 32) gg_flag[idx] = 0u;
  if (idx < NBLK) g_errpart[idx] = 0.0;
  if (idx == 0) {
    float t0 = ts[0];
    float dt0 = ts[1] - ts[0];
    g_t = t0;
    g_dt = dt0;
    g_si = 1;
    g_accept = 0;
    g_hit = 0;
    g_wrow = 0;
    g_arrive = 0u;
    g_done = 0;
    g_sic = 1;
    float tns = ts[1];
    g_tns = tns;
    g_h = fmaxf(fminf(dt0, tns - t0), 0.f);
  }
}

extern "C" void kernel_launch(void* const* d_in, const int* in_sizes, int n_in,
                              void* d_out, int out_size) {
  const float* ts = (const float*)d_in[0];
  const float* y0 = (const float*)d_in[1];
  const float* W0 = (const float*)d_in[2];
  const float* b0 = (const float*)d_in[3];
  const float* W1 = (const float*)d_in[4];
  const float* b1 = (const float*)d_in[5];
  const float* W2 = (const float*)d_in[6];
  const float* b2 = (const float*)d_in[7];
  float* out = (float*)d_out;

  cudaFuncSetAttribute(solve_kernel, cudaFuncAttributeMaxDynamicSharedMemorySize, SMEM_DYN);

  init_kernel<<<(TT * NELEM) / NTHR, NTHR>>>(ts, y0, W0, W1, W2, out);
  solve_kernel<<<NBLK, NTHR, SMEM_DYN>>>(ts, b0, b1, b2, out);
}

// round 15
// speedup vs baseline: 12.9793x; 1.0559x over previous
#include <cuda_runtime.h>
#include <cuda_bf16.h>
#include <math.h>
#include <stdint.h>

typedef __nv_bfloat16 bf16;

#define BB 1024
#define DD 128
#define WW 512
#define TT 8
#define NELEM (BB*DD)
#define HELEM (BB*WW)
#define MAX_STEPS 48
#define NBLK 256
#define NTHR 256
#define GCTA 16
#define RTOLc 1e-3f
#define ATOLc 1e-6f

#define SROWB 144            // smem row stride bytes
#define OA_LO  9216          // 64*144
#define OB_HI 18432
#define OB_LO 23040
#define BUFS  27648          // GEMM1/2 buffer set
#define NSTG 3
#define SMEM_DYN (NSTG*BUFS) // 82944

// GEMM3 compact sets: A 16 rows hi+lo, B 32 rows hi+lo
#define G3SET 13824
#define G3_ALO 2304
#define G3_BHI 4608
#define G3_BLO 9216

#define A21f 0.161f
#define A31f (-0.008480655492356989f)
#define A32f 0.335480655492357f
#define A41f 2.8971530571054935f
#define A42f (-6.359448489975075f)
#define A43f 4.3622954328695815f
#define A51f 5.325864828439257f
#define A52f (-11.748883564062828f)
#define A53f 7.4955393428898365f
#define A54f (-0.09249506636175525f)
#define A61f 5.86145544294642f
#define A62f (-12.92096931784711f)
#define A63f 8.159367898576159f
#define A64f (-0.071584973281401f)
#define A65f (-0.028269050394068383f)
#define Bc1 0.09646076681806523f
#define Bc2 0.01f
#define Bc3 0.4798896504144996f
#define Bc4 1.379008574103742f
#define Bc5 (-3.290069515436081f)
#define Bc6 2.324710524099774f
#define Ec1 (-0.00178001105222577714f)
#define Ec2 (-0.0008164344596567469f)
#define Ec3 0.007880878010261995f
#define Ec4 (-0.1447110071732629f)
#define Ec5 0.5823571654525552f
#define Ec6 (-0.45808210592918697f)
#define Ec7 0.015151515151515152f

// ---------------- device state ----------------
__device__ __align__(16) float g_y[NELEM], g_ynew[NELEM], g_k[7][NELEM];
__device__ __align__(16) bf16 g_Xhi[NELEM], g_Xlo[NELEM];
__device__ __align__(16) bf16 g_H1hi[HELEM], g_H1lo[HELEM];
__device__ __align__(16) bf16 g_H2hi[HELEM], g_H2lo[HELEM];
__device__ __align__(16) bf16 g_W0hi[WW*DD], g_W0lo[WW*DD];
__device__ __align__(16) bf16 g_W1hi[WW*WW], g_W1lo[WW*WW];
__device__ __align__(16) bf16 g_W2hi[DD*WW], g_W2lo[DD*WW];
__device__ double g_errpart[NBLK];
__device__ unsigned g_arrive;
__device__ volatile unsigned gg_flag[NBLK * 32];

__constant__ float c_coef[6][6] = {
  {A21f,0,0,0,0,0},
  {A31f,A32f,0,0,0,0},
  {A41f,A42f,A43f,0,0,0},
  {A51f,A52f,A53f,A54f,0,0},
  {A61f,A62f,A63f,A64f,A65f,0},
  {Bc1,Bc2,Bc3,Bc4,Bc5,Bc6},
};

// ---------------- helpers ----------------
__device__ __forceinline__ uint32_t smem_u32(const void* p) {
  uint32_t a;
  asm("{ .reg .u64 t; cvta.to.shared.u64 t, %1; cvt.u32.u64 %0, t; }" : "=r"(a) : "l"(p));
  return a;
}
__device__ __forceinline__ void cp16(uint32_t dst, const void* src) {
  asm volatile("cp.async.cg.shared.global [%0], [%1], 16;" :: "r"(dst), "l"(src) : "memory");
}
__device__ __forceinline__ void cp16ca(uint32_t dst, const void* src) {
  asm volatile("cp.async.ca.shared.global [%0], [%1], 16;" :: "r"(dst), "l"(src) : "memory");
}
__device__ __forceinline__ void cp_commit() { asm volatile("cp.async.commit_group;" ::: "memory"); }
__device__ __forceinline__ void cp_wait1() { asm volatile("cp.async.wait_group 1;" ::: "memory"); }
__device__ __forceinline__ void cp_wait0() { asm volatile("cp.async.wait_group 0;" ::: "memory"); }

#define LDMX4(r, addr) \
  asm volatile("ldmatrix.sync.aligned.m8n8.x4.shared.b16 {%0,%1,%2,%3}, [%4];" \
    : "=r"((r)[0]), "=r"((r)[1]), "=r"((r)[2]), "=r"((r)[3]) : "r"(addr))
#define LDMX2(r, addr) \
  asm volatile("ldmatrix.sync.aligned.m8n8.x2.shared.b16 {%0,%1}, [%2];" \
    : "=r"((r)[0]), "=r"((r)[1]) : "r"(addr))

__device__ __forceinline__ void mma16816(float* c, const uint32_t* a, const uint32_t* b) {
  asm volatile(
    "mma.sync.aligned.m16n8k16.row.col.f32.bf16.bf16.f32 "
    "{%0,%1,%2,%3}, {%4,%5,%6,%7}, {%8,%9}, {%0,%1,%2,%3};"
    : "+f"(c[0]), "+f"(c[1]), "+f"(c[2]), "+f"(c[3])
    : "r"(a[0]), "r"(a[1]), "r"(a[2]), "r"(a[3]), "r"(b[0]), "r"(b[1]));
}

// ---------------- barriers ----------------
__device__ __forceinline__ void gsync() {
  __syncthreads();
  if (threadIdx.x == 0) {
    __threadfence();
    unsigned t = atomicAdd(&g_arrive, 1u) + 1u;
    unsigned target = ((t + NBLK - 1u) / NBLK) * NBLK;
    while (*(volatile unsigned*)&g_arrive < target) {}
    __threadfence();
  }
  __syncthreads();
}
__device__ __forceinline__ void ggsync(int grp, unsigned ep) {
  __syncthreads();
  if (threadIdx.x == 0) {
    __threadfence();
    gg_flag[blockIdx.x * 32] = ep;
  }
  if (threadIdx.x < GCTA) {
    const volatile unsigned* f = &gg_flag[(grp * GCTA + threadIdx.x) * 32];
    while (*f < ep) {}
  }
  __syncthreads();
}

// -------- MUFU-free softplus (abs err ~2e-6) --------
__device__ __forceinline__ float softplus_f(float x) {
  float t = fabsf(x);
  float s = fminf(t * 1.4426950408889634f, 100.f);
  float n = floorf(s);
  float r = n - s;
  float p = 1.3215487e-6f;
  p = fmaf(p, r, 1.5252734e-5f);
  p = fmaf(p, r, 1.5403530e-4f);
  p = fmaf(p, r, 1.3333558e-3f);
  p = fmaf(p, r, 9.6181291e-3f);
  p = fmaf(p, r, 5.5504109e-2f);
  p = fmaf(p, r, 2.4022651e-1f);
  p = fmaf(p, r, 6.9314718e-1f);
  p = fmaf(p, r, 1.0f);
  float u = p * __uint_as_float((uint32_t)(127 - (int)n) << 23);
  float d = 2.f + u;
  float w = fmaf(-0.1635f, u, 0.4915f);
  w = w * fmaf(-d, w, 2.f);
  w = w * fmaf(-d, w, 2.f);
  float v = u * w;
  float v2 = v * v;
  float g = 0.09090909f;
  g = fmaf(g, v2, 0.11111111f);
  g = fmaf(g, v2, 0.14285714f);
  g = fmaf(g, v2, 0.2f);
  g = fmaf(g, v2, 0.33333333f);
  g = fmaf(g, v2, 1.0f);
  return fmaxf(x, 0.f) + 2.f * v * g;
}

__device__ __forceinline__ void split_pack(float x0, float x1, uint32_t& hv, uint32_t& lv) {
  bf16 h0 = __float2bfloat16(x0), h1 = __float2bfloat16(x1);
  bf16 l0 = __float2bfloat16(x0 - __bfloat162float(h0));
  bf16 l1 = __float2bfloat16(x1 - __bfloat162float(h1));
  hv = (uint32_t)__bfloat16_as_ushort(h0) | ((uint32_t)__bfloat16_as_ushort(h1) << 16);
  lv = (uint32_t)__bfloat16_as_ushort(l0) | ((uint32_t)__bfloat16_as_ushort(l1) << 16);
}

// ---------------- GEMM1/2: C[64,32] = act(A[64,K] @ B[32,K]^T + bias) -> bf16 hi/lo ----------------
template<int NC, bool SP>
__device__ __forceinline__ void mma_gemm(
    const bf16* __restrict__ Ahi, const bf16* __restrict__ Alo,
    const bf16* __restrict__ Bhi, const bf16* __restrict__ Blo,
    int ldk, int bm, int bn,
    const float* __restrict__ bias,
    bf16* __restrict__ Chi, bf16* __restrict__ Clo, int ldc,
    char* sm)
{
  const int tid = threadIdx.x;
  const int wid = tid >> 5;
  const int lane = tid & 31;
  const int grp = lane >> 2, tig = lane & 3;
  const int wm = wid >> 1, wn = wid & 1;

  float hh[2][4] = {}, hl[2][4] = {}, lh[2][4] = {};

  int ar[4], as[4]; bool asel[4];
  #pragma unroll
  for (int i = 0; i < 4; ++i) {
    int lin = i * 256 + tid;
    asel[i] = lin >= 512;
    ar[i] = (lin >> 3) & 63;
    as[i] = (lin & 7) << 3;
  }
  int br[2], bs[2]; bool bsel[2];
  #pragma unroll
  for (int i = 0; i < 2; ++i) {
    int lin = i * 256 + tid;
    bsel[i] = lin >= 256;
    br[i] = (lin >> 3) & 31;
    bs[i] = (lin & 7) << 3;
  }
  const uint32_t smb = smem_u32(sm);
  uint32_t stA[4], stB[2];
  #pragma unroll
  for (int i = 0; i < 4; ++i) stA[i] = smb + (asel[i] ? OA_LO : 0) + ar[i] * SROWB + as[i] * 2;
  #pragma unroll
  for (int i = 0; i < 2; ++i) stB[i] = smb + (bsel[i] ? OB_LO : OB_HI) + br[i] * SROWB + bs[i] * 2;
  const bf16* gA[4]; const bf16* gB[2];
  #pragma unroll
  for (int i = 0; i < 4; ++i) gA[i] = (asel[i] ? Alo : Ahi) + (bm + ar[i]) * ldk + as[i];
  #pragma unroll
  for (int i = 0; i < 2; ++i) gB[i] = (bsel[i] ? Blo : Bhi) + (bn + br[i]) * ldk + bs[i];

  const uint32_t laA_hi = smb + (wm * 16 + (lane & 15)) * SROWB + ((lane >> 4) << 4);
  const uint32_t laA_lo = laA_hi + OA_LO;
  const uint32_t laB4_hi = smb + OB_HI + (wn * 16 + ((lane >> 4) << 3) + (lane & 7)) * SROWB
                           + (((lane >> 3) & 1) << 4);
  const uint32_t laB4_lo = laB4_hi + (OB_LO - OB_HI);

  #pragma unroll
  for (int i = 0; i < 4; ++i) cp16(stA[i], gA[i]);
  #pragma unroll
  for (int i = 0; i < 2; ++i) cp16ca(stB[i], gB[i]);
  cp_commit();
  if (NC > 1) {
    #pragma unroll
    for (int i = 0; i < 4; ++i) cp16(stA[i] + BUFS, gA[i] + 64);
    #pragma unroll
    for (int i = 0; i < 2; ++i) cp16ca(stB[i] + BUFS, gB[i] + 64);
    cp_commit();
  }

  if (NC == 2) {
    // both chunks ready: single wait + single sync, process both
    cp_wait0();
    __syncthreads();
    #pragma unroll
    for (int c = 0; c < 2; ++c) {
      const uint32_t bo = c ? BUFS : 0;
      #pragma unroll
      for (int ks = 0; ks < 4; ++ks) {
        uint32_t ah[4], al[4], b4h[4], b4l[4];
        LDMX4(ah, laA_hi + bo + ks * 32);
        LDMX4(al, laA_lo + bo + ks * 32);
        LDMX4(b4h, laB4_hi + bo + ks * 32);
        LDMX4(b4l, laB4_lo + bo + ks * 32);
        mma16816(hh[0], ah, b4h);
        mma16816(hl[0], ah, b4l);
        mma16816(lh[0], al, b4h);
        mma16816(hh[1], ah, b4h + 2);
        mma16816(hl[1], ah, b4l + 2);
        mma16816(lh[1], al, b4h + 2);
      }
    }
  } else {
    for (int c = 0; c < NC; ++c) {
      cp_wait1();
      __syncthreads();
      const uint32_t bo = (uint32_t)(c % NSTG) * BUFS;
      #pragma unroll
      for (int ks = 0; ks < 4; ++ks) {
        uint32_t ah[4], al[4], b4h[4], b4l[4];
        LDMX4(ah, laA_hi + bo + ks * 32);
        LDMX4(al, laA_lo + bo + ks * 32);
        LDMX4(b4h, laB4_hi + bo + ks * 32);
        LDMX4(b4l, laB4_lo + bo + ks * 32);
        mma16816(hh[0], ah, b4h);
        mma16816(hl[0], ah, b4l);
        mma16816(lh[0], al, b4h);
        mma16816(hh[1], ah, b4h + 2);
        mma16816(hl[1], ah, b4l + 2);
        mma16816(lh[1], al, b4h + 2);
      }
      if (c + 2 < NC) {
        const uint32_t bo2 = (uint32_t)((c + 2) % NSTG) * BUFS;
        int k0 = (c + 2) * 64;
        #pragma unroll
        for (int i = 0; i < 4; ++i) cp16(stA[i] + bo2, gA[i] + k0);
        #pragma unroll
        for (int i = 0; i < 2; ++i) cp16ca(stB[i] + bo2, gB[i] + k0);
      }
      cp_commit();
    }
  }

  #pragma unroll
  for (int ni = 0; ni < 2; ++ni) {
    int m0 = bm + wm * 16 + grp;
    int n  = bn + wn * 16 + ni * 8 + tig * 2;
    float bv0 = __ldg(bias + n), bv1 = __ldg(bias + n + 1);
    float x0 = hh[ni][0] + hl[ni][0] + lh[ni][0] + bv0;
    float x1 = hh[ni][1] + hl[ni][1] + lh[ni][1] + bv1;
    float x2 = hh[ni][2] + hl[ni][2] + lh[ni][2] + bv0;
    float x3 = hh[ni][3] + hl[ni][3] + lh[ni][3] + bv1;
    if (SP) { x0 = softplus_f(x0); x1 = softplus_f(x1); x2 = softplus_f(x2); x3 = softplus_f(x3); }
    uint32_t hv, lv;
    split_pack(x0, x1, hv, lv);
    __stcg((uint32_t*)(Chi + m0 * ldc + n), hv);
    __stcg((uint32_t*)(Clo + m0 * ldc + n), lv);
    split_pack(x2, x3, hv, lv);
    __stcg((uint32_t*)(Chi + (m0 + 8) * ldc + n), hv);
    __stcg((uint32_t*)(Clo + (m0 + 8) * ldc + n), lv);
  }
}

// ---------------- GEMM3 (stage S): k_S[16,32] tile, K=512, 6-set pipeline, fused epilogue ----------------
template<int S>
__device__ __forceinline__ void gemm3_stage(
    char* sm, float* sred,
    int bm, int bn, const float* __restrict__ b2, double* sd, float h)
{
  const int tid = threadIdx.x;
  const int wid = tid >> 5, lane = tid & 31;
  const int wn = wid & 3, wk = wid >> 2;       // 4 n8-slices x 2 k-halves
  const int grp = lane >> 2, tig = lane & 3;

  float hh[4] = {}, hl[4] = {}, lh[4] = {};

  const bool aselt = tid >= 128;
  const int arow = (tid >> 3) & 15;
  const int aseg = (tid & 7) << 3;
  int br[2], bs[2]; bool bsel[2];
  #pragma unroll
  for (int i = 0; i < 2; ++i) {
    int lin = i * 256 + tid;
    bsel[i] = lin >= 256;
    br[i] = (lin >> 3) & 31;
    bs[i] = (lin & 7) << 3;
  }

  const uint32_t smb = smem_u32(sm);
  const uint32_t stAo = (aselt ? G3_ALO : 0) + arow * SROWB + aseg * 2;
  uint32_t stBo[2];
  #pragma unroll
  for (int i = 0; i < 2; ++i) stBo[i] = (bsel[i] ? G3_BLO : G3_BHI) + br[i] * SROWB + bs[i] * 2;
  const bf16* gA = (aselt ? g_H2lo : g_H2hi) + (bm + arow) * WW + aseg;
  const bf16* gB[2];
  #pragma unroll
  for (int i = 0; i < 2; ++i) gB[i] = (bsel[i] ? g_W2lo : g_W2hi) + (bn + br[i]) * WW + bs[i];

  const uint32_t laAo_hi = (lane & 15) * SROWB + ((lane >> 4) << 4);
  const uint32_t laAo_lo = laAo_hi + G3_ALO;
  const uint32_t laBo_hi = G3_BHI + (wn * 8 + (lane & 7)) * SROWB + (((lane >> 3) & 1) << 4);
  const uint32_t laBo_lo = laBo_hi + (G3_BLO - G3_BHI);

  // prologue: chunks 0,1 -> sets 0,1 (group); chunks 2,3 -> sets 2,3 (group)
  #pragma unroll
  for (int p = 0; p < 2; ++p) {
    #pragma unroll
    for (int q = 0; q < 2; ++q) {
      int ck = p * 2 + q;
      uint32_t setb = smb + (uint32_t)ck * G3SET;
      cp16(setb + stAo, gA + ck * 64);
      cp16ca(setb + stBo[0], gB[0] + ck * 64);
      cp16ca(setb + stBo[1], gB[1] + ck * 64);
    }
    cp_commit();
  }

  for (int i = 0; i < 4; ++i) {
    cp_wait1();
    __syncthreads();
    #pragma unroll
    for (int cc = 0; cc < 2; ++cc) {
      const int chunk = 2 * i + cc;
      const uint32_t setb = smb + (uint32_t)(chunk % 6) * G3SET;
      #pragma unroll
      for (int ks2 = 0; ks2 < 2; ++ks2) {
        const int ks = wk * 2 + ks2;
        uint32_t ah[4], al[4], bh[2], bl[2];
        LDMX4(ah, setb + laAo_hi + ks * 32);
        LDMX4(al, setb + laAo_lo + ks * 32);
        LDMX2(bh, setb + laBo_hi + ks * 32);
        LDMX2(bl, setb + laBo_lo + ks * 32);
        mma16816(hh, ah, bh);
        mma16816(hl, ah, bl);
        mma16816(lh, al, bh);
      }
    }
    const int pc = 2 * i + 4;
    if (pc < 8) {
      #pragma unroll
      for (int q = 0; q < 2; ++q) {
        int ck = pc + q;
        uint32_t setb = smb + (uint32_t)(ck % 6) * G3SET;
        cp16(setb + stAo, gA + ck * 64);
        cp16ca(setb + stBo[0], gB[0] + ck * 64);
        cp16ca(setb + stBo[1], gB[1] + ck * 64);
      }
    }
    cp_commit();
  }

  float acc[4];
  #pragma unroll
  for (int j = 0; j < 4; ++j) acc[j] = hh[j] + hl[j] + lh[j];

  const int nl = wn * 8 + tig * 2;
  if (wk == 1) {
    sred[grp * 32 + nl]           = acc[0];
    sred[grp * 32 + nl + 1]       = acc[1];
    sred[(grp + 8) * 32 + nl]     = acc[2];
    sred[(grp + 8) * 32 + nl + 1] = acc[3];
  }
  __syncthreads();
  double ss = 0.0;
  if (wk == 0) {
    acc[0] += sred[grp * 32 + nl];
    acc[1] += sred[grp * 32 + nl + 1];
    acc[2] += sred[(grp + 8) * 32 + nl];
    acc[3] += sred[(grp + 8) * 32 + nl + 1];

    const int n0 = bn + nl;
    const int m0 = bm + grp;
    const int i0 = m0 * DD + n0;
    const int i1 = (m0 + 8) * DD + n0;
    float bv0 = __ldg(b2 + n0), bv1 = __ldg(b2 + n0 + 1);
    float2 v0 = {acc[0] + bv0, acc[1] + bv1};
    float2 v1 = {acc[2] + bv0, acc[3] + bv1};
    __stcg((float2*)(g_k[S] + i0), v0);
    __stcg((float2*)(g_k[S] + i1), v1);

    const int idxs[2] = {i0, i1};
    const float2 vs[2] = {v0, v1};
    if constexpr (S <= 5) {
      #pragma unroll
      for (int r = 0; r < 2; ++r) {
        int ix = idxs[r];
        float2 y2 = __ldcg((const float2*)(g_y + ix));
        float cS = c_coef[S][S];
        float ax = cS * vs[r].x, ay = cS * vs[r].y;
        #pragma unroll
        for (int j = 0; j < S; ++j) {
          float cj = c_coef[S][j];
          float2 kj = __ldcg((const float2*)(g_k[j] + ix));
          ax = fmaf(cj, kj.x, ax);
          ay = fmaf(cj, kj.y, ay);
        }
        float Xx = fmaf(h, ax, y2.x);
        float Xy = fmaf(h, ay, y2.y);
        if constexpr (S == 5) {
          float2 yn = {Xx, Xy};
          __stcg((float2*)(g_ynew + ix), yn);
        }
        uint32_t hv, lv;
        split_pack(Xx, Xy, hv, lv);
        __stcg((uint32_t*)(g_Xhi + ix), hv);
        __stcg((uint32_t*)(g_Xlo + ix), lv);
      }
    } else {
      #pragma unroll
      for (int r = 0; r < 2; ++r) {
        int ix = idxs[r];
        float2 k0 = __ldcg((const float2*)(g_k[0] + ix));
        float2 k1 = __ldcg((const float2*)(g_k[1] + ix));
        float2 k2 = __ldcg((const float2*)(g_k[2] + ix));
        float2 k3 = __ldcg((const float2*)(g_k[3] + ix));
        float2 k4 = __ldcg((const float2*)(g_k[4] + ix));
        float2 k5 = __ldcg((const float2*)(g_k[5] + ix));
        float2 y2 = __ldcg((const float2*)(g_y + ix));
        float2 yn = __ldcg((const float2*)(g_ynew + ix));
        #pragma unroll
        for (int cc = 0; cc < 2; ++cc) {
          float e = Ec1 * (cc ? k0.y : k0.x);
          e = fmaf(Ec2, cc ? k1.y : k1.x, e);
          e = fmaf(Ec3, cc ? k2.y : k2.x, e);
          e = fmaf(Ec4, cc ? k3.y : k3.x, e);
          e = fmaf(Ec5, cc ? k4.y : k4.x, e);
          e = fmaf(Ec6, cc ? k5.y : k5.x, e);
          e = fmaf(Ec7, cc ? vs[r].y : vs[r].x, e);
          float err = h * e;
          float yv = cc ? y2.y : y2.x, ynv = cc ? yn.y : yn.x;
          float scale = ATOLc + RTOLc * fmaxf(fabsf(yv), fabsf(ynv));
          float rr = err / scale;
          ss += (double)rr * (double)rr;
        }
      }
    }
  }
  if constexpr (S == 6) {
    sd[tid] = ss;
    __syncthreads();
    #pragma unroll
    for (int s2 = 128; s2 > 0; s2 >>= 1) {
      if (tid < s2) sd[tid] += sd[tid + s2];
      __syncthreads();
    }
    if (tid == 0) *(volatile double*)&g_errpart[blockIdx.x] = sd[0];
  }
}

// ---------------- one RK stage (group-local syncs) ----------------
template<int S>
__device__ __forceinline__ void do_stage(int grp_id, int lbid, unsigned& ep, float h,
    const float* b0, const float* b1, const float* b2,
    char* sm, float* sred, double* sd)
{
  const int bm = grp_id << 6;
  const int bn = lbid << 5;
  mma_gemm<2, true>(g_Xhi, g_Xlo, g_W0hi, g_W0lo, DD, bm, bn, b0, g_H1hi, g_H1lo, WW, sm);
  ggsync(grp_id, ep++);
  mma_gemm<8, true>(g_H1hi, g_H1lo, g_W1hi, g_W1lo, WW, bm, bn, b1, g_H2hi, g_H2lo, WW, sm);
  ggsync(grp_id, ep++);
  gemm3_stage<S>(sm, sred, bm + ((lbid >> 2) << 4), (lbid & 3) << 5, b2, sd, h);
  if (S < 6) ggsync(grp_id, ep++);
}

__device__ __forceinline__ void update_phase(int gid2, float* __restrict__ out,
                                             int accept, int hit, int wrow) {
  float2 v;
  if (accept) {
    v = __ldcg((const float2*)(g_ynew + gid2));
    __stcg((float2*)(g_y + gid2), v);
    if (hit) *(float2*)(out + wrow * NELEM + gid2) = v;
  } else {
    v = __ldcg((const float2*)(g_y + gid2));
  }
  uint32_t hv, lv;
  split_pack(v.x, v.y, hv, lv);
  __stcg((uint32_t*)(g_Xhi + gid2), hv);
  __stcg((uint32_t*)(g_Xlo + gid2), lv);
}

// ---------------- persistent solver ----------------
__global__ void __launch_bounds__(NTHR, 2) solve_kernel(
    const float* __restrict__ ts,
    const float* __restrict__ b0, const float* __restrict__ b1,
    const float* __restrict__ b2, float* __restrict__ out)
{
  extern __shared__ __align__(16) char sm[];
  __shared__ float sred[16 * 32];
  __shared__ double sd[NTHR];

  const int bid = blockIdx.x;
  const int tid = threadIdx.x;
  const int grp_id = bid >> 4;
  const int lbid = bid & 15;
  const int gid2 = (bid * NTHR + tid) * 2;
  unsigned ep = 1;

  // replicated controller state (bit-identical in every CTA/thread)
  float t = __ldg(ts + 0);
  float dt = __ldg(ts + 1) - t;
  int si = 1, done = 0, accept = 0, hit = 0, wrow = 0, sic = 1;
  float tns = __ldg(ts + 1);
  float h = fmaxf(fminf(dt, tns - t), 0.f);

  for (int step = 0; step < MAX_STEPS; ++step) {
    if (done) break;

    update_phase(gid2, out, accept, hit, wrow);
    ggsync(grp_id, ep++);

    do_stage<0>(grp_id, lbid, ep, h, b0, b1, b2, sm, sred, sd);
    do_stage<1>(grp_id, lbid, ep, h, b0, b1, b2, sm, sred, sd);
    do_stage<2>(grp_id, lbid, ep, h, b0, b1, b2, sm, sred, sd);
    do_stage<3>(grp_id, lbid, ep, h, b0, b1, b2, sm, sred, sd);
    do_stage<4>(grp_id, lbid, ep, h, b0, b1, b2, sm, sred, sd);
    do_stage<5>(grp_id, lbid, ep, h, b0, b1, b2, sm, sred, sd);
    do_stage<6>(grp_id, lbid, ep, h, b0, b1, b2, sm, sred, sd);

    gsync();   // all err partials visible to every CTA

    // every CTA reduces all partials locally (identical order -> identical result)
    sd[tid] = *(volatile double*)&g_errpart[tid];
    __syncthreads();
    #pragma unroll
    for (int s2 = 128; s2 > 0; s2 >>= 1) {
      if (tid < s2) sd[tid] += sd[tid + s2];
      __syncthreads();
    }
    const double total = sd[0];
    __syncthreads();

    float enorm = sqrtf((float)(total / (double)NELEM));
    accept = (enorm <= 1.0f) && !done;
    float t_new = t + h;
    hit = accept && (t_new >= tns - 1e-6f);
    if (accept) t = t_new;
    wrow = sic;
    si += hit;
    float factor;
    if (enorm > 0.f) {
      factor = 0.9f * powf(enorm, -0.2f);
      factor = fminf(fmaxf(factor, 0.2f), 10.f);
    } else factor = 10.f;
    if (!done) dt = dt * factor;
    done = (si >= TT) ? 1 : 0;
    sic = si < (TT - 1) ? si : (TT - 1);
    tns = __ldg(ts + sic);
    h = done ? 0.f : fmaxf(fminf(dt, tns - t), 0.f);
  }
  // apply the final step's accept (no-op if last step rejected)
  update_phase(gid2, out, accept, hit, wrow);
}

// ---------------- init ----------------
__global__ void init_kernel(const float* __restrict__ ts, const float* __restrict__ y0,
                            const float* __restrict__ W0, const float* __restrict__ W1,
                            const float* __restrict__ W2, float* __restrict__ out)
{
  int idx = blockIdx.x * NTHR + threadIdx.x;
  if (idx < TT * NELEM) out[idx] = (idx < NELEM) ? y0[idx] : 0.f;
  if (idx < NELEM) {
    float v = y0[idx];
    g_y[idx] = v;
    bf16 h = __float2bfloat16(v);
    g_Xhi[idx] = h;
    g_Xlo[idx] = __float2bfloat16(v - __bfloat162float(h));
  }
  if (idx < WW * DD) {
    float w = W0[idx];
    bf16 h = __float2bfloat16(w);
    g_W0hi[idx] = h; g_W0lo[idx] = __float2bfloat16(w - __bfloat162float(h));
    float w2 = W2[idx];
    bf16 h2 = __float2bfloat16(w2);
    g_W2hi[idx] = h2; g_W2lo[idx] = __float2bfloat16(w2 - __bfloat162float(h2));
  }
  if (idx < WW * WW) {
    float w = W1[idx];
    bf16 h = __float2bfloat16(w);
    g_W1hi[idx] = h; g_W1lo[idx] = __float2bfloat16(w - __bfloat162float(h));
  }
  if (idx < NBLK * 32) gg_flag[idx] = 0u;
  if (idx < NBLK) g_errpart[idx] = 0.0;
  if (idx == 0) g_arrive = 0u;
}

extern "C" void kernel_launch(void* const* d_in, const int* in_sizes, int n_in,
                              void* d_out, int out_size) {
  const float* ts = (const float*)d_in[0];
  const float* y0 = (const float*)d_in[1];
  const float* W0 = (const float*)d_in[2];
  const float* b0 = (const float*)d_in[3];
  const float* W1 = (const float*)d_in[4];
  const float* b1 = (const float*)d_in[5];
  const float* W2 = (const float*)d_in[6];
  const float* b2 = (const float*)d_in[7];
  float* out = (float*)d_out;

  cudaFuncSetAttribute(solve_kernel, cudaFuncAttributeMaxDynamicSharedMemorySize, SMEM_DYN);

  init_kernel<<<(TT * NELEM) / NTHR, NTHR>>>(ts, y0, W0, W1, W2, out);
  solve_kernel<<<NBLK, NTHR, SMEM_DYN>>>(ts, b0, b1, b2, out);
}

// round 16
// speedup vs baseline: 14.6736x; 1.1305x over previous
#include <cuda_runtime.h>
#include <cuda_bf16.h>
#include <math.h>
#include <stdint.h>

typedef __nv_bfloat16 bf16;

#define BB 1024
#define DD 128
#define WW 512
#define TT 8
#define NELEM (BB*DD)
#define HELEM (BB*WW)
#define MAX_STEPS 48
#define NBLK 256
#define NTHR 256
#define GCTA 16
#define RTOLc 1e-3f
#define ATOLc 1e-6f

#define SROWB 144
#define OA_LO  9216
#define OB_HI 18432
#define OB_LO 23040
#define BUFS  27648
#define NSTG 3
#define SMEM_DYN (NSTG*BUFS)

#define G3SET 13824
#define G3_ALO 2304
#define G3_BHI 4608
#define G3_BLO 9216

#define A21f 0.161f
#define A31f (-0.008480655492356989f)
#define A32f 0.335480655492357f
#define A41f 2.8971530571054935f
#define A42f (-6.359448489975075f)
#define A43f 4.3622954328695815f
#define A51f 5.325864828439257f
#define A52f (-11.748883564062828f)
#define A53f 7.4955393428898365f
#define A54f (-0.09249506636175525f)
#define A61f 5.86145544294642f
#define A62f (-12.92096931784711f)
#define A63f 8.159367898576159f
#define A64f (-0.071584973281401f)
#define A65f (-0.028269050394068383f)
#define Bc1 0.09646076681806523f
#define Bc2 0.01f
#define Bc3 0.4798896504144996f
#define Bc4 1.379008574103742f
#define Bc5 (-3.290069515436081f)
#define Bc6 2.324710524099774f
#define Ec1 (-0.00178001105222577714f)
#define Ec2 (-0.0008164344596567469f)
#define Ec3 0.007880878010261995f
#define Ec4 (-0.1447110071732629f)
#define Ec5 0.5823571654525552f
#define Ec6 (-0.45808210592918697f)
#define Ec7 0.015151515151515152f

// ---------------- device state ----------------
__device__ __align__(16) float g_yb[2][NELEM], g_k[7][NELEM];
__device__ __align__(16) bf16 g_Xhi[NELEM], g_Xlo[NELEM];
__device__ __align__(16) bf16 g_H1hi[HELEM], g_H1lo[HELEM];
__device__ __align__(16) bf16 g_H2hi[HELEM], g_H2lo[HELEM];
__device__ __align__(16) bf16 g_W0hi[WW*DD], g_W0lo[WW*DD];
__device__ __align__(16) bf16 g_W1hi[WW*WW], g_W1lo[WW*WW];
__device__ __align__(16) bf16 g_W2hi[DD*WW], g_W2lo[DD*WW];
__device__ double g_errpart[NBLK];
__device__ unsigned g_arrive;
__device__ volatile unsigned gg_flag[NBLK * 32];

__constant__ float c_coef[6][6] = {
  {A21f,0,0,0,0,0},
  {A31f,A32f,0,0,0,0},
  {A41f,A42f,A43f,0,0,0},
  {A51f,A52f,A53f,A54f,0,0},
  {A61f,A62f,A63f,A64f,A65f,0},
  {Bc1,Bc2,Bc3,Bc4,Bc5,Bc6},
};

// ---------------- helpers ----------------
__device__ __forceinline__ uint32_t smem_u32(const void* p) {
  uint32_t a;
  asm("{ .reg .u64 t; cvta.to.shared.u64 t, %1; cvt.u32.u64 %0, t; }" : "=r"(a) : "l"(p));
  return a;
}
__device__ __forceinline__ void cp16(uint32_t dst, const void* src) {
  asm volatile("cp.async.cg.shared.global [%0], [%1], 16;" :: "r"(dst), "l"(src) : "memory");
}
__device__ __forceinline__ void cp16ca(uint32_t dst, const void* src) {
  asm volatile("cp.async.ca.shared.global [%0], [%1], 16;" :: "r"(dst), "l"(src) : "memory");
}
__device__ __forceinline__ void cp_commit() { asm volatile("cp.async.commit_group;" ::: "memory"); }
__device__ __forceinline__ void cp_wait1() { asm volatile("cp.async.wait_group 1;" ::: "memory"); }
__device__ __forceinline__ void cp_wait0() { asm volatile("cp.async.wait_group 0;" ::: "memory"); }

#define LDMX4(r, addr) \
  asm volatile("ldmatrix.sync.aligned.m8n8.x4.shared.b16 {%0,%1,%2,%3}, [%4];" \
    : "=r"((r)[0]), "=r"((r)[1]), "=r"((r)[2]), "=r"((r)[3]) : "r"(addr))
#define LDMX2(r, addr) \
  asm volatile("ldmatrix.sync.aligned.m8n8.x2.shared.b16 {%0,%1}, [%2];" \
    : "=r"((r)[0]), "=r"((r)[1]) : "r"(addr))

__device__ __forceinline__ void mma16816(float* c, const uint32_t* a, const uint32_t* b) {
  asm volatile(
    "mma.sync.aligned.m16n8k16.row.col.f32.bf16.bf16.f32 "
    "{%0,%1,%2,%3}, {%4,%5,%6,%7}, {%8,%9}, {%0,%1,%2,%3};"
    : "+f"(c[0]), "+f"(c[1]), "+f"(c[2]), "+f"(c[3])
    : "r"(a[0]), "r"(a[1]), "r"(a[2]), "r"(a[3]), "r"(b[0]), "r"(b[1]));
}

// ---------------- barriers ----------------
__device__ __forceinline__ void gsync() {
  __syncthreads();
  if (threadIdx.x == 0) {
    __threadfence();
    unsigned t = atomicAdd(&g_arrive, 1u) + 1u;
    unsigned target = ((t + NBLK - 1u) / NBLK) * NBLK;
    while (*(volatile unsigned*)&g_arrive < target) {}
    __threadfence();
  }
  __syncthreads();
}
__device__ __forceinline__ void ggsync(int grp, unsigned ep) {
  __syncthreads();
  if (threadIdx.x == 0) {
    __threadfence();
    gg_flag[blockIdx.x * 32] = ep;
  }
  if (threadIdx.x < GCTA) {
    const volatile unsigned* f = &gg_flag[(grp * GCTA + threadIdx.x) * 32];
    while (*f < ep) {}
  }
  __syncthreads();
}

// -------- MUFU-free softplus (abs err ~2e-6) --------
__device__ __forceinline__ float softplus_f(float x) {
  float t = fabsf(x);
  float s = fminf(t * 1.4426950408889634f, 100.f);
  float n = floorf(s);
  float r = n - s;
  float p = 1.3215487e-6f;
  p = fmaf(p, r, 1.5252734e-5f);
  p = fmaf(p, r, 1.5403530e-4f);
  p = fmaf(p, r, 1.3333558e-3f);
  p = fmaf(p, r, 9.6181291e-3f);
  p = fmaf(p, r, 5.5504109e-2f);
  p = fmaf(p, r, 2.4022651e-1f);
  p = fmaf(p, r, 6.9314718e-1f);
  p = fmaf(p, r, 1.0f);
  float u = p * __uint_as_float((uint32_t)(127 - (int)n) << 23);
  float d = 2.f + u;
  float w = fmaf(-0.1635f, u, 0.4915f);
  w = w * fmaf(-d, w, 2.f);
  w = w * fmaf(-d, w, 2.f);
  float v = u * w;
  float v2 = v * v;
  float g = 0.09090909f;
  g = fmaf(g, v2, 0.11111111f);
  g = fmaf(g, v2, 0.14285714f);
  g = fmaf(g, v2, 0.2f);
  g = fmaf(g, v2, 0.33333333f);
  g = fmaf(g, v2, 1.0f);
  return fmaxf(x, 0.f) + 2.f * v * g;
}

__device__ __forceinline__ void split_pack(float x0, float x1, uint32_t& hv, uint32_t& lv) {
  bf16 h0 = __float2bfloat16(x0), h1 = __float2bfloat16(x1);
  bf16 l0 = __float2bfloat16(x0 - __bfloat162float(h0));
  bf16 l1 = __float2bfloat16(x1 - __bfloat162float(h1));
  hv = (uint32_t)__bfloat16_as_ushort(h0) | ((uint32_t)__bfloat16_as_ushort(h1) << 16);
  lv = (uint32_t)__bfloat16_as_ushort(l0) | ((uint32_t)__bfloat16_as_ushort(l1) << 16);
}

// ---------------- GEMM1/2: C[64,32] = act(A[64,K] @ B[32,K]^T + bias) -> bf16 hi/lo ----------------
template<int NC, bool SP>
__device__ __forceinline__ void mma_gemm(
    const bf16* __restrict__ Ahi, const bf16* __restrict__ Alo,
    const bf16* __restrict__ Bhi, const bf16* __restrict__ Blo,
    int ldk, int bm, int bn,
    const float* __restrict__ bias,
    bf16* __restrict__ Chi, bf16* __restrict__ Clo, int ldc,
    char* sm)
{
  const int tid = threadIdx.x;
  const int wid = tid >> 5;
  const int lane = tid & 31;
  const int grp = lane >> 2, tig = lane & 3;
  const int wm = wid >> 1, wn = wid & 1;

  float hh[2][4] = {}, hl[2][4] = {}, lh[2][4] = {};

  int ar[4], as[4]; bool asel[4];
  #pragma unroll
  for (int i = 0; i < 4; ++i) {
    int lin = i * 256 + tid;
    asel[i] = lin >= 512;
    ar[i] = (lin >> 3) & 63;
    as[i] = (lin & 7) << 3;
  }
  int br[2], bs[2]; bool bsel[2];
  #pragma unroll
  for (int i = 0; i < 2; ++i) {
    int lin = i * 256 + tid;
    bsel[i] = lin >= 256;
    br[i] = (lin >> 3) & 31;
    bs[i] = (lin & 7) << 3;
  }
  const uint32_t smb = smem_u32(sm);
  uint32_t stA[4], stB[2];
  #pragma unroll
  for (int i = 0; i < 4; ++i) stA[i] = smb + (asel[i] ? OA_LO : 0) + ar[i] * SROWB + as[i] * 2;
  #pragma unroll
  for (int i = 0; i < 2; ++i) stB[i] = smb + (bsel[i] ? OB_LO : OB_HI) + br[i] * SROWB + bs[i] * 2;
  const bf16* gA[4]; const bf16* gB[2];
  #pragma unroll
  for (int i = 0; i < 4; ++i) gA[i] = (asel[i] ? Alo : Ahi) + (bm + ar[i]) * ldk + as[i];
  #pragma unroll
  for (int i = 0; i < 2; ++i) gB[i] = (bsel[i] ? Blo : Bhi) + (bn + br[i]) * ldk + bs[i];

  const uint32_t laA_hi = smb + (wm * 16 + (lane & 15)) * SROWB + ((lane >> 4) << 4);
  const uint32_t laA_lo = laA_hi + OA_LO;
  const uint32_t laB4_hi = smb + OB_HI + (wn * 16 + ((lane >> 4) << 3) + (lane & 7)) * SROWB
                           + (((lane >> 3) & 1) << 4);
  const uint32_t laB4_lo = laB4_hi + (OB_LO - OB_HI);

  #pragma unroll
  for (int i = 0; i < 4; ++i) cp16(stA[i], gA[i]);
  #pragma unroll
  for (int i = 0; i < 2; ++i) cp16ca(stB[i], gB[i]);
  cp_commit();
  if (NC > 1) {
    #pragma unroll
    for (int i = 0; i < 4; ++i) cp16(stA[i] + BUFS, gA[i] + 64);
    #pragma unroll
    for (int i = 0; i < 2; ++i) cp16ca(stB[i] + BUFS, gB[i] + 64);
    cp_commit();
  }

  if (NC == 2) {
    cp_wait0();
    __syncthreads();
    #pragma unroll
    for (int c = 0; c < 2; ++c) {
      const uint32_t bo = c ? BUFS : 0;
      #pragma unroll
      for (int ks = 0; ks < 4; ++ks) {
        uint32_t ah[4], al[4], b4h[4], b4l[4];
        LDMX4(ah, laA_hi + bo + ks * 32);
        LDMX4(al, laA_lo + bo + ks * 32);
        LDMX4(b4h, laB4_hi + bo + ks * 32);
        LDMX4(b4l, laB4_lo + bo + ks * 32);
        mma16816(hh[0], ah, b4h);
        mma16816(hl[0], ah, b4l);
        mma16816(lh[0], al, b4h);
        mma16816(hh[1], ah, b4h + 2);
        mma16816(hl[1], ah, b4l + 2);
        mma16816(lh[1], al, b4h + 2);
      }
    }
  } else {
    for (int c = 0; c < NC; ++c) {
      cp_wait1();
      __syncthreads();
      const uint32_t bo = (uint32_t)(c % NSTG) * BUFS;
      #pragma unroll
      for (int ks = 0; ks < 4; ++ks) {
        uint32_t ah[4], al[4], b4h[4], b4l[4];
        LDMX4(ah, laA_hi + bo + ks * 32);
        LDMX4(al, laA_lo + bo + ks * 32);
        LDMX4(b4h, laB4_hi + bo + ks * 32);
        LDMX4(b4l, laB4_lo + bo + ks * 32);
        mma16816(hh[0], ah, b4h);
        mma16816(hl[0], ah, b4l);
        mma16816(lh[0], al, b4h);
        mma16816(hh[1], ah, b4h + 2);
        mma16816(hl[1], ah, b4l + 2);
        mma16816(lh[1], al, b4h + 2);
      }
      if (c + 2 < NC) {
        const uint32_t bo2 = (uint32_t)((c + 2) % NSTG) * BUFS;
        int k0 = (c + 2) * 64;
        #pragma unroll
        for (int i = 0; i < 4; ++i) cp16(stA[i] + bo2, gA[i] + k0);
        #pragma unroll
        for (int i = 0; i < 2; ++i) cp16ca(stB[i] + bo2, gB[i] + k0);
      }
      cp_commit();
    }
  }

  #pragma unroll
  for (int ni = 0; ni < 2; ++ni) {
    int m0 = bm + wm * 16 + grp;
    int n  = bn + wn * 16 + ni * 8 + tig * 2;
    float bv0 = __ldg(bias + n), bv1 = __ldg(bias + n + 1);
    float x0 = hh[ni][0] + hl[ni][0] + lh[ni][0] + bv0;
    float x1 = hh[ni][1] + hl[ni][1] + lh[ni][1] + bv1;
    float x2 = hh[ni][2] + hl[ni][2] + lh[ni][2] + bv0;
    float x3 = hh[ni][3] + hl[ni][3] + lh[ni][3] + bv1;
    if (SP) { x0 = softplus_f(x0); x1 = softplus_f(x1); x2 = softplus_f(x2); x3 = softplus_f(x3); }
    uint32_t hv, lv;
    split_pack(x0, x1, hv, lv);
    __stcg((uint32_t*)(Chi + m0 * ldc + n), hv);
    __stcg((uint32_t*)(Clo + m0 * ldc + n), lv);
    split_pack(x2, x3, hv, lv);
    __stcg((uint32_t*)(Chi + (m0 + 8) * ldc + n), hv);
    __stcg((uint32_t*)(Clo + (m0 + 8) * ldc + n), lv);
  }
}

// ---------------- GEMM3 (stage S): k tile [16,32], K=512, 6-set pipeline, fused epilogue ----------------
template<int S>
__device__ __forceinline__ void gemm3_stage(
    char* sm, float* sred,
    int bm, int bn, const float* __restrict__ b2, double* sd, float h,
    const float* __restrict__ yb, const float* __restrict__ ynb,
    int slot0, int kdst)
{
  const int tid = threadIdx.x;
  const int wid = tid >> 5, lane = tid & 31;
  const int wn = wid & 3, wk = wid >> 2;
  const int grp = lane >> 2, tig = lane & 3;

  float hh[4] = {}, hl[4] = {}, lh[4] = {};

  const bool aselt = tid >= 128;
  const int arow = (tid >> 3) & 15;
  const int aseg = (tid & 7) << 3;
  int br[2], bs[2]; bool bsel[2];
  #pragma unroll
  for (int i = 0; i < 2; ++i) {
    int lin = i * 256 + tid;
    bsel[i] = lin >= 256;
    br[i] = (lin >> 3) & 31;
    bs[i] = (lin & 7) << 3;
  }

  const uint32_t smb = smem_u32(sm);
  const uint32_t stAo = (aselt ? G3_ALO : 0) + arow * SROWB + aseg * 2;
  uint32_t stBo[2];
  #pragma unroll
  for (int i = 0; i < 2; ++i) stBo[i] = (bsel[i] ? G3_BLO : G3_BHI) + br[i] * SROWB + bs[i] * 2;
  const bf16* gA = (aselt ? g_H2lo : g_H2hi) + (bm + arow) * WW + aseg;
  const bf16* gB[2];
  #pragma unroll
  for (int i = 0; i < 2; ++i) gB[i] = (bsel[i] ? g_W2lo : g_W2hi) + (bn + br[i]) * WW + bs[i];

  const uint32_t laAo_hi = (lane & 15) * SROWB + ((lane >> 4) << 4);
  const uint32_t laAo_lo = laAo_hi + G3_ALO;
  const uint32_t laBo_hi = G3_BHI + (wn * 8 + (lane & 7)) * SROWB + (((lane >> 3) & 1) << 4);
  const uint32_t laBo_lo = laBo_hi + (G3_BLO - G3_BHI);

  #pragma unroll
  for (int p = 0; p < 2; ++p) {
    #pragma unroll
    for (int q = 0; q < 2; ++q) {
      int ck = p * 2 + q;
      uint32_t setb = smb + (uint32_t)ck * G3SET;
      cp16(setb + stAo, gA + ck * 64);
      cp16ca(setb + stBo[0], gB[0] + ck * 64);
      cp16ca(setb + stBo[1], gB[1] + ck * 64);
    }
    cp_commit();
  }

  for (int i = 0; i < 4; ++i) {
    cp_wait1();
    __syncthreads();
    #pragma unroll
    for (int cc = 0; cc < 2; ++cc) {
      const int chunk = 2 * i + cc;
      const uint32_t setb = smb + (uint32_t)(chunk % 6) * G3SET;
      #pragma unroll
      for (int ks2 = 0; ks2 < 2; ++ks2) {
        const int ks = wk * 2 + ks2;
        uint32_t ah[4], al[4], bh[2], bl[2];
        LDMX4(ah, setb + laAo_hi + ks * 32);
        LDMX4(al, setb + laAo_lo + ks * 32);
        LDMX2(bh, setb + laBo_hi + ks * 32);
        LDMX2(bl, setb + laBo_lo + ks * 32);
        mma16816(hh, ah, bh);
        mma16816(hl, ah, bl);
        mma16816(lh, al, bh);
      }
    }
    const int pc = 2 * i + 4;
    if (pc < 8) {
      #pragma unroll
      for (int q = 0; q < 2; ++q) {
        int ck = pc + q;
        uint32_t setb = smb + (uint32_t)(ck % 6) * G3SET;
        cp16(setb + stAo, gA + ck * 64);
        cp16ca(setb + stBo[0], gB[0] + ck * 64);
        cp16ca(setb + stBo[1], gB[1] + ck * 64);
      }
    }
    cp_commit();
  }

  float acc[4];
  #pragma unroll
  for (int j = 0; j < 4; ++j) acc[j] = hh[j] + hl[j] + lh[j];

  const int nl = wn * 8 + tig * 2;
  if (wk == 1) {
    sred[grp * 32 + nl]           = acc[0];
    sred[grp * 32 + nl + 1]       = acc[1];
    sred[(grp + 8) * 32 + nl]     = acc[2];
    sred[(grp + 8) * 32 + nl + 1] = acc[3];
  }
  __syncthreads();
  double ss = 0.0;
  if (wk == 0) {
    acc[0] += sred[grp * 32 + nl];
    acc[1] += sred[grp * 32 + nl + 1];
    acc[2] += sred[(grp + 8) * 32 + nl];
    acc[3] += sred[(grp + 8) * 32 + nl + 1];

    const int n0 = bn + nl;
    const int m0 = bm + grp;
    const int i0 = m0 * DD + n0;
    const int i1 = (m0 + 8) * DD + n0;
    float bv0 = __ldg(b2 + n0), bv1 = __ldg(b2 + n0 + 1);
    float2 v0 = {acc[0] + bv0, acc[1] + bv1};
    float2 v1 = {acc[2] + bv0, acc[3] + bv1};
    float* kout = g_k[0] + (size_t)kdst * NELEM;
    __stcg((float2*)(kout + i0), v0);
    __stcg((float2*)(kout + i1), v1);

    const int idxs[2] = {i0, i1};
    const float2 vs[2] = {v0, v1};
    if constexpr (S <= 5) {
      #pragma unroll
      for (int r = 0; r < 2; ++r) {
        int ix = idxs[r];
        float2 y2 = __ldcg((const float2*)(yb + ix));
        float cS = c_coef[S][S];
        float ax = cS * vs[r].x, ay = cS * vs[r].y;
        #pragma unroll
        for (int j = 0; j < S; ++j) {
          float cj = c_coef[S][j];
          const float* kj_p = (j == 0) ? (g_k[0] + (size_t)slot0 * NELEM) : g_k[j];
          float2 kj = __ldcg((const float2*)(kj_p + ix));
          ax = fmaf(cj, kj.x, ax);
          ay = fmaf(cj, kj.y, ay);
        }
        float Xx = fmaf(h, ax, y2.x);
        float Xy = fmaf(h, ay, y2.y);
        if constexpr (S == 5) {
          float2 yn = {Xx, Xy};
          __stcg((float2*)(const_cast<float*>(ynb) + ix), yn);
        }
        uint32_t hv, lv;
        split_pack(Xx, Xy, hv, lv);
        __stcg((uint32_t*)(g_Xhi + ix), hv);
        __stcg((uint32_t*)(g_Xlo + ix), lv);
      }
    } else {
      #pragma unroll
      for (int r = 0; r < 2; ++r) {
        int ix = idxs[r];
        float2 k0 = __ldcg((const float2*)(g_k[0] + (size_t)slot0 * NELEM + ix));
        float2 k1 = __ldcg((const float2*)(g_k[1] + ix));
        float2 k2 = __ldcg((const float2*)(g_k[2] + ix));
        float2 k3 = __ldcg((const float2*)(g_k[3] + ix));
        float2 k4 = __ldcg((const float2*)(g_k[4] + ix));
        float2 k5 = __ldcg((const float2*)(g_k[5] + ix));
        float2 y2 = __ldcg((const float2*)(yb + ix));
        float2 yn = __ldcg((const float2*)(ynb + ix));
        #pragma unroll
        for (int cc = 0; cc < 2; ++cc) {
          float e = Ec1 * (cc ? k0.y : k0.x);
          e = fmaf(Ec2, cc ? k1.y : k1.x, e);
          e = fmaf(Ec3, cc ? k2.y : k2.x, e);
          e = fmaf(Ec4, cc ? k3.y : k3.x, e);
          e = fmaf(Ec5, cc ? k4.y : k4.x, e);
          e = fmaf(Ec6, cc ? k5.y : k5.x, e);
          e = fmaf(Ec7, cc ? vs[r].y : vs[r].x, e);
          float err = h * e;
          float yv = cc ? y2.y : y2.x, ynv = cc ? yn.y : yn.x;
          float scale = ATOLc + RTOLc * fmaxf(fabsf(yv), fabsf(ynv));
          float rr = err / scale;
          ss += (double)rr * (double)rr;
        }
      }
    }
  }
  if constexpr (S == 6) {
    sd[tid] = ss;
    __syncthreads();
    #pragma unroll
    for (int s2 = 128; s2 > 0; s2 >>= 1) {
      if (tid < s2) sd[tid] += sd[tid + s2];
      __syncthreads();
    }
    if (tid == 0) *(volatile double*)&g_errpart[blockIdx.x] = sd[0];
  }
}

// ---------------- one RK stage ----------------
template<int S>
__device__ __forceinline__ void do_stage(int grp_id, int lbid, unsigned& ep, float h,
    const float* b0, const float* b1, const float* b2,
    char* sm, float* sred, double* sd,
    const float* yb, const float* ynb, int slot0, int kdst)
{
  const int bm = grp_id << 6;
  const int bn = lbid << 5;
  mma_gemm<2, true>(g_Xhi, g_Xlo, g_W0hi, g_W0lo, DD, bm, bn, b0, g_H1hi, g_H1lo, WW, sm);
  ggsync(grp_id, ep++);
  mma_gemm<8, true>(g_H1hi, g_H1lo, g_W1hi, g_W1lo, WW, bm, bn, b1, g_H2hi, g_H2lo, WW, sm);
  ggsync(grp_id, ep++);
  gemm3_stage<S>(sm, sred, bm + ((lbid >> 2) << 4), (lbid & 3) << 5, b2, sd, h,
                 yb, ynb, slot0, kdst);
  if (S < 6) ggsync(grp_id, ep++);
}

// update: out write on hit; build X for first live stage: X = y + a21h * k1
__device__ __forceinline__ void update_phase(int gid2, float* __restrict__ out,
                                             int hit, int wrow,
                                             const float* __restrict__ yb,
                                             const float* __restrict__ k1p,
                                             float a21h) {
  float2 yv = __ldcg((const float2*)(yb + gid2));
  if (hit) *(float2*)(out + wrow * NELEM + gid2) = yv;
  float2 k1 = __ldcg((const float2*)(k1p + gid2));
  float Xx = fmaf(a21h, k1.x, yv.x);
  float Xy = fmaf(a21h, k1.y, yv.y);
  uint32_t hv, lv;
  split_pack(Xx, Xy, hv, lv);
  __stcg((uint32_t*)(g_Xhi + gid2), hv);
  __stcg((uint32_t*)(g_Xlo + gid2), lv);
}

// ---------------- persistent solver ----------------
__global__ void __launch_bounds__(NTHR, 2) solve_kernel(
    const float* __restrict__ ts,
    const float* __restrict__ b0, const float* __restrict__ b1,
    const float* __restrict__ b2, float* __restrict__ out)
{
  extern __shared__ __align__(16) char sm[];
  __shared__ float sred[16 * 32];
  __shared__ double sd[NTHR];

  const int bid = blockIdx.x;
  const int tid = threadIdx.x;
  const int grp_id = bid >> 4;
  const int lbid = bid & 15;
  const int gid2 = (bid * NTHR + tid) * 2;
  unsigned ep = 1;

  // replicated controller state (bit-identical in every CTA/thread)
  float t = __ldg(ts + 0);
  float dt = __ldg(ts + 1) - t;
  int si = 1, done = 0, hit = 0, wrow = 0, sic = 1;
  int par = 0, slot0 = 0, slot6 = 6;
  float tns = __ldg(ts + 1);
  float h = fmaxf(fminf(dt, tns - t), 0.f);

  for (int step = 0; step < MAX_STEPS; ++step) {
    if (done) break;

    const float* yb = g_yb[par];
    const float* ynb = g_yb[par ^ 1];
    // step 0: X = split(y) (stage 0 computes k1 itself).
    // steps >=1: stage 0 is skipped (FSAL: k1 = reused slot0); X = y + h*A21*k1.
    float a21h = (step == 0) ? 0.f : h * A21f;
    update_phase(gid2, out, hit, wrow, yb, g_k[0] + (size_t)slot0 * NELEM, a21h);
    ggsync(grp_id, ep++);

    if (step == 0)
      do_stage<0>(grp_id, lbid, ep, h, b0, b1, b2, sm, sred, sd, yb, ynb, slot0, slot0);
    do_stage<1>(grp_id, lbid, ep, h, b0, b1, b2, sm, sred, sd, yb, ynb, slot0, 1);
    do_stage<2>(grp_id, lbid, ep, h, b0, b1, b2, sm, sred, sd, yb, ynb, slot0, 2);
    do_stage<3>(grp_id, lbid, ep, h, b0, b1, b2, sm, sred, sd, yb, ynb, slot0, 3);
    do_stage<4>(grp_id, lbid, ep, h, b0, b1, b2, sm, sred, sd, yb, ynb, slot0, 4);
    do_stage<5>(grp_id, lbid, ep, h, b0, b1, b2, sm, sred, sd, yb, ynb, slot0, 5);
    do_stage<6>(grp_id, lbid, ep, h, b0, b1, b2, sm, sred, sd, yb, ynb, slot0, slot6);

    gsync();   // all err partials visible to every CTA

    sd[tid] = *(volatile double*)&g_errpart[tid];
    __syncthreads();
    #pragma unroll
    for (int s2 = 128; s2 > 0; s2 >>= 1) {
      if (tid < s2) sd[tid] += sd[tid + s2];
      __syncthreads();
    }
    const double total = sd[0];
    __syncthreads();

    float enorm = sqrtf((float)(total / (double)NELEM));
    int accept = (enorm <= 1.0f) && !done;
    float t_new = t + h;
    hit = accept && (t_new >= tns - 1e-6f);
    if (accept) t = t_new;
    wrow = sic;
    si += hit;
    float factor;
    if (enorm > 0.f) {
      factor = 0.9f * powf(enorm, -0.2f);
      factor = fminf(fmaxf(factor, 0.2f), 10.f);
    } else factor = 10.f;
    if (!done) dt = dt * factor;
    if (accept) {
      par ^= 1;                       // ynew becomes y
      int tmp = slot0; slot0 = slot6; slot6 = tmp;  // k7 becomes k1 (FSAL)
    }
    done = (si >= TT) ? 1 : 0;
    sic = si < (TT - 1) ? si : (TT - 1);
    tns = __ldg(ts + sic);
    h = done ? 0.f : fmaxf(fminf(dt, tns - t), 0.f);
  }
  // final pending out-write (no-op unless last step hit)
  if (hit) {
    float2 v = __ldcg((const float2*)(g_yb[par] + gid2));
    *(float2*)(out + wrow * NELEM + gid2) = v;
  }
}

// ---------------- init ----------------
__global__ void init_kernel(const float* __restrict__ ts, const float* __restrict__ y0,
                            const float* __restrict__ W0, const float* __restrict__ W1,
                            const float* __restrict__ W2, float* __restrict__ out)
{
  int idx = blockIdx.x * NTHR + threadIdx.x;
  if (idx < TT * NELEM) out[idx] = (idx < NELEM) ? y0[idx] : 0.f;
  if (idx < NELEM) {
    float v = y0[idx];
    g_yb[0][idx] = v;
    bf16 h = __float2bfloat16(v);
    g_Xhi[idx] = h;
    g_Xlo[idx] = __float2bfloat16(v - __bfloat162float(h));
  }
  if (idx < WW * DD) {
    float w = W0[idx];
    bf16 h = __float2bfloat16(w);
    g_W0hi[idx] = h; g_W0lo[idx] = __float2bfloat16(w - __bfloat162float(h));
    float w2 = W2[idx];
    bf16 h2 = __float2bfloat16(w2);
    g_W2hi[idx] = h2; g_W2lo[idx] = __float2bfloat16(w2 - __bfloat162float(h2));
  }
  if (idx < WW * WW) {
    float w = W1[idx];
    bf16 h = __float2bfloat16(w);
    g_W1hi[idx] = h; g_W1lo[idx] = __float2bfloat16(w - __bfloat162float(h));
  }
  if (idx < NBLK * 32) gg_flag[idx] = 0u;
  if (idx < NBLK) g_errpart[idx] = 0.0;
  if (idx == 0) g_arrive = 0u;
}

extern "C" void kernel_launch(void* const* d_in, const int* in_sizes, int n_in,
                              void* d_out, int out_size) {
  const float* ts = (const float*)d_in[0];
  const float* y0 = (const float*)d_in[1];
  const float* W0 = (const float*)d_in[2];
  const float* b0 = (const float*)d_in[3];
  const float* W1 = (const float*)d_in[4];
  const float* b1 = (const float*)d_in[5];
  const float* W2 = (const float*)d_in[6];
  const float* b2 = (const float*)d_in[7];
  float* out = (float*)d_out;

  cudaFuncSetAttribute(solve_kernel, cudaFuncAttributeMaxDynamicSharedMemorySize, SMEM_DYN);

  init_kernel<<<(TT * NELEM) / NTHR, NTHR>>>(ts, y0, W0, W1, W2, out);
  solve_kernel<<<NBLK, NTHR, SMEM_DYN>>>(ts, b0, b1, b2, out);
}